// round 1
// baseline (speedup 1.0000x reference)
#include <cuda_runtime.h>
#include <math.h>

#define B_   4
#define S_   8192
#define H_   768
#define NH_  12
#define HD_  64
#define NB_  64          // S_/128 blocks
#define WIN_ 384
#define KC_  64          // key chunk
#define NROW_ 191        // pos rows needed per chunk: 128+KC_-1
#define PST_ 65          // padded pos row stride (odd -> conflict free)
#define SBST_ 65         // score buffer stride

#define TOT_ (B_*S_*H_)

// ---------------- scratch (device globals; no allocs allowed) ----------------
__device__ float g_Q[TOT_];
__device__ float g_K[TOT_];
__device__ float g_V[TOT_];
__device__ float g_CTX[TOT_];
__device__ float g_XR[TOT_];
__device__ float g_PK[512 * H_];
__device__ float g_PQ[512 * H_];
__device__ float g_PKG[NH_ * 511 * HD_];
__device__ float g_PQG[NH_ * 511 * HD_];

// ---------------- SGEMM: C = A[M,K] @ B[K,N] + bias (+ residual) -------------
// 128x128 block tile, BK=16, 256 threads, 8x8 microtile (split 4+4 fragments)
__global__ void __launch_bounds__(256) sgemm_bias(
    const float* __restrict__ A, const float* __restrict__ Bm,
    const float* __restrict__ bias, const float* __restrict__ Rres,
    float* __restrict__ C, int M, int N, int K)
{
    __shared__ float As[16][128];
    __shared__ float Bs[16][128];

    const int tid = threadIdx.x;
    const int bn = blockIdx.x * 128;
    const int bm = blockIdx.y * 128;
    const int tx = tid & 15;
    const int ty = tid >> 4;

    float acc[8][8];
    #pragma unroll
    for (int i = 0; i < 8; i++)
        #pragma unroll
        for (int j = 0; j < 8; j++) acc[i][j] = 0.f;

    for (int kt = 0; kt < K; kt += 16) {
        // load A tile 128x16, store transposed As[k][m]
        #pragma unroll
        for (int i = 0; i < 2; i++) {
            int id = tid + i * 256;              // 0..511
            int r  = id >> 2;                    // 0..127
            int c4 = (id & 3) << 2;              // 0,4,8,12
            float4 v = *(const float4*)(A + (size_t)(bm + r) * K + kt + c4);
            As[c4 + 0][r] = v.x;
            As[c4 + 1][r] = v.y;
            As[c4 + 2][r] = v.z;
            As[c4 + 3][r] = v.w;
        }
        // load B tile 16x128
        #pragma unroll
        for (int i = 0; i < 2; i++) {
            int id = tid + i * 256;
            int r  = id >> 5;                    // 0..15
            int c4 = (id & 31) << 2;             // 0..124
            *(float4*)&Bs[r][c4] =
                *(const float4*)(Bm + (size_t)(kt + r) * N + bn + c4);
        }
        __syncthreads();

        #pragma unroll
        for (int k = 0; k < 16; k++) {
            float a[8], b[8];
            *(float4*)&a[0] = *(float4*)&As[k][ty * 4];
            *(float4*)&a[4] = *(float4*)&As[k][64 + ty * 4];
            *(float4*)&b[0] = *(float4*)&Bs[k][tx * 4];
            *(float4*)&b[4] = *(float4*)&Bs[k][64 + tx * 4];
            #pragma unroll
            for (int i = 0; i < 8; i++)
                #pragma unroll
                for (int j = 0; j < 8; j++)
                    acc[i][j] = fmaf(a[i], b[j], acc[i][j]);
        }
        __syncthreads();
    }

    // epilogue
    #pragma unroll
    for (int ih = 0; ih < 2; ih++) {
        #pragma unroll
        for (int ii = 0; ii < 4; ii++) {
            size_t row = (size_t)bm + ih * 64 + ty * 4 + ii;
            #pragma unroll
            for (int jh = 0; jh < 2; jh++) {
                #pragma unroll
                for (int jj = 0; jj < 4; jj++) {
                    int col = bn + jh * 64 + tx * 4 + jj;
                    float v = acc[ih * 4 + ii][jh * 4 + jj] + bias[col];
                    if (Rres != nullptr) v += Rres[row * (size_t)N + col];
                    C[row * (size_t)N + col] = v;
                }
            }
        }
    }
}

// ---------------- bucketization + gathered pos tables -------------------------
__device__ __forceinline__ int bucket_idx_dev(int d)
{
    int ad = d < 0 ? -d : d;
    int v;
    if (ad <= 128) {
        v = d;                                   // linear zone (|d| <= mid)
    } else {
        // replicate fp32 op order of reference:
        // ceil( log(ad/128) / fp32(ln(255/128)) * 127 ) + 128, times sign
        float t = logf((float)ad / 128.0f);
        t = t / 0.6892332713f;                   // fp32(ln(255/128))
        t = t * 127.0f;
        float lp = ceilf(t) + 128.0f;
        v = (int)(d < 0 ? -lp : lp);
    }
    v += 256;
    return v < 0 ? 0 : (v > 511 ? 511 : v);
}

// PKG[h][dd][d] = pos_k[f(dd-383)][h][d]; same for PQG with pos_q
__global__ void build_pos(const float* __restrict__ PK, const float* __restrict__ PQ,
                          float* __restrict__ PKG, float* __restrict__ PQG)
{
    int dd = blockIdx.x;                         // 0..510
    int t  = threadIdx.x;                        // 0..767
    int p  = bucket_idx_dev(dd - 383);
    int h  = t >> 6;
    int d  = t & 63;
    size_t dst = ((size_t)h * 511 + dd) * HD_ + d;
    size_t src = (size_t)p * H_ + t;
    PKG[dst] = PK[src];
    PQG[dst] = PQ[src];
}

// ---------------- attention: one CTA per (head, block, batch) ----------------
// scores[q,k] = (q.k + q.posk_g[q-k] + k.posq_g[q-k]) / sqrt(192)
// streaming online softmax over 6 chunks of 64 keys; q,ctx register-resident.
__global__ void __launch_bounds__(128) attn_kernel(
    const float* __restrict__ Q, const float* __restrict__ K,
    const float* __restrict__ V,
    const float* __restrict__ PKG, const float* __restrict__ PQG,
    float* __restrict__ CTX)
{
    extern __shared__ float sm[];
    float* ksh  = sm;                            // KC_*HD_  = 4096
    float* vsh  = ksh + KC_ * HD_;               // 4096
    float* pks  = vsh + KC_ * HD_;               // NROW_*PST_ = 12415
    float* pqs  = pks + NROW_ * PST_;            // 12415
    float* sbuf = pqs + NROW_ * PST_;            // 128*SBST_  = 8320

    const int h = blockIdx.x, n = blockIdx.y, b = blockIdx.z;
    const int tid = threadIdx.x;                 // q row
    const size_t qrow0 = (size_t)b * S_ + (size_t)n * 128;
    const size_t hoff  = (size_t)h * HD_;

    // stage Q tile (coalesced) then move own row to registers (stride-65 read)
    for (int i = tid; i < 128 * HD_; i += 128) {
        int r = i >> 6, c = i & 63;
        pks[r * PST_ + c] = Q[(qrow0 + r) * H_ + hoff + c];
    }
    __syncthreads();
    float qv[HD_];
    #pragma unroll
    for (int d = 0; d < HD_; d++) qv[d] = pks[tid * PST_ + d];
    __syncthreads();

    float ctx[HD_];
    #pragma unroll
    for (int d = 0; d < HD_; d++) ctx[d] = 0.f;
    float m = -1e30f, l = 0.f;
    const float scale = 0.07216878364870323f;    // 1/sqrt(192)

    const float* pkgh = PKG + (size_t)h * 511 * HD_;
    const float* pqgh = PQG + (size_t)h * 511 * HD_;

    for (int c0 = 0; c0 < WIN_; c0 += KC_) {
        const long sk0 = (long)n * 128 - 128 + c0;

        // K/V chunk (zero pad outside sequence; matches reference pad semantics)
        for (int i = tid; i < KC_ * 16; i += 128) {
            int r  = i >> 4;
            int c4 = (i & 15) << 2;
            long s = sk0 + r;
            float4 kv, vv;
            if (s >= 0 && s < S_) {
                size_t g = ((size_t)b * S_ + s) * H_ + hoff + c4;
                kv = *(const float4*)(K + g);
                vv = *(const float4*)(V + g);
            } else {
                kv = make_float4(0.f, 0.f, 0.f, 0.f);
                vv = make_float4(0.f, 0.f, 0.f, 0.f);
            }
            *(float4*)(ksh + r * HD_ + c4) = kv;
            *(float4*)(vsh + r * HD_ + c4) = vv;
        }

        // pos rows for this chunk: dd = (320-c0)+rr, rr = q - j + 63 in [0,190]
        const int ddb = 320 - c0;
        for (int i = tid; i < NROW_ * HD_; i += 128) {
            int rr = i >> 6, d = i & 63;
            pks[rr * PST_ + d] = pkgh[(size_t)(ddb + rr) * HD_ + d];
            pqs[rr * PST_ + d] = pqgh[(size_t)(ddb + rr) * HD_ + d];
        }
        __syncthreads();

        // scores for 64 keys
        float mb = -1e30f;
        float* srow = sbuf + tid * SBST_;
        for (int j = 0; j < KC_; ++j) {
            const float* kr  = ksh + j * HD_;
            const float* pkr = pks + (tid - j + 63) * PST_;
            const float* pqr = pqs + (tid - j + 63) * PST_;
            float a1 = 0.f, a2 = 0.f, a3 = 0.f;
            #pragma unroll
            for (int d = 0; d < HD_; d++) {
                float kd = kr[d];
                a1 = fmaf(qv[d], kd,     a1);    // c2c
                a2 = fmaf(qv[d], pkr[d], a2);    // c2p
                a3 = fmaf(kd,    pqr[d], a3);    // p2c
            }
            float sv = (a1 + a2 + a3) * scale;
            srow[j] = sv;
            mb = fmaxf(mb, sv);
        }

        // online softmax update
        float mnew = fmaxf(m, mb);
        float corr = __expf(m - mnew);
        float lb = 0.f;
        for (int j = 0; j < KC_; j++) {
            float p = __expf(srow[j] - mnew);
            srow[j] = p;
            lb += p;
        }
        l = l * corr + lb;
        m = mnew;

        #pragma unroll
        for (int d = 0; d < HD_; d++) ctx[d] *= corr;
        for (int j = 0; j < KC_; j++) {
            float p = srow[j];
            const float* vr = vsh + j * HD_;
            #pragma unroll
            for (int d = 0; d < HD_; d++) ctx[d] = fmaf(p, vr[d], ctx[d]);
        }
        __syncthreads();
    }

    // normalize, stage, coalesced write
    float invl = 1.0f / l;
    #pragma unroll
    for (int d = 0; d < HD_; d++) pks[tid * PST_ + d] = ctx[d] * invl;
    __syncthreads();
    for (int i = tid; i < 128 * HD_; i += 128) {
        int r = i >> 6, c = i & 63;
        CTX[(qrow0 + r) * H_ + hoff + c] = pks[r * PST_ + c];
    }
}

// ---------------- LayerNorm over H=768, one row per CTA ----------------------
__global__ void __launch_bounds__(256) ln_kernel(
    const float* __restrict__ X, const float* __restrict__ gam,
    const float* __restrict__ bet, float* __restrict__ out)
{
    const int row = blockIdx.x;
    const int t   = threadIdx.x;
    const float* x = X + (size_t)row * H_;
    float v0 = x[t], v1 = x[t + 256], v2 = x[t + 512];
    float s = v0 + v1 + v2;
    float q = v0 * v0 + v1 * v1 + v2 * v2;

    __shared__ float sh[64];
    #pragma unroll
    for (int o = 16; o > 0; o >>= 1) {
        s += __shfl_down_sync(0xffffffffu, s, o);
        q += __shfl_down_sync(0xffffffffu, q, o);
    }
    int w = t >> 5, lane = t & 31;
    if (lane == 0) { sh[w] = s; sh[32 + w] = q; }
    __syncthreads();
    if (t == 0) {
        float ts = 0.f, tq = 0.f;
        #pragma unroll
        for (int i = 0; i < 8; i++) { ts += sh[i]; tq += sh[32 + i]; }
        sh[0] = ts;
        sh[32] = tq;
    }
    __syncthreads();
    float mu  = sh[0] * (1.0f / 768.0f);
    float var = sh[32] * (1.0f / 768.0f) - mu * mu;
    float r   = rsqrtf(var + 1e-7f);

    float* o = out + (size_t)row * H_;
    o[t]       = (v0 - mu) * r * gam[t]       + bet[t];
    o[t + 256] = (v1 - mu) * r * gam[t + 256] + bet[t + 256];
    o[t + 512] = (v2 - mu) * r * gam[t + 512] + bet[t + 512];
}

// ---------------- launch ------------------------------------------------------
extern "C" void kernel_launch(void* const* d_in, const int* in_sizes, int n_in,
                              void* d_out, int out_size)
{
    const float* hidden = (const float*)d_in[0];
    const float* rel    = (const float*)d_in[1];
    const float* Wq = (const float*)d_in[2];  const float* bq = (const float*)d_in[3];
    const float* Wk = (const float*)d_in[4];  const float* bk = (const float*)d_in[5];
    const float* Wv = (const float*)d_in[6];  const float* bv = (const float*)d_in[7];
    const float* Wo = (const float*)d_in[8];  const float* bo = (const float*)d_in[9];
    const float* lns = (const float*)d_in[10];
    const float* lnb = (const float*)d_in[11];
    float* out = (float*)d_out;

    float *Qp, *Kp, *Vp, *PK, *PQ, *PKG, *PQG, *CT, *XR;
    cudaGetSymbolAddress((void**)&Qp,  g_Q);
    cudaGetSymbolAddress((void**)&Kp,  g_K);
    cudaGetSymbolAddress((void**)&Vp,  g_V);
    cudaGetSymbolAddress((void**)&PK,  g_PK);
    cudaGetSymbolAddress((void**)&PQ,  g_PQ);
    cudaGetSymbolAddress((void**)&PKG, g_PKG);
    cudaGetSymbolAddress((void**)&PQG, g_PQG);
    cudaGetSymbolAddress((void**)&CT,  g_CTX);
    cudaGetSymbolAddress((void**)&XR,  g_XR);

    const int M = B_ * S_;                       // 32768

    dim3 gBig(H_ / 128, M / 128);                // (6, 256)
    dim3 gPos(H_ / 128, 512 / 128);              // (6, 4)

    // QKV projections
    sgemm_bias<<<gBig, 256>>>(hidden, Wq, bq, nullptr, Qp, M, H_, H_);
    sgemm_bias<<<gBig, 256>>>(hidden, Wk, bk, nullptr, Kp, M, H_, H_);
    sgemm_bias<<<gBig, 256>>>(hidden, Wv, bv, nullptr, Vp, M, H_, H_);

    // positional projections (shared Wq/Wk) + gathered tables
    sgemm_bias<<<gPos, 256>>>(rel, Wk, bk, nullptr, PK, 512, H_, H_);
    sgemm_bias<<<gPos, 256>>>(rel, Wq, bq, nullptr, PQ, 512, H_, H_);
    build_pos<<<511, 768>>>(PK, PQ, PKG, PQG);

    // attention
    const int smem_attn = (KC_ * HD_ * 2 + NROW_ * PST_ * 2 + 128 * SBST_) * 4;
    cudaFuncSetAttribute(attn_kernel,
                         cudaFuncAttributeMaxDynamicSharedMemorySize, smem_attn);
    attn_kernel<<<dim3(NH_, NB_, B_), 128, smem_attn>>>(Qp, Kp, Vp, PKG, PQG, CT);

    // output projection + residual, then layernorm
    sgemm_bias<<<gBig, 256>>>(CT, Wo, bo, hidden, XR, M, H_, H_);
    ln_kernel<<<M, 256>>>(XR, lns, lnb, out);
}

// round 2
// speedup vs baseline: 1.2789x; 1.2789x over previous
#include <cuda_runtime.h>
#include <math.h>
#include <stdint.h>

#define B_   4
#define S_   8192
#define H_   768
#define NH_  12
#define HD_  64
#define NB_  64          // S_/128 blocks
#define WIN_ 384
#define KC_  64          // key chunk
#define NROW_ 191        // pos rows needed per chunk: 128+KC_-1
#define PST_ 65          // padded pos row stride (odd -> conflict free)
#define SBST_ 65         // score buffer stride

#define TOT_ (B_*S_*H_)

// ---------------- scratch (device globals; no allocs allowed) ----------------
__device__ float g_Q[TOT_];
__device__ float g_K[TOT_];
__device__ float g_V[TOT_];
__device__ float g_CTX[TOT_];
__device__ float g_XR[TOT_];
__device__ float g_PK[512 * H_];
__device__ float g_PQ[512 * H_];
__device__ float g_PKG[NH_ * 511 * HD_];
__device__ float g_PQG[NH_ * 511 * HD_];

// ---------------- TF32 tensor-core GEMM --------------------------------------
// C = A[M,K] @ B[K,N] + bias (+ residual). 128x128 tile, BK=16, 256 threads,
// 8 warps in 4(m) x 2(n); each warp 32x64 via m16n8k8 tf32 mma.

__device__ __forceinline__ float cvt_tf32(float x) {
    uint32_t u;
    asm("cvt.rna.tf32.f32 %0, %1;" : "=r"(u) : "f"(x));
    return __uint_as_float(u);
}

__device__ __forceinline__ void mma_tf32(float* c, const uint32_t* a, const uint32_t* b) {
    asm volatile(
        "mma.sync.aligned.m16n8k8.row.col.f32.tf32.tf32.f32 "
        "{%0,%1,%2,%3},{%4,%5,%6,%7},{%8,%9},{%0,%1,%2,%3};\n"
        : "+f"(c[0]), "+f"(c[1]), "+f"(c[2]), "+f"(c[3])
        : "r"(a[0]), "r"(a[1]), "r"(a[2]), "r"(a[3]), "r"(b[0]), "r"(b[1]));
}

#define AST 20    // As row stride (floats): conflict-free for frag loads
#define BST 136   // Bs row stride (floats): conflict-free for frag loads

__global__ void __launch_bounds__(256) tf32_gemm(
    const float* __restrict__ A, const float* __restrict__ Bm,
    const float* __restrict__ bias, const float* __restrict__ Rres,
    float* __restrict__ C, int M, int N, int K)
{
    __shared__ float As[128 * AST];
    __shared__ float Bs[16 * BST];

    const int tid  = threadIdx.x;
    const int lane = tid & 31;
    const int warp = tid >> 5;
    const int wm   = (warp & 3) * 32;     // warp row base in tile
    const int wn   = (warp >> 2) * 64;    // warp col base in tile
    const int bm   = blockIdx.y * 128;
    const int bn   = blockIdx.x * 128;
    const int gid  = lane >> 2;           // group id 0..7
    const int tig  = lane & 3;            // thread-in-group 0..3

    float acc[2][8][4];
    #pragma unroll
    for (int mt = 0; mt < 2; mt++)
        #pragma unroll
        for (int nt = 0; nt < 8; nt++)
            #pragma unroll
            for (int i = 0; i < 4; i++) acc[mt][nt][i] = 0.f;

    for (int kt = 0; kt < K; kt += 16) {
        // A tile 128x16 (row-major, converted to tf32)
        #pragma unroll
        for (int i = 0; i < 2; i++) {
            int id = tid + i * 256;                 // 0..511
            int r  = id >> 2;
            int c4 = (id & 3) << 2;
            float4 v = *(const float4*)(A + (size_t)(bm + r) * K + kt + c4);
            v.x = cvt_tf32(v.x); v.y = cvt_tf32(v.y);
            v.z = cvt_tf32(v.z); v.w = cvt_tf32(v.w);
            *(float4*)&As[r * AST + c4] = v;
        }
        // B tile 16x128
        #pragma unroll
        for (int i = 0; i < 2; i++) {
            int id = tid + i * 256;
            int r  = id >> 5;
            int c4 = (id & 31) << 2;
            float4 v = *(const float4*)(Bm + (size_t)(kt + r) * N + bn + c4);
            v.x = cvt_tf32(v.x); v.y = cvt_tf32(v.y);
            v.z = cvt_tf32(v.z); v.w = cvt_tf32(v.w);
            *(float4*)&Bs[r * BST + c4] = v;
        }
        __syncthreads();

        #pragma unroll
        for (int ks = 0; ks < 2; ks++) {
            const int k8 = ks * 8;
            uint32_t a[2][4], b[8][2];
            #pragma unroll
            for (int mt = 0; mt < 2; mt++) {
                int r0 = wm + mt * 16 + gid;
                a[mt][0] = __float_as_uint(As[r0 * AST + k8 + tig]);
                a[mt][1] = __float_as_uint(As[(r0 + 8) * AST + k8 + tig]);
                a[mt][2] = __float_as_uint(As[r0 * AST + k8 + tig + 4]);
                a[mt][3] = __float_as_uint(As[(r0 + 8) * AST + k8 + tig + 4]);
            }
            #pragma unroll
            for (int nt = 0; nt < 8; nt++) {
                int cc = wn + nt * 8 + gid;
                b[nt][0] = __float_as_uint(Bs[(k8 + tig) * BST + cc]);
                b[nt][1] = __float_as_uint(Bs[(k8 + tig + 4) * BST + cc]);
            }
            #pragma unroll
            for (int mt = 0; mt < 2; mt++)
                #pragma unroll
                for (int nt = 0; nt < 8; nt++)
                    mma_tf32(acc[mt][nt], a[mt], b[nt]);
        }
        __syncthreads();
    }

    // epilogue: direct stores (float2 per fragment row)
    #pragma unroll
    for (int mt = 0; mt < 2; mt++) {
        #pragma unroll
        for (int hi = 0; hi < 2; hi++) {
            size_t row = (size_t)bm + wm + mt * 16 + gid + hi * 8;
            #pragma unroll
            for (int nt = 0; nt < 8; nt++) {
                int col = bn + wn + nt * 8 + tig * 2;
                float v0 = acc[mt][nt][hi * 2 + 0] + bias[col];
                float v1 = acc[mt][nt][hi * 2 + 1] + bias[col + 1];
                if (Rres != nullptr) {
                    float2 rr = *(const float2*)(Rres + row * (size_t)N + col);
                    v0 += rr.x; v1 += rr.y;
                }
                *(float2*)(C + row * (size_t)N + col) = make_float2(v0, v1);
            }
        }
    }
}

// ---------------- bucketization + gathered pos tables -------------------------
__device__ __forceinline__ int bucket_idx_dev(int d)
{
    int ad = d < 0 ? -d : d;
    int v;
    if (ad <= 128) {
        v = d;
    } else {
        float t = logf((float)ad / 128.0f);
        t = t / 0.6892332713f;                   // fp32(ln(255/128))
        t = t * 127.0f;
        float lp = ceilf(t) + 128.0f;
        v = (int)(d < 0 ? -lp : lp);
    }
    v += 256;
    return v < 0 ? 0 : (v > 511 ? 511 : v);
}

__global__ void build_pos(const float* __restrict__ PK, const float* __restrict__ PQ,
                          float* __restrict__ PKG, float* __restrict__ PQG)
{
    int dd = blockIdx.x;                         // 0..510
    int t  = threadIdx.x;                        // 0..767
    int p  = bucket_idx_dev(dd - 383);
    int h  = t >> 6;
    int d  = t & 63;
    size_t dst = ((size_t)h * 511 + dd) * HD_ + d;
    size_t src = (size_t)p * H_ + t;
    PKG[dst] = PK[src];
    PQG[dst] = PQ[src];
}

// ---------------- attention: one CTA per (head, block, batch) ----------------
__global__ void __launch_bounds__(128) attn_kernel(
    const float* __restrict__ Q, const float* __restrict__ K,
    const float* __restrict__ V,
    const float* __restrict__ PKG, const float* __restrict__ PQG,
    float* __restrict__ CTX)
{
    extern __shared__ float sm[];
    float* ksh  = sm;                            // KC_*HD_  = 4096
    float* vsh  = ksh + KC_ * HD_;               // 4096
    float* pks  = vsh + KC_ * HD_;               // NROW_*PST_ = 12415
    float* pqs  = pks + NROW_ * PST_;            // 12415
    float* sbuf = pqs + NROW_ * PST_;            // 128*SBST_  = 8320

    const int h = blockIdx.x, n = blockIdx.y, b = blockIdx.z;
    const int tid = threadIdx.x;                 // q row
    const size_t qrow0 = (size_t)b * S_ + (size_t)n * 128;
    const size_t hoff  = (size_t)h * HD_;

    for (int i = tid; i < 128 * HD_; i += 128) {
        int r = i >> 6, c = i & 63;
        pks[r * PST_ + c] = Q[(qrow0 + r) * H_ + hoff + c];
    }
    __syncthreads();
    float qv[HD_];
    #pragma unroll
    for (int d = 0; d < HD_; d++) qv[d] = pks[tid * PST_ + d];
    __syncthreads();

    float ctx[HD_];
    #pragma unroll
    for (int d = 0; d < HD_; d++) ctx[d] = 0.f;
    float m = -1e30f, l = 0.f;
    const float scale = 0.07216878364870323f;    // 1/sqrt(192)

    const float* pkgh = PKG + (size_t)h * 511 * HD_;
    const float* pqgh = PQG + (size_t)h * 511 * HD_;

    for (int c0 = 0; c0 < WIN_; c0 += KC_) {
        const long sk0 = (long)n * 128 - 128 + c0;

        for (int i = tid; i < KC_ * 16; i += 128) {
            int r  = i >> 4;
            int c4 = (i & 15) << 2;
            long s = sk0 + r;
            float4 kv, vv;
            if (s >= 0 && s < S_) {
                size_t g = ((size_t)b * S_ + s) * H_ + hoff + c4;
                kv = *(const float4*)(K + g);
                vv = *(const float4*)(V + g);
            } else {
                kv = make_float4(0.f, 0.f, 0.f, 0.f);
                vv = make_float4(0.f, 0.f, 0.f, 0.f);
            }
            *(float4*)(ksh + r * HD_ + c4) = kv;
            *(float4*)(vsh + r * HD_ + c4) = vv;
        }

        const int ddb = 320 - c0;
        for (int i = tid; i < NROW_ * HD_; i += 128) {
            int rr = i >> 6, d = i & 63;
            pks[rr * PST_ + d] = pkgh[(size_t)(ddb + rr) * HD_ + d];
            pqs[rr * PST_ + d] = pqgh[(size_t)(ddb + rr) * HD_ + d];
        }
        __syncthreads();

        float mb = -1e30f;
        float* srow = sbuf + tid * SBST_;
        for (int j = 0; j < KC_; ++j) {
            const float* kr  = ksh + j * HD_;
            const float* pkr = pks + (tid - j + 63) * PST_;
            const float* pqr = pqs + (tid - j + 63) * PST_;
            float a1 = 0.f, a2 = 0.f, a3 = 0.f;
            #pragma unroll
            for (int d = 0; d < HD_; d++) {
                float kd = kr[d];
                a1 = fmaf(qv[d], kd,     a1);
                a2 = fmaf(qv[d], pkr[d], a2);
                a3 = fmaf(kd,    pqr[d], a3);
            }
            float sv = (a1 + a2 + a3) * scale;
            srow[j] = sv;
            mb = fmaxf(mb, sv);
        }

        float mnew = fmaxf(m, mb);
        float corr = __expf(m - mnew);
        float lb = 0.f;
        for (int j = 0; j < KC_; j++) {
            float p = __expf(srow[j] - mnew);
            srow[j] = p;
            lb += p;
        }
        l = l * corr + lb;
        m = mnew;

        #pragma unroll
        for (int d = 0; d < HD_; d++) ctx[d] *= corr;
        for (int j = 0; j < KC_; j++) {
            float p = srow[j];
            const float* vr = vsh + j * HD_;
            #pragma unroll
            for (int d = 0; d < HD_; d++) ctx[d] = fmaf(p, vr[d], ctx[d]);
        }
        __syncthreads();
    }

    float invl = 1.0f / l;
    #pragma unroll
    for (int d = 0; d < HD_; d++) pks[tid * PST_ + d] = ctx[d] * invl;
    __syncthreads();
    for (int i = tid; i < 128 * HD_; i += 128) {
        int r = i >> 6, c = i & 63;
        CTX[(qrow0 + r) * H_ + hoff + c] = pks[r * PST_ + c];
    }
}

// ---------------- LayerNorm over H=768, one row per CTA ----------------------
__global__ void __launch_bounds__(256) ln_kernel(
    const float* __restrict__ X, const float* __restrict__ gam,
    const float* __restrict__ bet, float* __restrict__ out)
{
    const int row = blockIdx.x;
    const int t   = threadIdx.x;
    const float* x = X + (size_t)row * H_;
    float v0 = x[t], v1 = x[t + 256], v2 = x[t + 512];
    float s = v0 + v1 + v2;
    float q = v0 * v0 + v1 * v1 + v2 * v2;

    __shared__ float sh[64];
    #pragma unroll
    for (int o = 16; o > 0; o >>= 1) {
        s += __shfl_down_sync(0xffffffffu, s, o);
        q += __shfl_down_sync(0xffffffffu, q, o);
    }
    int w = t >> 5, lane = t & 31;
    if (lane == 0) { sh[w] = s; sh[32 + w] = q; }
    __syncthreads();
    if (t == 0) {
        float ts = 0.f, tq = 0.f;
        #pragma unroll
        for (int i = 0; i < 8; i++) { ts += sh[i]; tq += sh[32 + i]; }
        sh[0] = ts;
        sh[32] = tq;
    }
    __syncthreads();
    float mu  = sh[0] * (1.0f / 768.0f);
    float var = sh[32] * (1.0f / 768.0f) - mu * mu;
    float r   = rsqrtf(var + 1e-7f);

    float* o = out + (size_t)row * H_;
    o[t]       = (v0 - mu) * r * gam[t]       + bet[t];
    o[t + 256] = (v1 - mu) * r * gam[t + 256] + bet[t + 256];
    o[t + 512] = (v2 - mu) * r * gam[t + 512] + bet[t + 512];
}

// ---------------- launch ------------------------------------------------------
extern "C" void kernel_launch(void* const* d_in, const int* in_sizes, int n_in,
                              void* d_out, int out_size)
{
    const float* hidden = (const float*)d_in[0];
    const float* rel    = (const float*)d_in[1];
    const float* Wq = (const float*)d_in[2];  const float* bq = (const float*)d_in[3];
    const float* Wk = (const float*)d_in[4];  const float* bk = (const float*)d_in[5];
    const float* Wv = (const float*)d_in[6];  const float* bv = (const float*)d_in[7];
    const float* Wo = (const float*)d_in[8];  const float* bo = (const float*)d_in[9];
    const float* lns = (const float*)d_in[10];
    const float* lnb = (const float*)d_in[11];
    float* out = (float*)d_out;

    float *Qp, *Kp, *Vp, *PK, *PQ, *PKG, *PQG, *CT, *XR;
    cudaGetSymbolAddress((void**)&Qp,  g_Q);
    cudaGetSymbolAddress((void**)&Kp,  g_K);
    cudaGetSymbolAddress((void**)&Vp,  g_V);
    cudaGetSymbolAddress((void**)&PK,  g_PK);
    cudaGetSymbolAddress((void**)&PQ,  g_PQ);
    cudaGetSymbolAddress((void**)&PKG, g_PKG);
    cudaGetSymbolAddress((void**)&PQG, g_PQG);
    cudaGetSymbolAddress((void**)&CT,  g_CTX);
    cudaGetSymbolAddress((void**)&XR,  g_XR);

    const int M = B_ * S_;                       // 32768

    dim3 gBig(H_ / 128, M / 128);                // (6, 256)
    dim3 gPos(H_ / 128, 512 / 128);              // (6, 4)

    // QKV projections (tf32 tensor cores)
    tf32_gemm<<<gBig, 256>>>(hidden, Wq, bq, nullptr, Qp, M, H_, H_);
    tf32_gemm<<<gBig, 256>>>(hidden, Wk, bk, nullptr, Kp, M, H_, H_);
    tf32_gemm<<<gBig, 256>>>(hidden, Wv, bv, nullptr, Vp, M, H_, H_);

    // positional projections (shared Wq/Wk) + gathered tables
    tf32_gemm<<<gPos, 256>>>(rel, Wk, bk, nullptr, PK, 512, H_, H_);
    tf32_gemm<<<gPos, 256>>>(rel, Wq, bq, nullptr, PQ, 512, H_, H_);
    build_pos<<<511, 768>>>(PK, PQ, PKG, PQG);

    // attention
    const int smem_attn = (KC_ * HD_ * 2 + NROW_ * PST_ * 2 + 128 * SBST_) * 4;
    cudaFuncSetAttribute(attn_kernel,
                         cudaFuncAttributeMaxDynamicSharedMemorySize, smem_attn);
    attn_kernel<<<dim3(NH_, NB_, B_), 128, smem_attn>>>(Qp, Kp, Vp, PKG, PQG, CT);

    // output projection + residual, then layernorm
    tf32_gemm<<<gBig, 256>>>(CT, Wo, bo, hidden, XR, M, H_, H_);
    ln_kernel<<<M, 256>>>(XR, lns, lnb, out);
}

// round 3
// speedup vs baseline: 2.7179x; 2.1252x over previous
#include <cuda_runtime.h>
#include <math.h>
#include <stdint.h>

#define B_   4
#define S_   8192
#define H_   768
#define NH_  12
#define HD_  64
#define NB_  64
#define TOT_ (B_*S_*H_)

// attention smem strides (floats), chosen for conflict-free fragment loads
#define QST 68
#define KST 68
#define VST 72
#define SST 132

// ---------------- scratch (device globals; no allocs allowed) ----------------
__device__ float g_Q[TOT_];
__device__ float g_K[TOT_];
__device__ float g_V[TOT_];
__device__ float g_CTX[TOT_];
__device__ float g_XR[TOT_];
__device__ float g_PK[512 * H_];
__device__ float g_PQ[512 * H_];
// transposed diff-gathered pos tables: [h][d][512]; col = dd+1, col0 = pad(0)
__device__ float g_PKT[NH_ * HD_ * 512];
__device__ float g_PQT[NH_ * HD_ * 512];

// ---------------- TF32 helpers ------------------------------------------------
__device__ __forceinline__ float cvt_tf32(float x) {
    uint32_t u;
    asm("cvt.rna.tf32.f32 %0, %1;" : "=r"(u) : "f"(x));
    return __uint_as_float(u);
}

__device__ __forceinline__ void mma_tf32(float* c, const uint32_t* a, const uint32_t* b) {
    asm volatile(
        "mma.sync.aligned.m16n8k8.row.col.f32.tf32.tf32.f32 "
        "{%0,%1,%2,%3},{%4,%5,%6,%7},{%8,%9},{%0,%1,%2,%3};\n"
        : "+f"(c[0]), "+f"(c[1]), "+f"(c[2]), "+f"(c[3])
        : "r"(a[0]), "r"(a[1]), "r"(a[2]), "r"(a[3]), "r"(b[0]), "r"(b[1]));
}

// ---------------- TF32 tensor-core GEMM (dense projections) -------------------
#define AST 20
#define BST 136

__global__ void __launch_bounds__(256) tf32_gemm(
    const float* __restrict__ A, const float* __restrict__ Bm,
    const float* __restrict__ bias, const float* __restrict__ Rres,
    float* __restrict__ C, int M, int N, int K)
{
    __shared__ float As[128 * AST];
    __shared__ float Bs[16 * BST];

    const int tid  = threadIdx.x;
    const int lane = tid & 31;
    const int warp = tid >> 5;
    const int wm   = (warp & 3) * 32;
    const int wn   = (warp >> 2) * 64;
    const int bm   = blockIdx.y * 128;
    const int bn   = blockIdx.x * 128;
    const int gid  = lane >> 2;
    const int tig  = lane & 3;

    float acc[2][8][4];
    #pragma unroll
    for (int mt = 0; mt < 2; mt++)
        #pragma unroll
        for (int nt = 0; nt < 8; nt++)
            #pragma unroll
            for (int i = 0; i < 4; i++) acc[mt][nt][i] = 0.f;

    for (int kt = 0; kt < K; kt += 16) {
        #pragma unroll
        for (int i = 0; i < 2; i++) {
            int id = tid + i * 256;
            int r  = id >> 2;
            int c4 = (id & 3) << 2;
            float4 v = *(const float4*)(A + (size_t)(bm + r) * K + kt + c4);
            v.x = cvt_tf32(v.x); v.y = cvt_tf32(v.y);
            v.z = cvt_tf32(v.z); v.w = cvt_tf32(v.w);
            *(float4*)&As[r * AST + c4] = v;
        }
        #pragma unroll
        for (int i = 0; i < 2; i++) {
            int id = tid + i * 256;
            int r  = id >> 5;
            int c4 = (id & 31) << 2;
            float4 v = *(const float4*)(Bm + (size_t)(kt + r) * N + bn + c4);
            v.x = cvt_tf32(v.x); v.y = cvt_tf32(v.y);
            v.z = cvt_tf32(v.z); v.w = cvt_tf32(v.w);
            *(float4*)&Bs[r * BST + c4] = v;
        }
        __syncthreads();

        #pragma unroll
        for (int ks = 0; ks < 2; ks++) {
            const int k8 = ks * 8;
            uint32_t a[2][4], b[8][2];
            #pragma unroll
            for (int mt = 0; mt < 2; mt++) {
                int r0 = wm + mt * 16 + gid;
                a[mt][0] = __float_as_uint(As[r0 * AST + k8 + tig]);
                a[mt][1] = __float_as_uint(As[(r0 + 8) * AST + k8 + tig]);
                a[mt][2] = __float_as_uint(As[r0 * AST + k8 + tig + 4]);
                a[mt][3] = __float_as_uint(As[(r0 + 8) * AST + k8 + tig + 4]);
            }
            #pragma unroll
            for (int nt = 0; nt < 8; nt++) {
                int cc = wn + nt * 8 + gid;
                b[nt][0] = __float_as_uint(Bs[(k8 + tig) * BST + cc]);
                b[nt][1] = __float_as_uint(Bs[(k8 + tig + 4) * BST + cc]);
            }
            #pragma unroll
            for (int mt = 0; mt < 2; mt++)
                #pragma unroll
                for (int nt = 0; nt < 8; nt++)
                    mma_tf32(acc[mt][nt], a[mt], b[nt]);
        }
        __syncthreads();
    }

    #pragma unroll
    for (int mt = 0; mt < 2; mt++) {
        #pragma unroll
        for (int hi = 0; hi < 2; hi++) {
            size_t row = (size_t)bm + wm + mt * 16 + gid + hi * 8;
            #pragma unroll
            for (int nt = 0; nt < 8; nt++) {
                int col = bn + wn + nt * 8 + tig * 2;
                float v0 = acc[mt][nt][hi * 2 + 0] + bias[col];
                float v1 = acc[mt][nt][hi * 2 + 1] + bias[col + 1];
                if (Rres != nullptr) {
                    float2 rr = *(const float2*)(Rres + row * (size_t)N + col);
                    v0 += rr.x; v1 += rr.y;
                }
                *(float2*)(C + row * (size_t)N + col) = make_float2(v0, v1);
            }
        }
    }
}

// ---------------- bucketization + transposed pos tables ----------------------
__device__ __forceinline__ int bucket_idx_dev(int d)
{
    int ad = d < 0 ? -d : d;
    int v;
    if (ad <= 128) {
        v = d;
    } else {
        float t = logf((float)ad / 128.0f);
        t = t / 0.6892332713f;                   // fp32(ln(255/128))
        t = t * 127.0f;
        float lp = ceilf(t) + 128.0f;
        v = (int)(d < 0 ? -lp : lp);
    }
    v += 256;
    return v < 0 ? 0 : (v > 511 ? 511 : v);
}

// PKT[(h*64+d)*512 + dd+1] = tf32(PK[bucket(dd-383)][h*64+d]); col 0 = 0 pad
__global__ void build_pos_t(const float* __restrict__ PK, const float* __restrict__ PQ,
                            float* __restrict__ PKT, float* __restrict__ PQT)
{
    int dd = blockIdx.x;                         // 0..510
    int t  = threadIdx.x;                        // 0..767
    int p  = bucket_idx_dev(dd - 383);
    size_t dst = (size_t)t * 512 + dd + 1;       // t = h*64+d
    PKT[dst] = cvt_tf32(PK[(size_t)p * H_ + t]);
    PQT[dst] = cvt_tf32(PQ[(size_t)p * H_ + t]);
    if (dd == 0) {
        PKT[(size_t)t * 512] = 0.f;
        PQT[(size_t)t * 512] = 0.f;
    }
}

// ---------------- MMA attention: one CTA per (head, block, batch) ------------
// chunk = 128 keys, 3 chunks. S assembled = c2c + scatter(C2P) + scatter(P2C),
// online softmax, ctx += P@V with warp-register accumulators.
__global__ void __launch_bounds__(256, 1) attn_mma(
    const float* __restrict__ Q, const float* __restrict__ K,
    const float* __restrict__ V,
    const float* __restrict__ PKT, const float* __restrict__ PQT,
    float* __restrict__ CTX)
{
    extern __shared__ float sm[];
    float* Qs   = sm;                    // 128*QST
    float* Ks   = Qs + 128 * QST;        // 128*KST
    float* Vs   = Ks + 128 * KST;        // 128*VST
    float* Ss   = Vs + 128 * VST;        // 128*SST
    float* mrow = Ss + 128 * SST;        // 128
    float* lrow = mrow + 128;            // 128
    float* crow = lrow + 128;            // 128
    float* pbuf = crow + 128;            // 256

    const int h = blockIdx.x, n = blockIdx.y, b = blockIdx.z;
    const int tid  = threadIdx.x;
    const int lane = tid & 31;
    const int warp = tid >> 5;
    const int gid  = lane >> 2;
    const int tig  = lane & 3;
    const size_t qrow0 = (size_t)b * S_ + (size_t)n * 128;
    const size_t hoff  = (size_t)h * HD_;

    // stage Q tile (tf32-rounded)
    for (int i = tid; i < 128 * 16; i += 256) {
        int r = i >> 4, c4 = (i & 15) << 2;
        float4 v = *(const float4*)(Q + (qrow0 + r) * H_ + hoff + c4);
        v.x = cvt_tf32(v.x); v.y = cvt_tf32(v.y);
        v.z = cvt_tf32(v.z); v.w = cvt_tf32(v.w);
        *(float4*)&Qs[r * QST + c4] = v;
    }
    if (tid < 128) { mrow[tid] = -1e30f; lrow[tid] = 0.f; }
    __syncthreads();

    float ctx[8][4];
    #pragma unroll
    for (int nt = 0; nt < 8; nt++)
        #pragma unroll
        for (int i = 0; i < 4; i++) ctx[nt][i] = 0.f;

    const float* pkt = PKT + (size_t)h * HD_ * 512;
    const float* pqt = PQT + (size_t)h * HD_ * 512;
    const float scale = 0.07216878364870323f;    // 1/sqrt(192)

    for (int c = 0; c < 3; c++) {
        const int  c0  = c * 128;
        const long sk0 = (long)n * 128 - 128 + c0;

        // stage K,V chunk (zero-pad outside sequence)
        for (int i = tid; i < 128 * 16; i += 256) {
            int r = i >> 4, c4 = (i & 15) << 2;
            long s = sk0 + r;
            float4 kv, vv;
            if (s >= 0 && s < S_) {
                size_t g = ((size_t)b * S_ + s) * H_ + hoff + c4;
                kv = *(const float4*)(K + g);
                vv = *(const float4*)(V + g);
                kv.x = cvt_tf32(kv.x); kv.y = cvt_tf32(kv.y);
                kv.z = cvt_tf32(kv.z); kv.w = cvt_tf32(kv.w);
                vv.x = cvt_tf32(vv.x); vv.y = cvt_tf32(vv.y);
                vv.z = cvt_tf32(vv.z); vv.w = cvt_tf32(vv.w);
            } else {
                kv = make_float4(0.f, 0.f, 0.f, 0.f);
                vv = kv;
            }
            *(float4*)&Ks[r * KST + c4] = kv;
            *(float4*)&Vs[r * VST + c4] = vv;
        }
        __syncthreads();

        // ---- c2c: S = Q @ K^T -------------------------------------------------
        {
            const int wm = (warp & 3) * 32, wn = (warp >> 2) * 64;
            float acc[2][8][4];
            #pragma unroll
            for (int mt = 0; mt < 2; mt++)
                #pragma unroll
                for (int nt = 0; nt < 8; nt++)
                    #pragma unroll
                    for (int i = 0; i < 4; i++) acc[mt][nt][i] = 0.f;

            #pragma unroll
            for (int ks = 0; ks < 8; ks++) {
                const int k8 = ks * 8;
                uint32_t a[2][4], bf[8][2];
                #pragma unroll
                for (int mt = 0; mt < 2; mt++) {
                    int r0 = wm + mt * 16 + gid;
                    a[mt][0] = __float_as_uint(Qs[r0 * QST + k8 + tig]);
                    a[mt][1] = __float_as_uint(Qs[(r0 + 8) * QST + k8 + tig]);
                    a[mt][2] = __float_as_uint(Qs[r0 * QST + k8 + tig + 4]);
                    a[mt][3] = __float_as_uint(Qs[(r0 + 8) * QST + k8 + tig + 4]);
                }
                #pragma unroll
                for (int nt = 0; nt < 8; nt++) {
                    int cc = wn + nt * 8 + gid;          // key index
                    bf[nt][0] = __float_as_uint(Ks[cc * KST + k8 + tig]);
                    bf[nt][1] = __float_as_uint(Ks[cc * KST + k8 + tig + 4]);
                }
                #pragma unroll
                for (int mt = 0; mt < 2; mt++)
                    #pragma unroll
                    for (int nt = 0; nt < 8; nt++)
                        mma_tf32(acc[mt][nt], a[mt], bf[nt]);
            }
            // store into S
            #pragma unroll
            for (int mt = 0; mt < 2; mt++) {
                int r1 = wm + mt * 16 + gid;
                #pragma unroll
                for (int nt = 0; nt < 8; nt++) {
                    int cc = wn + nt * 8 + 2 * tig;
                    *(float2*)&Ss[r1 * SST + cc] =
                        make_float2(acc[mt][nt][0], acc[mt][nt][1]);
                    *(float2*)&Ss[(r1 + 8) * SST + cc] =
                        make_float2(acc[mt][nt][2], acc[mt][nt][3]);
                }
            }
        }
        __syncthreads();

        // ---- C2P: Q @ PKT_slice, scatter-add S[q][q-col+128] ------------------
        {
            const int wm = (warp & 3) * 32, wn2 = (warp >> 2) * 128;
            const int colbase = 256 - c0;
            #pragma unroll
            for (int half = 0; half < 2; half++) {
                const int cb = wn2 + half * 64;
                float acc[2][8][4];
                #pragma unroll
                for (int mt = 0; mt < 2; mt++)
                    #pragma unroll
                    for (int nt = 0; nt < 8; nt++)
                        #pragma unroll
                        for (int i = 0; i < 4; i++) acc[mt][nt][i] = 0.f;

                #pragma unroll
                for (int ks = 0; ks < 8; ks++) {
                    const int k8 = ks * 8;
                    uint32_t a[2][4], bf[8][2];
                    #pragma unroll
                    for (int mt = 0; mt < 2; mt++) {
                        int r0 = wm + mt * 16 + gid;
                        a[mt][0] = __float_as_uint(Qs[r0 * QST + k8 + tig]);
                        a[mt][1] = __float_as_uint(Qs[(r0 + 8) * QST + k8 + tig]);
                        a[mt][2] = __float_as_uint(Qs[r0 * QST + k8 + tig + 4]);
                        a[mt][3] = __float_as_uint(Qs[(r0 + 8) * QST + k8 + tig + 4]);
                    }
                    #pragma unroll
                    for (int nt = 0; nt < 8; nt++) {
                        int cc = colbase + cb + nt * 8 + gid;
                        bf[nt][0] = __float_as_uint(__ldg(&pkt[(size_t)(k8 + tig) * 512 + cc]));
                        bf[nt][1] = __float_as_uint(__ldg(&pkt[(size_t)(k8 + tig + 4) * 512 + cc]));
                    }
                    #pragma unroll
                    for (int mt = 0; mt < 2; mt++)
                        #pragma unroll
                        for (int nt = 0; nt < 8; nt++)
                            mma_tf32(acc[mt][nt], a[mt], bf[nt]);
                }
                // scatter-add: jj = r - cidx + 128
                #pragma unroll
                for (int mt = 0; mt < 2; mt++) {
                    int r1 = wm + mt * 16 + gid;
                    #pragma unroll
                    for (int nt = 0; nt < 8; nt++) {
                        int ci = cb + nt * 8 + 2 * tig;
                        int jj;
                        jj = r1 - ci + 128;
                        if (jj >= 0 && jj < 128) Ss[r1 * SST + jj] += acc[mt][nt][0];
                        jj = r1 - ci + 127;
                        if (jj >= 0 && jj < 128) Ss[r1 * SST + jj] += acc[mt][nt][1];
                        int r2 = r1 + 8;
                        jj = r2 - ci + 128;
                        if (jj >= 0 && jj < 128) Ss[r2 * SST + jj] += acc[mt][nt][2];
                        jj = r2 - ci + 127;
                        if (jj >= 0 && jj < 128) Ss[r2 * SST + jj] += acc[mt][nt][3];
                    }
                }
                __syncthreads();
            }
        }

        // ---- P2C: K @ PQT_slice, scatter-add S[jj+col-128][jj] ---------------
        {
            const int wm = (warp & 3) * 32, wn2 = (warp >> 2) * 128;
            const int colbase = 256 - c0;
            #pragma unroll
            for (int half = 0; half < 2; half++) {
                const int cb = wn2 + half * 64;
                float acc[2][8][4];
                #pragma unroll
                for (int mt = 0; mt < 2; mt++)
                    #pragma unroll
                    for (int nt = 0; nt < 8; nt++)
                        #pragma unroll
                        for (int i = 0; i < 4; i++) acc[mt][nt][i] = 0.f;

                #pragma unroll
                for (int ks = 0; ks < 8; ks++) {
                    const int k8 = ks * 8;
                    uint32_t a[2][4], bf[8][2];
                    #pragma unroll
                    for (int mt = 0; mt < 2; mt++) {
                        int r0 = wm + mt * 16 + gid;
                        a[mt][0] = __float_as_uint(Ks[r0 * KST + k8 + tig]);
                        a[mt][1] = __float_as_uint(Ks[(r0 + 8) * KST + k8 + tig]);
                        a[mt][2] = __float_as_uint(Ks[r0 * KST + k8 + tig + 4]);
                        a[mt][3] = __float_as_uint(Ks[(r0 + 8) * KST + k8 + tig + 4]);
                    }
                    #pragma unroll
                    for (int nt = 0; nt < 8; nt++) {
                        int cc = colbase + cb + nt * 8 + gid;
                        bf[nt][0] = __float_as_uint(__ldg(&pqt[(size_t)(k8 + tig) * 512 + cc]));
                        bf[nt][1] = __float_as_uint(__ldg(&pqt[(size_t)(k8 + tig + 4) * 512 + cc]));
                    }
                    #pragma unroll
                    for (int mt = 0; mt < 2; mt++)
                        #pragma unroll
                        for (int nt = 0; nt < 8; nt++)
                            mma_tf32(acc[mt][nt], a[mt], bf[nt]);
                }
                // scatter-add: q = jj + cidx - 128
                #pragma unroll
                for (int mt = 0; mt < 2; mt++) {
                    int r1 = wm + mt * 16 + gid;     // jj
                    #pragma unroll
                    for (int nt = 0; nt < 8; nt++) {
                        int ci = cb + nt * 8 + 2 * tig;
                        int q;
                        q = r1 + ci - 128;
                        if (q >= 0 && q < 128) Ss[q * SST + r1] += acc[mt][nt][0];
                        q = r1 + ci - 127;
                        if (q >= 0 && q < 128) Ss[q * SST + r1] += acc[mt][nt][1];
                        int r2 = r1 + 8;
                        q = r2 + ci - 128;
                        if (q >= 0 && q < 128) Ss[q * SST + r2] += acc[mt][nt][2];
                        q = r2 + ci - 127;
                        if (q >= 0 && q < 128) Ss[q * SST + r2] += acc[mt][nt][3];
                    }
                }
                __syncthreads();
            }
        }

        // ---- online softmax (2 threads per row) ------------------------------
        {
            const int r  = tid & 127;
            const int hh = tid >> 7;
            float* srow = Ss + r * SST + hh * 64;
            float mx = -1e30f;
            #pragma unroll 8
            for (int j = 0; j < 64; j++) mx = fmaxf(mx, srow[j]);
            pbuf[tid] = mx;
            __syncthreads();
            if (tid < 128) {
                float mb   = fmaxf(pbuf[tid], pbuf[tid + 128]) * scale;
                float mold = mrow[tid];
                float mnew = fmaxf(mold, mb);
                crow[tid]  = __expf(mold - mnew);
                mrow[tid]  = mnew;
            }
            __syncthreads();
            float mnew = mrow[r];
            float ssum = 0.f;
            #pragma unroll 8
            for (int j = 0; j < 64; j++) {
                float p = __expf(srow[j] * scale - mnew);
                srow[j] = p;
                ssum += p;
            }
            pbuf[tid] = ssum;
            __syncthreads();
            if (tid < 128)
                lrow[tid] = lrow[tid] * crow[tid] + pbuf[tid] + pbuf[tid + 128];
            __syncthreads();
        }

        // ---- PV: ctx = ctx*corr + P @ V --------------------------------------
        {
            const int wm1 = warp * 16;
            float c1 = crow[wm1 + gid], c2 = crow[wm1 + gid + 8];
            #pragma unroll
            for (int nt = 0; nt < 8; nt++) {
                ctx[nt][0] *= c1; ctx[nt][1] *= c1;
                ctx[nt][2] *= c2; ctx[nt][3] *= c2;
            }
            #pragma unroll
            for (int ks = 0; ks < 16; ks++) {
                const int k8 = ks * 8;
                uint32_t a[4], bf[8][2];
                int r0 = wm1 + gid;
                a[0] = __float_as_uint(Ss[r0 * SST + k8 + tig]);
                a[1] = __float_as_uint(Ss[(r0 + 8) * SST + k8 + tig]);
                a[2] = __float_as_uint(Ss[r0 * SST + k8 + tig + 4]);
                a[3] = __float_as_uint(Ss[(r0 + 8) * SST + k8 + tig + 4]);
                #pragma unroll
                for (int nt = 0; nt < 8; nt++) {
                    int cc = nt * 8 + gid;
                    bf[nt][0] = __float_as_uint(Vs[(k8 + tig) * VST + cc]);
                    bf[nt][1] = __float_as_uint(Vs[(k8 + tig + 4) * VST + cc]);
                }
                #pragma unroll
                for (int nt = 0; nt < 8; nt++)
                    mma_tf32(ctx[nt], a, bf[nt]);
            }
        }
        __syncthreads();
    }

    // ---- write ctx / l -------------------------------------------------------
    {
        const int wm1 = warp * 16;
        float inv1 = 1.0f / lrow[wm1 + gid];
        float inv2 = 1.0f / lrow[wm1 + gid + 8];
        size_t row1 = qrow0 + wm1 + gid;
        size_t row2 = row1 + 8;
        #pragma unroll
        for (int nt = 0; nt < 8; nt++) {
            int col = nt * 8 + 2 * tig;
            *(float2*)(CTX + row1 * H_ + hoff + col) =
                make_float2(ctx[nt][0] * inv1, ctx[nt][1] * inv1);
            *(float2*)(CTX + row2 * H_ + hoff + col) =
                make_float2(ctx[nt][2] * inv2, ctx[nt][3] * inv2);
        }
    }
}

// ---------------- LayerNorm over H=768, one row per CTA ----------------------
__global__ void __launch_bounds__(256) ln_kernel(
    const float* __restrict__ X, const float* __restrict__ gam,
    const float* __restrict__ bet, float* __restrict__ out)
{
    const int row = blockIdx.x;
    const int t   = threadIdx.x;
    const float* x = X + (size_t)row * H_;
    float v0 = x[t], v1 = x[t + 256], v2 = x[t + 512];
    float s = v0 + v1 + v2;
    float q = v0 * v0 + v1 * v1 + v2 * v2;

    __shared__ float sh[64];
    #pragma unroll
    for (int o = 16; o > 0; o >>= 1) {
        s += __shfl_down_sync(0xffffffffu, s, o);
        q += __shfl_down_sync(0xffffffffu, q, o);
    }
    int w = t >> 5, lane = t & 31;
    if (lane == 0) { sh[w] = s; sh[32 + w] = q; }
    __syncthreads();
    if (t == 0) {
        float ts = 0.f, tq = 0.f;
        #pragma unroll
        for (int i = 0; i < 8; i++) { ts += sh[i]; tq += sh[32 + i]; }
        sh[0] = ts;
        sh[32] = tq;
    }
    __syncthreads();
    float mu  = sh[0] * (1.0f / 768.0f);
    float var = sh[32] * (1.0f / 768.0f) - mu * mu;
    float r   = rsqrtf(var + 1e-7f);

    float* o = out + (size_t)row * H_;
    o[t]       = (v0 - mu) * r * gam[t]       + bet[t];
    o[t + 256] = (v1 - mu) * r * gam[t + 256] + bet[t + 256];
    o[t + 512] = (v2 - mu) * r * gam[t + 512] + bet[t + 512];
}

// ---------------- launch ------------------------------------------------------
extern "C" void kernel_launch(void* const* d_in, const int* in_sizes, int n_in,
                              void* d_out, int out_size)
{
    const float* hidden = (const float*)d_in[0];
    const float* rel    = (const float*)d_in[1];
    const float* Wq = (const float*)d_in[2];  const float* bq = (const float*)d_in[3];
    const float* Wk = (const float*)d_in[4];  const float* bk = (const float*)d_in[5];
    const float* Wv = (const float*)d_in[6];  const float* bv = (const float*)d_in[7];
    const float* Wo = (const float*)d_in[8];  const float* bo = (const float*)d_in[9];
    const float* lns = (const float*)d_in[10];
    const float* lnb = (const float*)d_in[11];
    float* out = (float*)d_out;

    float *Qp, *Kp, *Vp, *PK, *PQ, *PKT, *PQT, *CT, *XR;
    cudaGetSymbolAddress((void**)&Qp,  g_Q);
    cudaGetSymbolAddress((void**)&Kp,  g_K);
    cudaGetSymbolAddress((void**)&Vp,  g_V);
    cudaGetSymbolAddress((void**)&PK,  g_PK);
    cudaGetSymbolAddress((void**)&PQ,  g_PQ);
    cudaGetSymbolAddress((void**)&PKT, g_PKT);
    cudaGetSymbolAddress((void**)&PQT, g_PQT);
    cudaGetSymbolAddress((void**)&CT,  g_CTX);
    cudaGetSymbolAddress((void**)&XR,  g_XR);

    const int M = B_ * S_;                       // 32768

    dim3 gBig(H_ / 128, M / 128);                // (6, 256)
    dim3 gPos(H_ / 128, 512 / 128);              // (6, 4)

    // QKV projections (tf32 tensor cores)
    tf32_gemm<<<gBig, 256>>>(hidden, Wq, bq, nullptr, Qp, M, H_, H_);
    tf32_gemm<<<gBig, 256>>>(hidden, Wk, bk, nullptr, Kp, M, H_, H_);
    tf32_gemm<<<gBig, 256>>>(hidden, Wv, bv, nullptr, Vp, M, H_, H_);

    // positional projections (shared Wq/Wk) + transposed diff tables
    tf32_gemm<<<gPos, 256>>>(rel, Wk, bk, nullptr, PK, 512, H_, H_);
    tf32_gemm<<<gPos, 256>>>(rel, Wq, bq, nullptr, PQ, 512, H_, H_);
    build_pos_t<<<511, 768>>>(PK, PQ, PKT, PQT);

    // MMA attention
    const int smem_attn =
        (128 * QST + 128 * KST + 128 * VST + 128 * SST + 3 * 128 + 256) * 4;
    cudaFuncSetAttribute(attn_mma,
                         cudaFuncAttributeMaxDynamicSharedMemorySize, smem_attn);
    attn_mma<<<dim3(NH_, NB_, B_), 256, smem_attn>>>(Qp, Kp, Vp, PKT, PQT, CT);

    // output projection + residual, then layernorm
    tf32_gemm<<<gBig, 256>>>(CT, Wo, bo, hidden, XR, M, H_, H_);
    ln_kernel<<<M, 256>>>(XR, lns, lnb, out);
}

// round 4
// speedup vs baseline: 2.9826x; 1.0974x over previous
#include <cuda_runtime.h>
#include <math.h>
#include <stdint.h>

#define B_   4
#define S_   8192
#define H_   768
#define NH_  12
#define HD_  64
#define NB_  64
#define TOT_ (B_*S_*H_)

// attention smem strides (floats), chosen for conflict-free fragment loads
#define QST 68
#define KST 68
#define VST 72
#define SST 132

// gemm smem strides
#define AST 20
#define BST 136
#define ASTAGE (128 * AST)     // floats per A stage
#define BSTAGE (16 * BST)      // floats per B stage
#define NSTAGE 4

// ---------------- scratch (device globals; no allocs allowed) ----------------
__device__ float g_Q[TOT_];
__device__ float g_K[TOT_];
__device__ float g_V[TOT_];
__device__ float g_CTX[TOT_];
__device__ float g_XR[TOT_];
__device__ float g_PK[512 * H_];
__device__ float g_PQ[512 * H_];
// transposed diff-gathered pos tables: [h][d][512]; col = dd+1, col0 = pad(0)
__device__ float g_PKT[NH_ * HD_ * 512];
__device__ float g_PQT[NH_ * HD_ * 512];

// ---------------- TF32 helpers ------------------------------------------------
__device__ __forceinline__ float cvt_tf32(float x) {
    uint32_t u;
    asm("cvt.rna.tf32.f32 %0, %1;" : "=r"(u) : "f"(x));
    return __uint_as_float(u);
}

__device__ __forceinline__ void mma_tf32(float* c, const uint32_t* a, const uint32_t* b) {
    asm volatile(
        "mma.sync.aligned.m16n8k8.row.col.f32.tf32.tf32.f32 "
        "{%0,%1,%2,%3},{%4,%5,%6,%7},{%8,%9},{%0,%1,%2,%3};\n"
        : "+f"(c[0]), "+f"(c[1]), "+f"(c[2]), "+f"(c[3])
        : "r"(a[0]), "r"(a[1]), "r"(a[2]), "r"(a[3]), "r"(b[0]), "r"(b[1]));
}

__device__ __forceinline__ void cp16(float* dst_smem, const float* src) {
    uint32_t d = (uint32_t)__cvta_generic_to_shared(dst_smem);
    asm volatile("cp.async.cg.shared.global [%0], [%1], 16;\n" :: "r"(d), "l"(src));
}
__device__ __forceinline__ void cp_commit() {
    asm volatile("cp.async.commit_group;\n");
}

// ---------------- TF32 tensor-core GEMM, 4-stage cp.async pipeline ------------
// C = A[M,K] @ B[K,N] + bias (+ residual). 128x128 tile, BK=16, 256 threads,
// 8 warps 4(m)x2(n), each 32x64 via m16n8k8. fp32 fed raw (HW tf32 truncation).
__global__ void __launch_bounds__(256) tf32_gemm(
    const float* __restrict__ A, const float* __restrict__ Bm,
    const float* __restrict__ bias, const float* __restrict__ Rres,
    float* __restrict__ C, int M, int N, int K)
{
    extern __shared__ float smg[];
    float* As = smg;                         // NSTAGE * ASTAGE
    float* Bs = smg + NSTAGE * ASTAGE;       // NSTAGE * BSTAGE

    const int tid  = threadIdx.x;
    const int lane = tid & 31;
    const int warp = tid >> 5;
    const int wm   = (warp & 3) * 32;
    const int wn   = (warp >> 2) * 64;
    const int bm   = blockIdx.y * 128;
    const int bn   = blockIdx.x * 128;
    const int gid  = lane >> 2;
    const int tig  = lane & 3;

    // per-thread fill coordinates
    const int ar  = tid >> 1;                // 0..127   (A row; 2 thr/row)
    const int ac4 = (tid & 1) << 3;          // 0 or 8 -> two float4 each
    const int br  = tid >> 4;                // 0..15    (B row)
    const int bc4 = (tid & 15) << 3;         // 0..120 step 8 -> two float4

    const int T = K >> 4;

    float acc[2][8][4];
    #pragma unroll
    for (int mt = 0; mt < 2; mt++)
        #pragma unroll
        for (int nt = 0; nt < 8; nt++)
            #pragma unroll
            for (int i = 0; i < 4; i++) acc[mt][nt][i] = 0.f;

    // fill stage s with k-tile kt
    auto fill = [&](int s, int kt) {
        const int kb = kt << 4;
        float* as = As + s * ASTAGE;
        float* bs = Bs + s * BSTAGE;
        cp16(&as[ar * AST + ac4],     A + (size_t)(bm + ar) * K + kb + ac4);
        cp16(&as[ar * AST + ac4 + 4], A + (size_t)(bm + ar) * K + kb + ac4 + 4);
        cp16(&bs[br * BST + bc4],     Bm + (size_t)(kb + br) * N + bn + bc4);
        cp16(&bs[br * BST + bc4 + 4], Bm + (size_t)(kb + br) * N + bn + bc4 + 4);
    };

    #pragma unroll
    for (int s = 0; s < NSTAGE - 1; s++) { fill(s, s); cp_commit(); }

    for (int kt = 0; kt < T; kt++) {
        asm volatile("cp.async.wait_group %0;\n" :: "n"(NSTAGE - 2));
        __syncthreads();

        const float* as = As + (kt & (NSTAGE - 1)) * ASTAGE;
        const float* bs = Bs + (kt & (NSTAGE - 1)) * BSTAGE;

        #pragma unroll
        for (int ks = 0; ks < 2; ks++) {
            const int k8 = ks * 8;
            uint32_t a[2][4], b[8][2];
            #pragma unroll
            for (int mt = 0; mt < 2; mt++) {
                int r0 = wm + mt * 16 + gid;
                a[mt][0] = __float_as_uint(as[r0 * AST + k8 + tig]);
                a[mt][1] = __float_as_uint(as[(r0 + 8) * AST + k8 + tig]);
                a[mt][2] = __float_as_uint(as[r0 * AST + k8 + tig + 4]);
                a[mt][3] = __float_as_uint(as[(r0 + 8) * AST + k8 + tig + 4]);
            }
            #pragma unroll
            for (int nt = 0; nt < 8; nt++) {
                int cc = wn + nt * 8 + gid;
                b[nt][0] = __float_as_uint(bs[(k8 + tig) * BST + cc]);
                b[nt][1] = __float_as_uint(bs[(k8 + tig + 4) * BST + cc]);
            }
            #pragma unroll
            for (int mt = 0; mt < 2; mt++)
                #pragma unroll
                for (int nt = 0; nt < 8; nt++)
                    mma_tf32(acc[mt][nt], a[mt], b[nt]);
        }
        __syncthreads();

        if (kt + NSTAGE - 1 < T)
            fill((kt + NSTAGE - 1) & (NSTAGE - 1), kt + NSTAGE - 1);
        cp_commit();
    }

    #pragma unroll
    for (int mt = 0; mt < 2; mt++) {
        #pragma unroll
        for (int hi = 0; hi < 2; hi++) {
            size_t row = (size_t)bm + wm + mt * 16 + gid + hi * 8;
            #pragma unroll
            for (int nt = 0; nt < 8; nt++) {
                int col = bn + wn + nt * 8 + tig * 2;
                float v0 = acc[mt][nt][hi * 2 + 0] + bias[col];
                float v1 = acc[mt][nt][hi * 2 + 1] + bias[col + 1];
                if (Rres != nullptr) {
                    float2 rr = *(const float2*)(Rres + row * (size_t)N + col);
                    v0 += rr.x; v1 += rr.y;
                }
                *(float2*)(C + row * (size_t)N + col) = make_float2(v0, v1);
            }
        }
    }
}

// ---------------- bucketization + transposed pos tables ----------------------
__device__ __forceinline__ int bucket_idx_dev(int d)
{
    int ad = d < 0 ? -d : d;
    int v;
    if (ad <= 128) {
        v = d;
    } else {
        float t = logf((float)ad / 128.0f);
        t = t / 0.6892332713f;                   // fp32(ln(255/128))
        t = t * 127.0f;
        float lp = ceilf(t) + 128.0f;
        v = (int)(d < 0 ? -lp : lp);
    }
    v += 256;
    return v < 0 ? 0 : (v > 511 ? 511 : v);
}

// PKT[(h*64+d)*512 + dd+1] = tf32(PK[bucket(dd-383)][h*64+d]); col 0 = 0 pad
__global__ void build_pos_t(const float* __restrict__ PK, const float* __restrict__ PQ,
                            float* __restrict__ PKT, float* __restrict__ PQT)
{
    int dd = blockIdx.x;                         // 0..510
    int t  = threadIdx.x;                        // 0..767
    int p  = bucket_idx_dev(dd - 383);
    size_t dst = (size_t)t * 512 + dd + 1;       // t = h*64+d
    PKT[dst] = cvt_tf32(PK[(size_t)p * H_ + t]);
    PQT[dst] = cvt_tf32(PQ[(size_t)p * H_ + t]);
    if (dd == 0) {
        PKT[(size_t)t * 512] = 0.f;
        PQT[(size_t)t * 512] = 0.f;
    }
}

// ---------------- MMA attention: one CTA per (head, block, batch) ------------
__global__ void __launch_bounds__(256, 1) attn_mma(
    const float* __restrict__ Q, const float* __restrict__ K,
    const float* __restrict__ V,
    const float* __restrict__ PKT, const float* __restrict__ PQT,
    float* __restrict__ CTX)
{
    extern __shared__ float sm[];
    float* Qs   = sm;                    // 128*QST
    float* Ks   = Qs + 128 * QST;        // 128*KST
    float* Vs   = Ks + 128 * KST;        // 128*VST
    float* Ss   = Vs + 128 * VST;        // 128*SST
    float* mrow = Ss + 128 * SST;        // 128
    float* lrow = mrow + 128;            // 128
    float* crow = lrow + 128;            // 128
    float* pbuf = crow + 128;            // 256

    const int h = blockIdx.x, n = blockIdx.y, b = blockIdx.z;
    const int tid  = threadIdx.x;
    const int lane = tid & 31;
    const int warp = tid >> 5;
    const int gid  = lane >> 2;
    const int tig  = lane & 3;
    const size_t qrow0 = (size_t)b * S_ + (size_t)n * 128;
    const size_t hoff  = (size_t)h * HD_;

    for (int i = tid; i < 128 * 16; i += 256) {
        int r = i >> 4, c4 = (i & 15) << 2;
        float4 v = *(const float4*)(Q + (qrow0 + r) * H_ + hoff + c4);
        v.x = cvt_tf32(v.x); v.y = cvt_tf32(v.y);
        v.z = cvt_tf32(v.z); v.w = cvt_tf32(v.w);
        *(float4*)&Qs[r * QST + c4] = v;
    }
    if (tid < 128) { mrow[tid] = -1e30f; lrow[tid] = 0.f; }
    __syncthreads();

    float ctx[8][4];
    #pragma unroll
    for (int nt = 0; nt < 8; nt++)
        #pragma unroll
        for (int i = 0; i < 4; i++) ctx[nt][i] = 0.f;

    const float* pkt = PKT + (size_t)h * HD_ * 512;
    const float* pqt = PQT + (size_t)h * HD_ * 512;
    const float scale = 0.07216878364870323f;    // 1/sqrt(192)

    for (int c = 0; c < 3; c++) {
        const int  c0  = c * 128;
        const long sk0 = (long)n * 128 - 128 + c0;

        for (int i = tid; i < 128 * 16; i += 256) {
            int r = i >> 4, c4 = (i & 15) << 2;
            long s = sk0 + r;
            float4 kv, vv;
            if (s >= 0 && s < S_) {
                size_t g = ((size_t)b * S_ + s) * H_ + hoff + c4;
                kv = *(const float4*)(K + g);
                vv = *(const float4*)(V + g);
                kv.x = cvt_tf32(kv.x); kv.y = cvt_tf32(kv.y);
                kv.z = cvt_tf32(kv.z); kv.w = cvt_tf32(kv.w);
                vv.x = cvt_tf32(vv.x); vv.y = cvt_tf32(vv.y);
                vv.z = cvt_tf32(vv.z); vv.w = cvt_tf32(vv.w);
            } else {
                kv = make_float4(0.f, 0.f, 0.f, 0.f);
                vv = kv;
            }
            *(float4*)&Ks[r * KST + c4] = kv;
            *(float4*)&Vs[r * VST + c4] = vv;
        }
        __syncthreads();

        // ---- c2c: S = Q @ K^T -------------------------------------------------
        {
            const int wm = (warp & 3) * 32, wn = (warp >> 2) * 64;
            float acc[2][8][4];
            #pragma unroll
            for (int mt = 0; mt < 2; mt++)
                #pragma unroll
                for (int nt = 0; nt < 8; nt++)
                    #pragma unroll
                    for (int i = 0; i < 4; i++) acc[mt][nt][i] = 0.f;

            #pragma unroll
            for (int ks = 0; ks < 8; ks++) {
                const int k8 = ks * 8;
                uint32_t a[2][4], bf[8][2];
                #pragma unroll
                for (int mt = 0; mt < 2; mt++) {
                    int r0 = wm + mt * 16 + gid;
                    a[mt][0] = __float_as_uint(Qs[r0 * QST + k8 + tig]);
                    a[mt][1] = __float_as_uint(Qs[(r0 + 8) * QST + k8 + tig]);
                    a[mt][2] = __float_as_uint(Qs[r0 * QST + k8 + tig + 4]);
                    a[mt][3] = __float_as_uint(Qs[(r0 + 8) * QST + k8 + tig + 4]);
                }
                #pragma unroll
                for (int nt = 0; nt < 8; nt++) {
                    int cc = wn + nt * 8 + gid;
                    bf[nt][0] = __float_as_uint(Ks[cc * KST + k8 + tig]);
                    bf[nt][1] = __float_as_uint(Ks[cc * KST + k8 + tig + 4]);
                }
                #pragma unroll
                for (int mt = 0; mt < 2; mt++)
                    #pragma unroll
                    for (int nt = 0; nt < 8; nt++)
                        mma_tf32(acc[mt][nt], a[mt], bf[nt]);
            }
            #pragma unroll
            for (int mt = 0; mt < 2; mt++) {
                int r1 = wm + mt * 16 + gid;
                #pragma unroll
                for (int nt = 0; nt < 8; nt++) {
                    int cc = wn + nt * 8 + 2 * tig;
                    *(float2*)&Ss[r1 * SST + cc] =
                        make_float2(acc[mt][nt][0], acc[mt][nt][1]);
                    *(float2*)&Ss[(r1 + 8) * SST + cc] =
                        make_float2(acc[mt][nt][2], acc[mt][nt][3]);
                }
            }
        }
        __syncthreads();

        // ---- C2P: Q @ PKT_slice, scatter-add S[q][q-col+128] ------------------
        {
            const int wm = (warp & 3) * 32, wn2 = (warp >> 2) * 128;
            const int colbase = 256 - c0;
            #pragma unroll
            for (int half = 0; half < 2; half++) {
                const int cb = wn2 + half * 64;
                float acc[2][8][4];
                #pragma unroll
                for (int mt = 0; mt < 2; mt++)
                    #pragma unroll
                    for (int nt = 0; nt < 8; nt++)
                        #pragma unroll
                        for (int i = 0; i < 4; i++) acc[mt][nt][i] = 0.f;

                #pragma unroll
                for (int ks = 0; ks < 8; ks++) {
                    const int k8 = ks * 8;
                    uint32_t a[2][4], bf[8][2];
                    #pragma unroll
                    for (int mt = 0; mt < 2; mt++) {
                        int r0 = wm + mt * 16 + gid;
                        a[mt][0] = __float_as_uint(Qs[r0 * QST + k8 + tig]);
                        a[mt][1] = __float_as_uint(Qs[(r0 + 8) * QST + k8 + tig]);
                        a[mt][2] = __float_as_uint(Qs[r0 * QST + k8 + tig + 4]);
                        a[mt][3] = __float_as_uint(Qs[(r0 + 8) * QST + k8 + tig + 4]);
                    }
                    #pragma unroll
                    for (int nt = 0; nt < 8; nt++) {
                        int cc = colbase + cb + nt * 8 + gid;
                        bf[nt][0] = __float_as_uint(__ldg(&pkt[(size_t)(k8 + tig) * 512 + cc]));
                        bf[nt][1] = __float_as_uint(__ldg(&pkt[(size_t)(k8 + tig + 4) * 512 + cc]));
                    }
                    #pragma unroll
                    for (int mt = 0; mt < 2; mt++)
                        #pragma unroll
                        for (int nt = 0; nt < 8; nt++)
                            mma_tf32(acc[mt][nt], a[mt], bf[nt]);
                }
                #pragma unroll
                for (int mt = 0; mt < 2; mt++) {
                    int r1 = wm + mt * 16 + gid;
                    #pragma unroll
                    for (int nt = 0; nt < 8; nt++) {
                        int ci = cb + nt * 8 + 2 * tig;
                        int jj;
                        jj = r1 - ci + 128;
                        if (jj >= 0 && jj < 128) Ss[r1 * SST + jj] += acc[mt][nt][0];
                        jj = r1 - ci + 127;
                        if (jj >= 0 && jj < 128) Ss[r1 * SST + jj] += acc[mt][nt][1];
                        int r2 = r1 + 8;
                        jj = r2 - ci + 128;
                        if (jj >= 0 && jj < 128) Ss[r2 * SST + jj] += acc[mt][nt][2];
                        jj = r2 - ci + 127;
                        if (jj >= 0 && jj < 128) Ss[r2 * SST + jj] += acc[mt][nt][3];
                    }
                }
                __syncthreads();
            }
        }

        // ---- P2C: K @ PQT_slice, scatter-add S[jj+col-128][jj] ---------------
        {
            const int wm = (warp & 3) * 32, wn2 = (warp >> 2) * 128;
            const int colbase = 256 - c0;
            #pragma unroll
            for (int half = 0; half < 2; half++) {
                const int cb = wn2 + half * 64;
                float acc[2][8][4];
                #pragma unroll
                for (int mt = 0; mt < 2; mt++)
                    #pragma unroll
                    for (int nt = 0; nt < 8; nt++)
                        #pragma unroll
                        for (int i = 0; i < 4; i++) acc[mt][nt][i] = 0.f;

                #pragma unroll
                for (int ks = 0; ks < 8; ks++) {
                    const int k8 = ks * 8;
                    uint32_t a[2][4], bf[8][2];
                    #pragma unroll
                    for (int mt = 0; mt < 2; mt++) {
                        int r0 = wm + mt * 16 + gid;
                        a[mt][0] = __float_as_uint(Ks[r0 * KST + k8 + tig]);
                        a[mt][1] = __float_as_uint(Ks[(r0 + 8) * KST + k8 + tig]);
                        a[mt][2] = __float_as_uint(Ks[r0 * KST + k8 + tig + 4]);
                        a[mt][3] = __float_as_uint(Ks[(r0 + 8) * KST + k8 + tig + 4]);
                    }
                    #pragma unroll
                    for (int nt = 0; nt < 8; nt++) {
                        int cc = colbase + cb + nt * 8 + gid;
                        bf[nt][0] = __float_as_uint(__ldg(&pqt[(size_t)(k8 + tig) * 512 + cc]));
                        bf[nt][1] = __float_as_uint(__ldg(&pqt[(size_t)(k8 + tig + 4) * 512 + cc]));
                    }
                    #pragma unroll
                    for (int mt = 0; mt < 2; mt++)
                        #pragma unroll
                        for (int nt = 0; nt < 8; nt++)
                            mma_tf32(acc[mt][nt], a[mt], bf[nt]);
                }
                #pragma unroll
                for (int mt = 0; mt < 2; mt++) {
                    int r1 = wm + mt * 16 + gid;
                    #pragma unroll
                    for (int nt = 0; nt < 8; nt++) {
                        int ci = cb + nt * 8 + 2 * tig;
                        int q;
                        q = r1 + ci - 128;
                        if (q >= 0 && q < 128) Ss[q * SST + r1] += acc[mt][nt][0];
                        q = r1 + ci - 127;
                        if (q >= 0 && q < 128) Ss[q * SST + r1] += acc[mt][nt][1];
                        int r2 = r1 + 8;
                        q = r2 + ci - 128;
                        if (q >= 0 && q < 128) Ss[q * SST + r2] += acc[mt][nt][2];
                        q = r2 + ci - 127;
                        if (q >= 0 && q < 128) Ss[q * SST + r2] += acc[mt][nt][3];
                    }
                }
                __syncthreads();
            }
        }

        // ---- online softmax (2 threads per row) ------------------------------
        {
            const int r  = tid & 127;
            const int hh = tid >> 7;
            float* srow = Ss + r * SST + hh * 64;
            float mx = -1e30f;
            #pragma unroll 8
            for (int j = 0; j < 64; j++) mx = fmaxf(mx, srow[j]);
            pbuf[tid] = mx;
            __syncthreads();
            if (tid < 128) {
                float mb   = fmaxf(pbuf[tid], pbuf[tid + 128]) * scale;
                float mold = mrow[tid];
                float mnew = fmaxf(mold, mb);
                crow[tid]  = __expf(mold - mnew);
                mrow[tid]  = mnew;
            }
            __syncthreads();
            float mnew = mrow[r];
            float ssum = 0.f;
            #pragma unroll 8
            for (int j = 0; j < 64; j++) {
                float p = __expf(srow[j] * scale - mnew);
                srow[j] = p;
                ssum += p;
            }
            pbuf[tid] = ssum;
            __syncthreads();
            if (tid < 128)
                lrow[tid] = lrow[tid] * crow[tid] + pbuf[tid] + pbuf[tid + 128];
            __syncthreads();
        }

        // ---- PV: ctx = ctx*corr + P @ V --------------------------------------
        {
            const int wm1 = warp * 16;
            float c1 = crow[wm1 + gid], c2 = crow[wm1 + gid + 8];
            #pragma unroll
            for (int nt = 0; nt < 8; nt++) {
                ctx[nt][0] *= c1; ctx[nt][1] *= c1;
                ctx[nt][2] *= c2; ctx[nt][3] *= c2;
            }
            #pragma unroll
            for (int ks = 0; ks < 16; ks++) {
                const int k8 = ks * 8;
                uint32_t a[4], bf[8][2];
                int r0 = wm1 + gid;
                a[0] = __float_as_uint(Ss[r0 * SST + k8 + tig]);
                a[1] = __float_as_uint(Ss[(r0 + 8) * SST + k8 + tig]);
                a[2] = __float_as_uint(Ss[r0 * SST + k8 + tig + 4]);
                a[3] = __float_as_uint(Ss[(r0 + 8) * SST + k8 + tig + 4]);
                #pragma unroll
                for (int nt = 0; nt < 8; nt++) {
                    int cc = nt * 8 + gid;
                    bf[nt][0] = __float_as_uint(Vs[(k8 + tig) * VST + cc]);
                    bf[nt][1] = __float_as_uint(Vs[(k8 + tig + 4) * VST + cc]);
                }
                #pragma unroll
                for (int nt = 0; nt < 8; nt++)
                    mma_tf32(ctx[nt], a, bf[nt]);
            }
        }
        __syncthreads();
    }

    // ---- write ctx / l -------------------------------------------------------
    {
        const int wm1 = warp * 16;
        float inv1 = 1.0f / lrow[wm1 + gid];
        float inv2 = 1.0f / lrow[wm1 + gid + 8];
        size_t row1 = qrow0 + wm1 + gid;
        size_t row2 = row1 + 8;
        #pragma unroll
        for (int nt = 0; nt < 8; nt++) {
            int col = nt * 8 + 2 * tig;
            *(float2*)(CTX + row1 * H_ + hoff + col) =
                make_float2(ctx[nt][0] * inv1, ctx[nt][1] * inv1);
            *(float2*)(CTX + row2 * H_ + hoff + col) =
                make_float2(ctx[nt][2] * inv2, ctx[nt][3] * inv2);
        }
    }
}

// ---------------- LayerNorm over H=768, one row per CTA ----------------------
__global__ void __launch_bounds__(256) ln_kernel(
    const float* __restrict__ X, const float* __restrict__ gam,
    const float* __restrict__ bet, float* __restrict__ out)
{
    const int row = blockIdx.x;
    const int t   = threadIdx.x;
    const float* x = X + (size_t)row * H_;
    float v0 = x[t], v1 = x[t + 256], v2 = x[t + 512];
    float s = v0 + v1 + v2;
    float q = v0 * v0 + v1 * v1 + v2 * v2;

    __shared__ float sh[64];
    #pragma unroll
    for (int o = 16; o > 0; o >>= 1) {
        s += __shfl_down_sync(0xffffffffu, s, o);
        q += __shfl_down_sync(0xffffffffu, q, o);
    }
    int w = t >> 5, lane = t & 31;
    if (lane == 0) { sh[w] = s; sh[32 + w] = q; }
    __syncthreads();
    if (t == 0) {
        float ts = 0.f, tq = 0.f;
        #pragma unroll
        for (int i = 0; i < 8; i++) { ts += sh[i]; tq += sh[32 + i]; }
        sh[0] = ts;
        sh[32] = tq;
    }
    __syncthreads();
    float mu  = sh[0] * (1.0f / 768.0f);
    float var = sh[32] * (1.0f / 768.0f) - mu * mu;
    float r   = rsqrtf(var + 1e-7f);

    float* o = out + (size_t)row * H_;
    o[t]       = (v0 - mu) * r * gam[t]       + bet[t];
    o[t + 256] = (v1 - mu) * r * gam[t + 256] + bet[t + 256];
    o[t + 512] = (v2 - mu) * r * gam[t + 512] + bet[t + 512];
}

// ---------------- launch ------------------------------------------------------
extern "C" void kernel_launch(void* const* d_in, const int* in_sizes, int n_in,
                              void* d_out, int out_size)
{
    const float* hidden = (const float*)d_in[0];
    const float* rel    = (const float*)d_in[1];
    const float* Wq = (const float*)d_in[2];  const float* bq = (const float*)d_in[3];
    const float* Wk = (const float*)d_in[4];  const float* bk = (const float*)d_in[5];
    const float* Wv = (const float*)d_in[6];  const float* bv = (const float*)d_in[7];
    const float* Wo = (const float*)d_in[8];  const float* bo = (const float*)d_in[9];
    const float* lns = (const float*)d_in[10];
    const float* lnb = (const float*)d_in[11];
    float* out = (float*)d_out;

    float *Qp, *Kp, *Vp, *PK, *PQ, *PKT, *PQT, *CT, *XR;
    cudaGetSymbolAddress((void**)&Qp,  g_Q);
    cudaGetSymbolAddress((void**)&Kp,  g_K);
    cudaGetSymbolAddress((void**)&Vp,  g_V);
    cudaGetSymbolAddress((void**)&PK,  g_PK);
    cudaGetSymbolAddress((void**)&PQ,  g_PQ);
    cudaGetSymbolAddress((void**)&PKT, g_PKT);
    cudaGetSymbolAddress((void**)&PQT, g_PQT);
    cudaGetSymbolAddress((void**)&CT,  g_CTX);
    cudaGetSymbolAddress((void**)&XR,  g_XR);

    const int M = B_ * S_;                       // 32768

    dim3 gBig(H_ / 128, M / 128);                // (6, 256)
    dim3 gPos(H_ / 128, 512 / 128);              // (6, 4)

    const int smem_gemm = NSTAGE * (ASTAGE + BSTAGE) * 4;   // 75776 B
    static int gemm_attr_set = 0;
    cudaFuncSetAttribute(tf32_gemm,
                         cudaFuncAttributeMaxDynamicSharedMemorySize, smem_gemm);
    (void)gemm_attr_set;

    // QKV projections (pipelined tf32 tensor cores)
    tf32_gemm<<<gBig, 256, smem_gemm>>>(hidden, Wq, bq, nullptr, Qp, M, H_, H_);
    tf32_gemm<<<gBig, 256, smem_gemm>>>(hidden, Wk, bk, nullptr, Kp, M, H_, H_);
    tf32_gemm<<<gBig, 256, smem_gemm>>>(hidden, Wv, bv, nullptr, Vp, M, H_, H_);

    // positional projections (shared Wq/Wk) + transposed diff tables
    tf32_gemm<<<gPos, 256, smem_gemm>>>(rel, Wk, bk, nullptr, PK, 512, H_, H_);
    tf32_gemm<<<gPos, 256, smem_gemm>>>(rel, Wq, bq, nullptr, PQ, 512, H_, H_);
    build_pos_t<<<511, 768>>>(PK, PQ, PKT, PQT);

    // MMA attention
    const int smem_attn =
        (128 * QST + 128 * KST + 128 * VST + 128 * SST + 3 * 128 + 256) * 4;
    cudaFuncSetAttribute(attn_mma,
                         cudaFuncAttributeMaxDynamicSharedMemorySize, smem_attn);
    attn_mma<<<dim3(NH_, NB_, B_), 256, smem_attn>>>(Qp, Kp, Vp, PKT, PQT, CT);

    // output projection + residual, then layernorm
    tf32_gemm<<<gBig, 256, smem_gemm>>>(CT, Wo, bo, hidden, XR, M, H_, H_);
    ln_kernel<<<M, 256>>>(XR, lns, lnb, out);
}

// round 7
// speedup vs baseline: 3.2131x; 1.0773x over previous
#include <cuda_runtime.h>
#include <math.h>
#include <stdint.h>

#define B_   4
#define S_   8192
#define H_   768
#define NH_  12
#define HD_  64
#define NB_  64
#define TOT_ (B_*S_*H_)

// attention smem strides (floats)
#define QST 68
#define KST 68
#define VST 72
#define SST 132

// gemm smem strides
#define AST 20
#define BST 136
#define ASTAGE (128 * AST)     // floats per A stage
#define BSTAGE (16 * BST)      // floats per B stage
#define NSTAGE 3
#define GSMEM  (NSTAGE * (ASTAGE + BSTAGE) * 4)

// ---------------- scratch (device globals; no allocs allowed) ----------------
__device__ float g_Q[TOT_];
__device__ float g_K[TOT_];
__device__ float g_V[TOT_];
__device__ float g_CTX[TOT_];
__device__ float g_XR[TOT_];
__device__ float g_PK[512 * H_];
__device__ float g_PQ[512 * H_];
// transposed diff-gathered pos tables: [h][d][512]; col = dd+1, col0 = pad(0)
__device__ float g_PKT[NH_ * HD_ * 512];
__device__ float g_PQT[NH_ * HD_ * 512];

// ---------------- TF32 helpers ------------------------------------------------
__device__ __forceinline__ float cvt_tf32(float x) {
    uint32_t u;
    asm("cvt.rna.tf32.f32 %0, %1;" : "=r"(u) : "f"(x));
    return __uint_as_float(u);
}

__device__ __forceinline__ void mma_tf32(float* c, const uint32_t* a, const uint32_t* b) {
    asm volatile(
        "mma.sync.aligned.m16n8k8.row.col.f32.tf32.tf32.f32 "
        "{%0,%1,%2,%3},{%4,%5,%6,%7},{%8,%9},{%0,%1,%2,%3};\n"
        : "+f"(c[0]), "+f"(c[1]), "+f"(c[2]), "+f"(c[3])
        : "r"(a[0]), "r"(a[1]), "r"(a[2]), "r"(a[3]), "r"(b[0]), "r"(b[1]));
}

__device__ __forceinline__ void cp16(float* dst_smem, const float* src) {
    uint32_t d = (uint32_t)__cvta_generic_to_shared(dst_smem);
    asm volatile("cp.async.cg.shared.global [%0], [%1], 16;\n" :: "r"(d), "l"(src));
}
__device__ __forceinline__ void cp_commit() {
    asm volatile("cp.async.commit_group;\n");
}

// ---------------- TF32 tensor-core GEMM, 3-stage cp.async, 2 CTAs/SM ---------
__global__ void __launch_bounds__(256, 2) tf32_gemm(
    const float* __restrict__ A, const float* __restrict__ Bm,
    const float* __restrict__ bias, const float* __restrict__ Rres,
    float* __restrict__ C, int M, int N, int K)
{
    extern __shared__ float smg[];
    float* As = smg;                         // NSTAGE * ASTAGE
    float* Bs = smg + NSTAGE * ASTAGE;       // NSTAGE * BSTAGE

    const int tid  = threadIdx.x;
    const int lane = tid & 31;
    const int warp = tid >> 5;
    const int wm   = (warp & 3) * 32;
    const int wn   = (warp >> 2) * 64;
    const int bm   = blockIdx.y * 128;
    const int bn   = blockIdx.x * 128;
    const int gid  = lane >> 2;
    const int tig  = lane & 3;

    // per-thread fill coordinates
    const int ar  = tid >> 1;                // 0..127   (A row; 2 thr/row)
    const int ac4 = (tid & 1) << 3;          // 0 or 8 -> two float4 each
    const int br  = tid >> 4;                // 0..15    (B row)
    const int bc4 = (tid & 15) << 3;         // 0..120 step 8 -> two float4

    const int T = K >> 4;

    float acc[2][8][4];
    #pragma unroll
    for (int mt = 0; mt < 2; mt++)
        #pragma unroll
        for (int nt = 0; nt < 8; nt++)
            #pragma unroll
            for (int i = 0; i < 4; i++) acc[mt][nt][i] = 0.f;

    auto fill = [&](int s, int kt) {
        const int kb = kt << 4;
        float* as = As + s * ASTAGE;
        float* bs = Bs + s * BSTAGE;
        cp16(&as[ar * AST + ac4],     A + (size_t)(bm + ar) * K + kb + ac4);
        cp16(&as[ar * AST + ac4 + 4], A + (size_t)(bm + ar) * K + kb + ac4 + 4);
        cp16(&bs[br * BST + bc4],     Bm + (size_t)(kb + br) * N + bn + bc4);
        cp16(&bs[br * BST + bc4 + 4], Bm + (size_t)(kb + br) * N + bn + bc4 + 4);
        cp_commit();
    };

    fill(0, 0);
    fill(1, 1);

    for (int kt = 0; kt < T; kt++) {
        if (kt + 1 < T) asm volatile("cp.async.wait_group 1;\n");
        else            asm volatile("cp.async.wait_group 0;\n");
        __syncthreads();

        const float* as = As + (kt % NSTAGE) * ASTAGE;
        const float* bs = Bs + (kt % NSTAGE) * BSTAGE;

        #pragma unroll
        for (int ks = 0; ks < 2; ks++) {
            const int k8 = ks * 8;
            uint32_t a[2][4], b[8][2];
            #pragma unroll
            for (int mt = 0; mt < 2; mt++) {
                int r0 = wm + mt * 16 + gid;
                a[mt][0] = __float_as_uint(as[r0 * AST + k8 + tig]);
                a[mt][1] = __float_as_uint(as[(r0 + 8) * AST + k8 + tig]);
                a[mt][2] = __float_as_uint(as[r0 * AST + k8 + tig + 4]);
                a[mt][3] = __float_as_uint(as[(r0 + 8) * AST + k8 + tig + 4]);
            }
            #pragma unroll
            for (int nt = 0; nt < 8; nt++) {
                int cc = wn + nt * 8 + gid;
                b[nt][0] = __float_as_uint(bs[(k8 + tig) * BST + cc]);
                b[nt][1] = __float_as_uint(bs[(k8 + tig + 4) * BST + cc]);
            }
            #pragma unroll
            for (int mt = 0; mt < 2; mt++)
                #pragma unroll
                for (int nt = 0; nt < 8; nt++)
                    mma_tf32(acc[mt][nt], a[mt], b[nt]);
        }
        __syncthreads();

        if (kt + 2 < T) fill((kt + 2) % NSTAGE, kt + 2);
    }

    #pragma unroll
    for (int mt = 0; mt < 2; mt++) {
        #pragma unroll
        for (int hi = 0; hi < 2; hi++) {
            size_t row = (size_t)bm + wm + mt * 16 + gid + hi * 8;
            #pragma unroll
            for (int nt = 0; nt < 8; nt++) {
                int col = bn + wn + nt * 8 + tig * 2;
                float v0 = acc[mt][nt][hi * 2 + 0] + bias[col];
                float v1 = acc[mt][nt][hi * 2 + 1] + bias[col + 1];
                if (Rres != nullptr) {
                    float2 rr = *(const float2*)(Rres + row * (size_t)N + col);
                    v0 += rr.x; v1 += rr.y;
                }
                *(float2*)(C + row * (size_t)N + col) = make_float2(v0, v1);
            }
        }
    }
}

// ---------------- bucketization + transposed pos tables ----------------------
__device__ __forceinline__ int bucket_idx_dev(int d)
{
    int ad = d < 0 ? -d : d;
    int v;
    if (ad <= 128) {
        v = d;
    } else {
        float t = logf((float)ad / 128.0f);
        t = t / 0.6892332713f;                   // fp32(ln(255/128))
        t = t * 127.0f;
        float lp = ceilf(t) + 128.0f;
        v = (int)(d < 0 ? -lp : lp);
    }
    v += 256;
    return v < 0 ? 0 : (v > 511 ? 511 : v);
}

// PKT[(h*64+d)*512 + dd+1] = tf32(PK[bucket(dd-383)][h*64+d]); col 0 = 0 pad
__global__ void build_pos_t(const float* __restrict__ PK, const float* __restrict__ PQ,
                            float* __restrict__ PKT, float* __restrict__ PQT)
{
    int dd = blockIdx.x;                         // 0..510
    int t  = threadIdx.x;                        // 0..767
    int p  = bucket_idx_dev(dd - 383);
    size_t dst = (size_t)t * 512 + dd + 1;       // t = h*64+d
    PKT[dst] = cvt_tf32(PK[(size_t)p * H_ + t]);
    PQT[dst] = cvt_tf32(PQ[(size_t)p * H_ + t]);
    if (dd == 0) {
        PKT[(size_t)t * 512] = 0.f;
        PQT[(size_t)t * 512] = 0.f;
    }
}

// ---------------- MMA attention: one CTA per (head, block, batch) ------------
__global__ void __launch_bounds__(256, 1) attn_mma(
    const float* __restrict__ Q, const float* __restrict__ K,
    const float* __restrict__ V,
    const float* __restrict__ PKT, const float* __restrict__ PQT,
    float* __restrict__ CTX)
{
    extern __shared__ float sm[];
    float* Qs   = sm;
    float* Ks   = Qs + 128 * QST;
    float* Vs   = Ks + 128 * KST;
    float* Ss   = Vs + 128 * VST;
    float* mrow = Ss + 128 * SST;
    float* lrow = mrow + 128;
    float* crow = lrow + 128;
    float* pbuf = crow + 128;

    const int h = blockIdx.x, n = blockIdx.y, b = blockIdx.z;
    const int tid  = threadIdx.x;
    const int lane = tid & 31;
    const int warp = tid >> 5;
    const int gid  = lane >> 2;
    const int tig  = lane & 3;
    const size_t qrow0 = (size_t)b * S_ + (size_t)n * 128;
    const size_t hoff  = (size_t)h * HD_;

    for (int i = tid; i < 128 * 16; i += 256) {
        int r = i >> 4, c4 = (i & 15) << 2;
        *(float4*)&Qs[r * QST + c4] =
            *(const float4*)(Q + (qrow0 + r) * H_ + hoff + c4);
    }
    if (tid < 128) { mrow[tid] = -1e30f; lrow[tid] = 0.f; }
    __syncthreads();

    float ctx[8][4];
    #pragma unroll
    for (int nt = 0; nt < 8; nt++)
        #pragma unroll
        for (int i = 0; i < 4; i++) ctx[nt][i] = 0.f;

    const float* pkt = PKT + (size_t)h * HD_ * 512;
    const float* pqt = PQT + (size_t)h * HD_ * 512;
    const float scale = 0.07216878364870323f;    // 1/sqrt(192)

    for (int c = 0; c < 3; c++) {
        const int  c0  = c * 128;
        const long sk0 = (long)n * 128 - 128 + c0;

        for (int i = tid; i < 128 * 16; i += 256) {
            int r = i >> 4, c4 = (i & 15) << 2;
            long s = sk0 + r;
            float4 kv, vv;
            if (s >= 0 && s < S_) {
                size_t g = ((size_t)b * S_ + s) * H_ + hoff + c4;
                kv = *(const float4*)(K + g);
                vv = *(const float4*)(V + g);
            } else {
                kv = make_float4(0.f, 0.f, 0.f, 0.f);
                vv = kv;
            }
            *(float4*)&Ks[r * KST + c4] = kv;
            *(float4*)&Vs[r * VST + c4] = vv;
        }
        __syncthreads();

        // ---- c2c: S = Q @ K^T ----
        {
            const int wm = (warp & 3) * 32, wn = (warp >> 2) * 64;
            float acc[2][8][4];
            #pragma unroll
            for (int mt = 0; mt < 2; mt++)
                #pragma unroll
                for (int nt = 0; nt < 8; nt++)
                    #pragma unroll
                    for (int i = 0; i < 4; i++) acc[mt][nt][i] = 0.f;

            #pragma unroll
            for (int ks = 0; ks < 8; ks++) {
                const int k8 = ks * 8;
                uint32_t a[2][4], bf[8][2];
                #pragma unroll
                for (int mt = 0; mt < 2; mt++) {
                    int r0 = wm + mt * 16 + gid;
                    a[mt][0] = __float_as_uint(Qs[r0 * QST + k8 + tig]);
                    a[mt][1] = __float_as_uint(Qs[(r0 + 8) * QST + k8 + tig]);
                    a[mt][2] = __float_as_uint(Qs[r0 * QST + k8 + tig + 4]);
                    a[mt][3] = __float_as_uint(Qs[(r0 + 8) * QST + k8 + tig + 4]);
                }
                #pragma unroll
                for (int nt = 0; nt < 8; nt++) {
                    int cc = wn + nt * 8 + gid;
                    bf[nt][0] = __float_as_uint(Ks[cc * KST + k8 + tig]);
                    bf[nt][1] = __float_as_uint(Ks[cc * KST + k8 + tig + 4]);
                }
                #pragma unroll
                for (int mt = 0; mt < 2; mt++)
                    #pragma unroll
                    for (int nt = 0; nt < 8; nt++)
                        mma_tf32(acc[mt][nt], a[mt], bf[nt]);
            }
            #pragma unroll
            for (int mt = 0; mt < 2; mt++) {
                int r1 = wm + mt * 16 + gid;
                #pragma unroll
                for (int nt = 0; nt < 8; nt++) {
                    int cc = wn + nt * 8 + 2 * tig;
                    *(float2*)&Ss[r1 * SST + cc] =
                        make_float2(acc[mt][nt][0], acc[mt][nt][1]);
                    *(float2*)&Ss[(r1 + 8) * SST + cc] =
                        make_float2(acc[mt][nt][2], acc[mt][nt][3]);
                }
            }
        }
        __syncthreads();

        // ---- C2P: Q @ PKT_slice, scatter-add S[q][q-col+128] ----
        {
            const int wm = (warp & 3) * 32, wn2 = (warp >> 2) * 128;
            const int colbase = 256 - c0;
            #pragma unroll
            for (int half = 0; half < 2; half++) {
                const int cb = wn2 + half * 64;
                float acc[2][8][4];
                #pragma unroll
                for (int mt = 0; mt < 2; mt++)
                    #pragma unroll
                    for (int nt = 0; nt < 8; nt++)
                        #pragma unroll
                        for (int i = 0; i < 4; i++) acc[mt][nt][i] = 0.f;

                #pragma unroll
                for (int ks = 0; ks < 8; ks++) {
                    const int k8 = ks * 8;
                    uint32_t a[2][4], bf[8][2];
                    #pragma unroll
                    for (int mt = 0; mt < 2; mt++) {
                        int r0 = wm + mt * 16 + gid;
                        a[mt][0] = __float_as_uint(Qs[r0 * QST + k8 + tig]);
                        a[mt][1] = __float_as_uint(Qs[(r0 + 8) * QST + k8 + tig]);
                        a[mt][2] = __float_as_uint(Qs[r0 * QST + k8 + tig + 4]);
                        a[mt][3] = __float_as_uint(Qs[(r0 + 8) * QST + k8 + tig + 4]);
                    }
                    #pragma unroll
                    for (int nt = 0; nt < 8; nt++) {
                        int cc = colbase + cb + nt * 8 + gid;
                        bf[nt][0] = __float_as_uint(__ldg(&pkt[(size_t)(k8 + tig) * 512 + cc]));
                        bf[nt][1] = __float_as_uint(__ldg(&pkt[(size_t)(k8 + tig + 4) * 512 + cc]));
                    }
                    #pragma unroll
                    for (int mt = 0; mt < 2; mt++)
                        #pragma unroll
                        for (int nt = 0; nt < 8; nt++)
                            mma_tf32(acc[mt][nt], a[mt], bf[nt]);
                }
                #pragma unroll
                for (int mt = 0; mt < 2; mt++) {
                    int r1 = wm + mt * 16 + gid;
                    #pragma unroll
                    for (int nt = 0; nt < 8; nt++) {
                        int ci = cb + nt * 8 + 2 * tig;
                        int jj;
                        jj = r1 - ci + 128;
                        if (jj >= 0 && jj < 128) Ss[r1 * SST + jj] += acc[mt][nt][0];
                        jj = r1 - ci + 127;
                        if (jj >= 0 && jj < 128) Ss[r1 * SST + jj] += acc[mt][nt][1];
                        int r2 = r1 + 8;
                        jj = r2 - ci + 128;
                        if (jj >= 0 && jj < 128) Ss[r2 * SST + jj] += acc[mt][nt][2];
                        jj = r2 - ci + 127;
                        if (jj >= 0 && jj < 128) Ss[r2 * SST + jj] += acc[mt][nt][3];
                    }
                }
                __syncthreads();
            }
        }

        // ---- P2C: K @ PQT_slice, scatter-add S[jj+col-128][jj] ----
        {
            const int wm = (warp & 3) * 32, wn2 = (warp >> 2) * 128;
            const int colbase = 256 - c0;
            #pragma unroll
            for (int half = 0; half < 2; half++) {
                const int cb = wn2 + half * 64;
                float acc[2][8][4];
                #pragma unroll
                for (int mt = 0; mt < 2; mt++)
                    #pragma unroll
                    for (int nt = 0; nt < 8; nt++)
                        #pragma unroll
                        for (int i = 0; i < 4; i++) acc[mt][nt][i] = 0.f;

                #pragma unroll
                for (int ks = 0; ks < 8; ks++) {
                    const int k8 = ks * 8;
                    uint32_t a[2][4], bf[8][2];
                    #pragma unroll
                    for (int mt = 0; mt < 2; mt++) {
                        int r0 = wm + mt * 16 + gid;
                        a[mt][0] = __float_as_uint(Ks[r0 * KST + k8 + tig]);
                        a[mt][1] = __float_as_uint(Ks[(r0 + 8) * KST + k8 + tig]);
                        a[mt][2] = __float_as_uint(Ks[r0 * KST + k8 + tig + 4]);
                        a[mt][3] = __float_as_uint(Ks[(r0 + 8) * KST + k8 + tig + 4]);
                    }
                    #pragma unroll
                    for (int nt = 0; nt < 8; nt++) {
                        int cc = colbase + cb + nt * 8 + gid;
                        bf[nt][0] = __float_as_uint(__ldg(&pqt[(size_t)(k8 + tig) * 512 + cc]));
                        bf[nt][1] = __float_as_uint(__ldg(&pqt[(size_t)(k8 + tig + 4) * 512 + cc]));
                    }
                    #pragma unroll
                    for (int mt = 0; mt < 2; mt++)
                        #pragma unroll
                        for (int nt = 0; nt < 8; nt++)
                            mma_tf32(acc[mt][nt], a[mt], bf[nt]);
                }
                #pragma unroll
                for (int mt = 0; mt < 2; mt++) {
                    int r1 = wm + mt * 16 + gid;
                    #pragma unroll
                    for (int nt = 0; nt < 8; nt++) {
                        int ci = cb + nt * 8 + 2 * tig;
                        int q;
                        q = r1 + ci - 128;
                        if (q >= 0 && q < 128) Ss[q * SST + r1] += acc[mt][nt][0];
                        q = r1 + ci - 127;
                        if (q >= 0 && q < 128) Ss[q * SST + r1] += acc[mt][nt][1];
                        int r2 = r1 + 8;
                        q = r2 + ci - 128;
                        if (q >= 0 && q < 128) Ss[q * SST + r2] += acc[mt][nt][2];
                        q = r2 + ci - 127;
                        if (q >= 0 && q < 128) Ss[q * SST + r2] += acc[mt][nt][3];
                    }
                }
                __syncthreads();
            }
        }

        // ---- online softmax (2 threads per row) ----
        {
            const int r  = tid & 127;
            const int hh = tid >> 7;
            float* srow = Ss + r * SST + hh * 64;
            float mx = -1e30f;
            #pragma unroll 8
            for (int j = 0; j < 64; j++) mx = fmaxf(mx, srow[j]);
            pbuf[tid] = mx;
            __syncthreads();
            if (tid < 128) {
                float mb   = fmaxf(pbuf[tid], pbuf[tid + 128]) * scale;
                float mold = mrow[tid];
                float mnew = fmaxf(mold, mb);
                crow[tid]  = __expf(mold - mnew);
                mrow[tid]  = mnew;
            }
            __syncthreads();
            float mnew = mrow[r];
            float ssum = 0.f;
            #pragma unroll 8
            for (int j = 0; j < 64; j++) {
                float p = __expf(srow[j] * scale - mnew);
                srow[j] = p;
                ssum += p;
            }
            pbuf[tid] = ssum;
            __syncthreads();
            if (tid < 128)
                lrow[tid] = lrow[tid] * crow[tid] + pbuf[tid] + pbuf[tid + 128];
            __syncthreads();
        }

        // ---- PV: ctx = ctx*corr + P @ V ----
        {
            const int wm1 = warp * 16;
            float c1 = crow[wm1 + gid], c2 = crow[wm1 + gid + 8];
            #pragma unroll
            for (int nt = 0; nt < 8; nt++) {
                ctx[nt][0] *= c1; ctx[nt][1] *= c1;
                ctx[nt][2] *= c2; ctx[nt][3] *= c2;
            }
            #pragma unroll
            for (int ks = 0; ks < 16; ks++) {
                const int k8 = ks * 8;
                uint32_t a[4], bf[8][2];
                int r0 = wm1 + gid;
                a[0] = __float_as_uint(Ss[r0 * SST + k8 + tig]);
                a[1] = __float_as_uint(Ss[(r0 + 8) * SST + k8 + tig]);
                a[2] = __float_as_uint(Ss[r0 * SST + k8 + tig + 4]);
                a[3] = __float_as_uint(Ss[(r0 + 8) * SST + k8 + tig + 4]);
                #pragma unroll
                for (int nt = 0; nt < 8; nt++) {
                    int cc = nt * 8 + gid;
                    bf[nt][0] = __float_as_uint(Vs[(k8 + tig) * VST + cc]);
                    bf[nt][1] = __float_as_uint(Vs[(k8 + tig + 4) * VST + cc]);
                }
                #pragma unroll
                for (int nt = 0; nt < 8; nt++)
                    mma_tf32(ctx[nt], a, bf[nt]);
            }
        }
        __syncthreads();
    }

    {
        const int wm1 = warp * 16;
        float inv1 = 1.0f / lrow[wm1 + gid];
        float inv2 = 1.0f / lrow[wm1 + gid + 8];
        size_t row1 = qrow0 + wm1 + gid;
        size_t row2 = row1 + 8;
        #pragma unroll
        for (int nt = 0; nt < 8; nt++) {
            int col = nt * 8 + 2 * tig;
            *(float2*)(CTX + row1 * H_ + hoff + col) =
                make_float2(ctx[nt][0] * inv1, ctx[nt][1] * inv1);
            *(float2*)(CTX + row2 * H_ + hoff + col) =
                make_float2(ctx[nt][2] * inv2, ctx[nt][3] * inv2);
        }
    }
}

// ---------------- LayerNorm over H=768, one row per CTA ----------------------
__global__ void __launch_bounds__(256) ln_kernel(
    const float* __restrict__ X, const float* __restrict__ gam,
    const float* __restrict__ bet, float* __restrict__ out)
{
    const int row = blockIdx.x;
    const int t   = threadIdx.x;
    const float* x = X + (size_t)row * H_;
    float v0 = x[t], v1 = x[t + 256], v2 = x[t + 512];
    float s = v0 + v1 + v2;
    float q = v0 * v0 + v1 * v1 + v2 * v2;

    __shared__ float sh[64];
    #pragma unroll
    for (int o = 16; o > 0; o >>= 1) {
        s += __shfl_down_sync(0xffffffffu, s, o);
        q += __shfl_down_sync(0xffffffffu, q, o);
    }
    int w = t >> 5, lane = t & 31;
    if (lane == 0) { sh[w] = s; sh[32 + w] = q; }
    __syncthreads();
    if (t == 0) {
        float ts = 0.f, tq = 0.f;
        #pragma unroll
        for (int i = 0; i < 8; i++) { ts += sh[i]; tq += sh[32 + i]; }
        sh[0] = ts;
        sh[32] = tq;
    }
    __syncthreads();
    float mu  = sh[0] * (1.0f / 768.0f);
    float var = sh[32] * (1.0f / 768.0f) - mu * mu;
    float r   = rsqrtf(var + 1e-7f);

    float* o = out + (size_t)row * H_;
    o[t]       = (v0 - mu) * r * gam[t]       + bet[t];
    o[t + 256] = (v1 - mu) * r * gam[t + 256] + bet[t + 256];
    o[t + 512] = (v2 - mu) * r * gam[t + 512] + bet[t + 512];
}

// ---------------- launch ------------------------------------------------------
extern "C" void kernel_launch(void* const* d_in, const int* in_sizes, int n_in,
                              void* d_out, int out_size)
{
    const float* hidden = (const float*)d_in[0];
    const float* rel    = (const float*)d_in[1];
    const float* Wq = (const float*)d_in[2];  const float* bq = (const float*)d_in[3];
    const float* Wk = (const float*)d_in[4];  const float* bk = (const float*)d_in[5];
    const float* Wv = (const float*)d_in[6];  const float* bv = (const float*)d_in[7];
    const float* Wo = (const float*)d_in[8];  const float* bo = (const float*)d_in[9];
    const float* lns = (const float*)d_in[10];
    const float* lnb = (const float*)d_in[11];
    float* out = (float*)d_out;

    float *Qp, *Kp, *Vp, *PK, *PQ, *PKT, *PQT, *CT, *XR;
    cudaGetSymbolAddress((void**)&Qp,  g_Q);
    cudaGetSymbolAddress((void**)&Kp,  g_K);
    cudaGetSymbolAddress((void**)&Vp,  g_V);
    cudaGetSymbolAddress((void**)&PK,  g_PK);
    cudaGetSymbolAddress((void**)&PQ,  g_PQ);
    cudaGetSymbolAddress((void**)&PKT, g_PKT);
    cudaGetSymbolAddress((void**)&PQT, g_PQT);
    cudaGetSymbolAddress((void**)&CT,  g_CTX);
    cudaGetSymbolAddress((void**)&XR,  g_XR);

    const int M = B_ * S_;                       // 32768

    dim3 gBig(H_ / 128, M / 128);                // (6, 256)
    dim3 gPos(H_ / 128, 512 / 128);              // (6, 4)

    cudaFuncSetAttribute(tf32_gemm,
                         cudaFuncAttributeMaxDynamicSharedMemorySize, GSMEM);

    // QKV projections (pipelined tf32 tensor cores, 2 CTAs/SM)
    tf32_gemm<<<gBig, 256, GSMEM>>>(hidden, Wq, bq, nullptr, Qp, M, H_, H_);
    tf32_gemm<<<gBig, 256, GSMEM>>>(hidden, Wk, bk, nullptr, Kp, M, H_, H_);
    tf32_gemm<<<gBig, 256, GSMEM>>>(hidden, Wv, bv, nullptr, Vp, M, H_, H_);

    // positional projections (shared Wq/Wk) + transposed diff tables
    tf32_gemm<<<gPos, 256, GSMEM>>>(rel, Wk, bk, nullptr, PK, 512, H_, H_);
    tf32_gemm<<<gPos, 256, GSMEM>>>(rel, Wq, bq, nullptr, PQ, 512, H_, H_);
    build_pos_t<<<511, 768>>>(PK, PQ, PKT, PQT);

    // MMA attention
    const int smem_attn =
        (128 * QST + 128 * KST + 128 * VST + 128 * SST + 3 * 128 + 256) * 4;
    cudaFuncSetAttribute(attn_mma,
                         cudaFuncAttributeMaxDynamicSharedMemorySize, smem_attn);
    attn_mma<<<dim3(NH_, NB_, B_), 256, smem_attn>>>(Qp, Kp, Vp, PKT, PQT, CT);

    // output projection + residual, then layernorm
    tf32_gemm<<<gBig, 256, GSMEM>>>(CT, Wo, bo, hidden, XR, M, H_, H_);
    ln_kernel<<<M, 256>>>(XR, lns, lnb, out);
}

// round 8
// speedup vs baseline: 4.1051x; 1.2776x over previous
#include <cuda_runtime.h>
#include <cuda_fp16.h>
#include <math.h>
#include <stdint.h>

#define B_   4
#define S_   8192
#define H_   768
#define NH_  12
#define HD_  64
#define NB_  64
#define TOT_ (B_*S_*H_)

// attention smem strides
#define QSTU 36    // u32 stride for fp16 Q/K rows (32 u32 data + 4 pad; 36%32=4)
#define VST  72    // fp32 V stride
#define SST  132   // fp32 score stride

// fp16 gemm config: BK=32 halves
#define GST   20                   // u32 stride per 32-half row (16 data + 4 pad)
#define GSTG  (128 * GST)          // u32 per stage per operand
#define GNSTG 3
#define GKT   24                   // 768 / 32
#define GSMEM (2 * GNSTG * GSTG * 4)   // 61440 B

// ---------------- scratch (device globals; no allocs allowed) ----------------
__device__ __half g_HH[TOT_];              // hidden fp16
__device__ __half g_RELH[512 * H_];        // rel fp16
__device__ __half g_WTh[4 * H_ * H_];      // transposed fp16 Wq,Wk,Wv,Wo
__device__ __half g_Qh[TOT_];
__device__ __half g_Kh[TOT_];
__device__ float  g_V[TOT_];
__device__ __half g_CTH[TOT_];
__device__ float  g_XR[TOT_];
__device__ float  g_PK[512 * H_];
__device__ float  g_PQ[512 * H_];
__device__ __half g_PKH[NH_ * 512 * HD_];  // [h][dd+1][d] fp16, row0 = pad
__device__ __half g_PQH[NH_ * 512 * HD_];

// ---------------- helpers -----------------------------------------------------
__device__ __forceinline__ void mma_tf32(float* c, const uint32_t* a, const uint32_t* b) {
    asm volatile(
        "mma.sync.aligned.m16n8k8.row.col.f32.tf32.tf32.f32 "
        "{%0,%1,%2,%3},{%4,%5,%6,%7},{%8,%9},{%0,%1,%2,%3};\n"
        : "+f"(c[0]), "+f"(c[1]), "+f"(c[2]), "+f"(c[3])
        : "r"(a[0]), "r"(a[1]), "r"(a[2]), "r"(a[3]), "r"(b[0]), "r"(b[1]));
}

__device__ __forceinline__ void mma_f16(float* c, const uint32_t* a, const uint32_t* b) {
    asm volatile(
        "mma.sync.aligned.m16n8k16.row.col.f32.f16.f16.f32 "
        "{%0,%1,%2,%3},{%4,%5,%6,%7},{%8,%9},{%0,%1,%2,%3};\n"
        : "+f"(c[0]), "+f"(c[1]), "+f"(c[2]), "+f"(c[3])
        : "r"(a[0]), "r"(a[1]), "r"(a[2]), "r"(a[3]), "r"(b[0]), "r"(b[1]));
}

__device__ __forceinline__ void cp16u(uint32_t* dst_smem, const void* src) {
    uint32_t d = (uint32_t)__cvta_generic_to_shared(dst_smem);
    asm volatile("cp.async.cg.shared.global [%0], [%1], 16;\n" :: "r"(d), "l"(src));
}
__device__ __forceinline__ void cp_commit() {
    asm volatile("cp.async.commit_group;\n");
}

// ---------------- conversion kernels -----------------------------------------
__global__ void __launch_bounds__(256) f2h_kernel(
    const float* __restrict__ x, __half* __restrict__ y)
{
    size_t i = ((size_t)blockIdx.x * 256 + threadIdx.x) * 4;
    float4 v = *(const float4*)(x + i);
    *(__half2*)(y + i)     = __floats2half2_rn(v.x, v.y);
    *(__half2*)(y + i + 2) = __floats2half2_rn(v.z, v.w);
}

// WT[n][k] = fp16(W[k][n])
__global__ void __launch_bounds__(256) transpose768h(
    const float* __restrict__ W, __half* __restrict__ WT)
{
    __shared__ float t[32][33];
    int x = blockIdx.x * 32 + threadIdx.x;
    int y = blockIdx.y * 32 + threadIdx.y;
    #pragma unroll
    for (int i = 0; i < 32; i += 8)
        t[threadIdx.y + i][threadIdx.x] = W[(size_t)(y + i) * H_ + x];
    __syncthreads();
    x = blockIdx.y * 32 + threadIdx.x;
    y = blockIdx.x * 32 + threadIdx.y;
    #pragma unroll
    for (int i = 0; i < 32; i += 8)
        WT[(size_t)(y + i) * H_ + x] = __float2half_rn(t[threadIdx.x][threadIdx.y + i]);
}

// ---------------- fp16 tensor-core GEMM, 3-stage cp.async, 2 CTAs/SM ---------
// C = A[M,768](fp16) @ WT[N][K](fp16)^T + bias (+residual fp32).
// 128x128 tile, BK=32, 8 warps 4m x 2n, m16n8k16. Out: fp32 (Cf) or fp16 (Ch).
__global__ void __launch_bounds__(256, 2) fp16_gemm(
    const __half* __restrict__ A, const __half* __restrict__ Bw,
    const float* __restrict__ bias, const float* __restrict__ Rres,
    float* __restrict__ Cf, __half* __restrict__ Ch, int M)
{
    extern __shared__ uint32_t gsm[];
    uint32_t* As = gsm;
    uint32_t* Bs = gsm + GNSTG * GSTG;

    const int tid  = threadIdx.x;
    const int lane = tid & 31;
    const int warp = tid >> 5;
    const int wm   = (warp & 3) * 32;
    const int wn   = (warp >> 2) * 64;
    const int bm   = blockIdx.y * 128;
    const int bn   = blockIdx.x * 128;
    const int gid  = lane >> 2;
    const int tig  = lane & 3;

    // fill coords: 512 cp16 per operand per stage -> 2 per thread per operand
    const int fr = tid >> 1;                 // 0..127 row
    const int fc = (tid & 1) << 1;           // 0 or 2 (two uint4 each)

    float acc[2][8][4];
    #pragma unroll
    for (int mt = 0; mt < 2; mt++)
        #pragma unroll
        for (int nt = 0; nt < 8; nt++)
            #pragma unroll
            for (int i = 0; i < 4; i++) acc[mt][nt][i] = 0.f;

    auto fill = [&](int s, int kt) {
        const int kb = kt * 32;
        const __half* Ab = A  + (size_t)(bm + fr) * H_ + kb;
        const __half* Bb = Bw + (size_t)(bn + fr) * H_ + kb;
        uint32_t* as = As + s * GSTG + fr * GST;
        uint32_t* bs = Bs + s * GSTG + fr * GST;
        cp16u(&as[fc * 4],       Ab + fc * 8);
        cp16u(&as[(fc + 1) * 4], Ab + (fc + 1) * 8);
        cp16u(&bs[fc * 4],       Bb + fc * 8);
        cp16u(&bs[(fc + 1) * 4], Bb + (fc + 1) * 8);
        cp_commit();
    };

    fill(0, 0);
    fill(1, 1);

    for (int kt = 0; kt < GKT; kt++) {
        if (kt + 1 < GKT) asm volatile("cp.async.wait_group 1;\n");
        else              asm volatile("cp.async.wait_group 0;\n");
        __syncthreads();

        const uint32_t* as = As + (kt % GNSTG) * GSTG;
        const uint32_t* bs = Bs + (kt % GNSTG) * GSTG;

        #pragma unroll
        for (int ks = 0; ks < 2; ks++) {
            const int wb = ks * 8;
            uint32_t a[2][4], b[8][2];
            #pragma unroll
            for (int mt = 0; mt < 2; mt++) {
                int r0 = wm + mt * 16 + gid;
                a[mt][0] = as[r0 * GST + wb + tig];
                a[mt][1] = as[(r0 + 8) * GST + wb + tig];
                a[mt][2] = as[r0 * GST + wb + 4 + tig];
                a[mt][3] = as[(r0 + 8) * GST + wb + 4 + tig];
            }
            #pragma unroll
            for (int nt = 0; nt < 8; nt++) {
                int cc = wn + nt * 8 + gid;
                b[nt][0] = bs[cc * GST + wb + tig];
                b[nt][1] = bs[cc * GST + wb + 4 + tig];
            }
            #pragma unroll
            for (int mt = 0; mt < 2; mt++)
                #pragma unroll
                for (int nt = 0; nt < 8; nt++)
                    mma_f16(acc[mt][nt], a[mt], b[nt]);
        }
        __syncthreads();

        if (kt + 2 < GKT) fill((kt + 2) % GNSTG, kt + 2);
    }

    #pragma unroll
    for (int mt = 0; mt < 2; mt++) {
        #pragma unroll
        for (int hi = 0; hi < 2; hi++) {
            size_t row = (size_t)bm + wm + mt * 16 + gid + hi * 8;
            #pragma unroll
            for (int nt = 0; nt < 8; nt++) {
                int col = bn + wn + nt * 8 + tig * 2;
                float v0 = acc[mt][nt][hi * 2 + 0] + bias[col];
                float v1 = acc[mt][nt][hi * 2 + 1] + bias[col + 1];
                if (Rres != nullptr) {
                    float2 rr = *(const float2*)(Rres + row * (size_t)H_ + col);
                    v0 += rr.x; v1 += rr.y;
                }
                if (Cf != nullptr)
                    *(float2*)(Cf + row * (size_t)H_ + col) = make_float2(v0, v1);
                else
                    *(__half2*)(Ch + row * (size_t)H_ + col) = __floats2half2_rn(v0, v1);
            }
        }
    }
}

// ---------------- bucketization + fp16 pos tables ----------------------------
__device__ __forceinline__ int bucket_idx_dev(int d)
{
    int ad = d < 0 ? -d : d;
    int v;
    if (ad <= 128) {
        v = d;
    } else {
        float t = logf((float)ad / 128.0f);
        t = t / 0.6892332713f;                   // fp32(ln(255/128))
        t = t * 127.0f;
        float lp = ceilf(t) + 128.0f;
        v = (int)(d < 0 ? -lp : lp);
    }
    v += 256;
    return v < 0 ? 0 : (v > 511 ? 511 : v);
}

// PKH[h][dd+1][d] = fp16(PK[bucket(dd-383)][h*64+d]); row 0 = pad(0)
__global__ void build_pos_h(const float* __restrict__ PK, const float* __restrict__ PQ,
                            __half* __restrict__ PKH, __half* __restrict__ PQH)
{
    int dd = blockIdx.x;                         // 0..510
    int t  = threadIdx.x;                        // 0..767
    int p  = bucket_idx_dev(dd - 383);
    int h  = t >> 6;
    int d  = t & 63;
    size_t dst = ((size_t)h * 512 + dd + 1) * HD_ + d;
    PKH[dst] = __float2half_rn(PK[(size_t)p * H_ + t]);
    PQH[dst] = __float2half_rn(PQ[(size_t)p * H_ + t]);
    if (dd == 0) {
        PKH[((size_t)h * 512) * HD_ + d] = __float2half_rn(0.f);
        PQH[((size_t)h * 512) * HD_ + d] = __float2half_rn(0.f);
    }
}

// ---------------- attention: fp16 scores, tf32 PV ----------------------------
__global__ void __launch_bounds__(256, 1) attn_mma(
    const __half* __restrict__ Qh, const __half* __restrict__ Kh,
    const float* __restrict__ V,
    const __half* __restrict__ PKH, const __half* __restrict__ PQH,
    __half* __restrict__ CTH)
{
    extern __shared__ char smc[];
    uint32_t* Qsu = (uint32_t*)smc;                       // 128*QSTU
    uint32_t* Ksu = Qsu + 128 * QSTU;                     // 128*QSTU
    float* Vs   = (float*)(Ksu + 128 * QSTU);             // 128*VST
    float* Ss   = Vs + 128 * VST;                         // 128*SST
    float* mrow = Ss + 128 * SST;                         // 128
    float* lrow = mrow + 128;
    float* crow = lrow + 128;
    float* pbuf = crow + 128;                             // 256

    const int h = blockIdx.x, n = blockIdx.y, b = blockIdx.z;
    const int tid  = threadIdx.x;
    const int lane = tid & 31;
    const int warp = tid >> 5;
    const int gid  = lane >> 2;
    const int tig  = lane & 3;
    const size_t qrow0 = (size_t)b * S_ + (size_t)n * 128;
    const size_t hoff  = (size_t)h * HD_;

    // stage Q tile: 64 halves/row = 8 uint4/row, full coverage
    for (int i = tid; i < 128 * 8; i += 256) {
        int r = i >> 3, c = i & 7;
        uint4 v = *(const uint4*)(Qh + (qrow0 + r) * H_ + hoff + c * 8);
        uint32_t* d = &Qsu[r * QSTU + c * 4];
        d[0] = v.x; d[1] = v.y; d[2] = v.z; d[3] = v.w;
    }
    if (tid < 128) { mrow[tid] = -1e30f; lrow[tid] = 0.f; }
    __syncthreads();

    float ctx[8][4];
    #pragma unroll
    for (int nt = 0; nt < 8; nt++)
        #pragma unroll
        for (int i = 0; i < 4; i++) ctx[nt][i] = 0.f;

    const uint32_t* pk32 = (const uint32_t*)PKH + (size_t)h * 512 * 32;
    const uint32_t* pq32 = (const uint32_t*)PQH + (size_t)h * 512 * 32;
    const float scale = 0.07216878364870323f;    // 1/sqrt(192)

    for (int c = 0; c < 3; c++) {
        const int  c0  = c * 128;
        const long sk0 = (long)n * 128 - 128 + c0;

        // stage K (fp16, full row) and V (fp32), zero-pad outside sequence
        for (int i = tid; i < 128 * 8; i += 256) {
            int r = i >> 3, cc = i & 7;
            long s = sk0 + r;
            uint4 kv = make_uint4(0u, 0u, 0u, 0u);
            if (s >= 0 && s < S_)
                kv = *(const uint4*)(Kh + ((size_t)b * S_ + s) * H_ + hoff + cc * 8);
            uint32_t* d = &Ksu[r * QSTU + cc * 4];
            d[0] = kv.x; d[1] = kv.y; d[2] = kv.z; d[3] = kv.w;
        }
        for (int i = tid; i < 128 * 16; i += 256) {
            int r = i >> 4, c4 = (i & 15) << 2;
            long s = sk0 + r;
            float4 vv = make_float4(0.f, 0.f, 0.f, 0.f);
            if (s >= 0 && s < S_)
                vv = *(const float4*)(V + ((size_t)b * S_ + s) * H_ + hoff + c4);
            *(float4*)&Vs[r * VST + c4] = vv;
        }
        __syncthreads();

        // ---- c2c: S = Q @ K^T (fp16, 4 ksteps of k16) ----
        {
            const int wm = (warp & 3) * 32, wn = (warp >> 2) * 64;
            float acc[2][8][4];
            #pragma unroll
            for (int mt = 0; mt < 2; mt++)
                #pragma unroll
                for (int nt = 0; nt < 8; nt++)
                    #pragma unroll
                    for (int i = 0; i < 4; i++) acc[mt][nt][i] = 0.f;

            #pragma unroll
            for (int ks = 0; ks < 4; ks++) {
                const int wb = ks * 8;
                uint32_t a[2][4], bf[8][2];
                #pragma unroll
                for (int mt = 0; mt < 2; mt++) {
                    int r0 = wm + mt * 16 + gid;
                    a[mt][0] = Qsu[r0 * QSTU + wb + tig];
                    a[mt][1] = Qsu[(r0 + 8) * QSTU + wb + tig];
                    a[mt][2] = Qsu[r0 * QSTU + wb + 4 + tig];
                    a[mt][3] = Qsu[(r0 + 8) * QSTU + wb + 4 + tig];
                }
                #pragma unroll
                for (int nt = 0; nt < 8; nt++) {
                    int cc = wn + nt * 8 + gid;
                    bf[nt][0] = Ksu[cc * QSTU + wb + tig];
                    bf[nt][1] = Ksu[cc * QSTU + wb + 4 + tig];
                }
                #pragma unroll
                for (int mt = 0; mt < 2; mt++)
                    #pragma unroll
                    for (int nt = 0; nt < 8; nt++)
                        mma_f16(acc[mt][nt], a[mt], bf[nt]);
            }
            #pragma unroll
            for (int mt = 0; mt < 2; mt++) {
                int r1 = wm + mt * 16 + gid;
                #pragma unroll
                for (int nt = 0; nt < 8; nt++) {
                    int cc = wn + nt * 8 + 2 * tig;
                    *(float2*)&Ss[r1 * SST + cc] =
                        make_float2(acc[mt][nt][0], acc[mt][nt][1]);
                    *(float2*)&Ss[(r1 + 8) * SST + cc] =
                        make_float2(acc[mt][nt][2], acc[mt][nt][3]);
                }
            }
        }
        __syncthreads();

        // ---- C2P: Q @ PKH_slice^T, scatter-add S[q][q-col+128] ----
        {
            const int wm = (warp & 3) * 32, wn2 = (warp >> 2) * 128;
            const int colbase = 256 - c0;
            #pragma unroll
            for (int half = 0; half < 2; half++) {
                const int cb = wn2 + half * 64;
                float acc[2][8][4];
                #pragma unroll
                for (int mt = 0; mt < 2; mt++)
                    #pragma unroll
                    for (int nt = 0; nt < 8; nt++)
                        #pragma unroll
                        for (int i = 0; i < 4; i++) acc[mt][nt][i] = 0.f;

                #pragma unroll
                for (int ks = 0; ks < 4; ks++) {
                    const int wb = ks * 8;
                    uint32_t a[2][4], bf[8][2];
                    #pragma unroll
                    for (int mt = 0; mt < 2; mt++) {
                        int r0 = wm + mt * 16 + gid;
                        a[mt][0] = Qsu[r0 * QSTU + wb + tig];
                        a[mt][1] = Qsu[(r0 + 8) * QSTU + wb + tig];
                        a[mt][2] = Qsu[r0 * QSTU + wb + 4 + tig];
                        a[mt][3] = Qsu[(r0 + 8) * QSTU + wb + 4 + tig];
                    }
                    #pragma unroll
                    for (int nt = 0; nt < 8; nt++) {
                        int cc = colbase + cb + nt * 8 + gid;
                        bf[nt][0] = __ldg(&pk32[(size_t)cc * 32 + wb + tig]);
                        bf[nt][1] = __ldg(&pk32[(size_t)cc * 32 + wb + 4 + tig]);
                    }
                    #pragma unroll
                    for (int mt = 0; mt < 2; mt++)
                        #pragma unroll
                        for (int nt = 0; nt < 8; nt++)
                            mma_f16(acc[mt][nt], a[mt], bf[nt]);
                }
                #pragma unroll
                for (int mt = 0; mt < 2; mt++) {
                    int r1 = wm + mt * 16 + gid;
                    #pragma unroll
                    for (int nt = 0; nt < 8; nt++) {
                        int ci = cb + nt * 8 + 2 * tig;
                        int jj;
                        jj = r1 - ci + 128;
                        if (jj >= 0 && jj < 128) Ss[r1 * SST + jj] += acc[mt][nt][0];
                        jj = r1 - ci + 127;
                        if (jj >= 0 && jj < 128) Ss[r1 * SST + jj] += acc[mt][nt][1];
                        int r2 = r1 + 8;
                        jj = r2 - ci + 128;
                        if (jj >= 0 && jj < 128) Ss[r2 * SST + jj] += acc[mt][nt][2];
                        jj = r2 - ci + 127;
                        if (jj >= 0 && jj < 128) Ss[r2 * SST + jj] += acc[mt][nt][3];
                    }
                }
                __syncthreads();
            }
        }

        // ---- P2C: K @ PQH_slice^T, scatter-add S[jj+col-128][jj] ----
        {
            const int wm = (warp & 3) * 32, wn2 = (warp >> 2) * 128;
            const int colbase = 256 - c0;
            #pragma unroll
            for (int half = 0; half < 2; half++) {
                const int cb = wn2 + half * 64;
                float acc[2][8][4];
                #pragma unroll
                for (int mt = 0; mt < 2; mt++)
                    #pragma unroll
                    for (int nt = 0; nt < 8; nt++)
                        #pragma unroll
                        for (int i = 0; i < 4; i++) acc[mt][nt][i] = 0.f;

                #pragma unroll
                for (int ks = 0; ks < 4; ks++) {
                    const int wb = ks * 8;
                    uint32_t a[2][4], bf[8][2];
                    #pragma unroll
                    for (int mt = 0; mt < 2; mt++) {
                        int r0 = wm + mt * 16 + gid;
                        a[mt][0] = Ksu[r0 * QSTU + wb + tig];
                        a[mt][1] = Ksu[(r0 + 8) * QSTU + wb + tig];
                        a[mt][2] = Ksu[r0 * QSTU + wb + 4 + tig];
                        a[mt][3] = Ksu[(r0 + 8) * QSTU + wb + 4 + tig];
                    }
                    #pragma unroll
                    for (int nt = 0; nt < 8; nt++) {
                        int cc = colbase + cb + nt * 8 + gid;
                        bf[nt][0] = __ldg(&pq32[(size_t)cc * 32 + wb + tig]);
                        bf[nt][1] = __ldg(&pq32[(size_t)cc * 32 + wb + 4 + tig]);
                    }
                    #pragma unroll
                    for (int mt = 0; mt < 2; mt++)
                        #pragma unroll
                        for (int nt = 0; nt < 8; nt++)
                            mma_f16(acc[mt][nt], a[mt], bf[nt]);
                }
                #pragma unroll
                for (int mt = 0; mt < 2; mt++) {
                    int r1 = wm + mt * 16 + gid;
                    #pragma unroll
                    for (int nt = 0; nt < 8; nt++) {
                        int ci = cb + nt * 8 + 2 * tig;
                        int q;
                        q = r1 + ci - 128;
                        if (q >= 0 && q < 128) Ss[q * SST + r1] += acc[mt][nt][0];
                        q = r1 + ci - 127;
                        if (q >= 0 && q < 128) Ss[q * SST + r1] += acc[mt][nt][1];
                        int r2 = r1 + 8;
                        q = r2 + ci - 128;
                        if (q >= 0 && q < 128) Ss[q * SST + r2] += acc[mt][nt][2];
                        q = r2 + ci - 127;
                        if (q >= 0 && q < 128) Ss[q * SST + r2] += acc[mt][nt][3];
                    }
                }
                __syncthreads();
            }
        }

        // ---- online softmax (2 threads per row) ----
        {
            const int r  = tid & 127;
            const int hh = tid >> 7;
            float* srow = Ss + r * SST + hh * 64;
            float mx = -1e30f;
            #pragma unroll 8
            for (int j = 0; j < 64; j++) mx = fmaxf(mx, srow[j]);
            pbuf[tid] = mx;
            __syncthreads();
            if (tid < 128) {
                float mb   = fmaxf(pbuf[tid], pbuf[tid + 128]) * scale;
                float mold = mrow[tid];
                float mnew = fmaxf(mold, mb);
                crow[tid]  = __expf(mold - mnew);
                mrow[tid]  = mnew;
            }
            __syncthreads();
            float mnew = mrow[r];
            float ssum = 0.f;
            #pragma unroll 8
            for (int j = 0; j < 64; j++) {
                float p = __expf(srow[j] * scale - mnew);
                srow[j] = p;
                ssum += p;
            }
            pbuf[tid] = ssum;
            __syncthreads();
            if (tid < 128)
                lrow[tid] = lrow[tid] * crow[tid] + pbuf[tid] + pbuf[tid + 128];
            __syncthreads();
        }

        // ---- PV: ctx = ctx*corr + P @ V (tf32) ----
        {
            const int wm1 = warp * 16;
            float c1 = crow[wm1 + gid], c2 = crow[wm1 + gid + 8];
            #pragma unroll
            for (int nt = 0; nt < 8; nt++) {
                ctx[nt][0] *= c1; ctx[nt][1] *= c1;
                ctx[nt][2] *= c2; ctx[nt][3] *= c2;
            }
            #pragma unroll
            for (int ks = 0; ks < 16; ks++) {
                const int k8 = ks * 8;
                uint32_t a[4], bf[8][2];
                int r0 = wm1 + gid;
                a[0] = __float_as_uint(Ss[r0 * SST + k8 + tig]);
                a[1] = __float_as_uint(Ss[(r0 + 8) * SST + k8 + tig]);
                a[2] = __float_as_uint(Ss[r0 * SST + k8 + tig + 4]);
                a[3] = __float_as_uint(Ss[(r0 + 8) * SST + k8 + tig + 4]);
                #pragma unroll
                for (int nt = 0; nt < 8; nt++) {
                    int cc = nt * 8 + gid;
                    bf[nt][0] = __float_as_uint(Vs[(k8 + tig) * VST + cc]);
                    bf[nt][1] = __float_as_uint(Vs[(k8 + tig + 4) * VST + cc]);
                }
                #pragma unroll
                for (int nt = 0; nt < 8; nt++)
                    mma_tf32(ctx[nt], a, bf[nt]);
            }
        }
        __syncthreads();
    }

    // ---- write ctx (fp16 for out-proj input) ----
    {
        const int wm1 = warp * 16;
        float inv1 = 1.0f / lrow[wm1 + gid];
        float inv2 = 1.0f / lrow[wm1 + gid + 8];
        size_t row1 = qrow0 + wm1 + gid;
        size_t row2 = row1 + 8;
        #pragma unroll
        for (int nt = 0; nt < 8; nt++) {
            int col = nt * 8 + 2 * tig;
            *(__half2*)(CTH + row1 * H_ + hoff + col) =
                __floats2half2_rn(ctx[nt][0] * inv1, ctx[nt][1] * inv1);
            *(__half2*)(CTH + row2 * H_ + hoff + col) =
                __floats2half2_rn(ctx[nt][2] * inv2, ctx[nt][3] * inv2);
        }
    }
}

// ---------------- LayerNorm over H=768, one row per CTA ----------------------
__global__ void __launch_bounds__(256) ln_kernel(
    const float* __restrict__ X, const float* __restrict__ gam,
    const float* __restrict__ bet, float* __restrict__ out)
{
    const int row = blockIdx.x;
    const int t   = threadIdx.x;
    const float* x = X + (size_t)row * H_;
    float v0 = x[t], v1 = x[t + 256], v2 = x[t + 512];
    float s = v0 + v1 + v2;
    float q = v0 * v0 + v1 * v1 + v2 * v2;

    __shared__ float sh[64];
    #pragma unroll
    for (int o = 16; o > 0; o >>= 1) {
        s += __shfl_down_sync(0xffffffffu, s, o);
        q += __shfl_down_sync(0xffffffffu, q, o);
    }
    int w = t >> 5, lane = t & 31;
    if (lane == 0) { sh[w] = s; sh[32 + w] = q; }
    __syncthreads();
    if (t == 0) {
        float ts = 0.f, tq = 0.f;
        #pragma unroll
        for (int i = 0; i < 8; i++) { ts += sh[i]; tq += sh[32 + i]; }
        sh[0] = ts;
        sh[32] = tq;
    }
    __syncthreads();
    float mu  = sh[0] * (1.0f / 768.0f);
    float var = sh[32] * (1.0f / 768.0f) - mu * mu;
    float r   = rsqrtf(var + 1e-7f);

    float* o = out + (size_t)row * H_;
    o[t]       = (v0 - mu) * r * gam[t]       + bet[t];
    o[t + 256] = (v1 - mu) * r * gam[t + 256] + bet[t + 256];
    o[t + 512] = (v2 - mu) * r * gam[t + 512] + bet[t + 512];
}

// ---------------- launch ------------------------------------------------------
extern "C" void kernel_launch(void* const* d_in, const int* in_sizes, int n_in,
                              void* d_out, int out_size)
{
    const float* hidden = (const float*)d_in[0];
    const float* rel    = (const float*)d_in[1];
    const float* Wq = (const float*)d_in[2];  const float* bq = (const float*)d_in[3];
    const float* Wk = (const float*)d_in[4];  const float* bk = (const float*)d_in[5];
    const float* Wv = (const float*)d_in[6];  const float* bv = (const float*)d_in[7];
    const float* Wo = (const float*)d_in[8];  const float* bo = (const float*)d_in[9];
    const float* lns = (const float*)d_in[10];
    const float* lnb = (const float*)d_in[11];
    float* out = (float*)d_out;

    __half *HH, *RELH, *WTh, *Qh, *Kh, *CTH, *PKH, *PQH;
    float *Vp, *PK, *PQ, *XR;
    cudaGetSymbolAddress((void**)&HH,   g_HH);
    cudaGetSymbolAddress((void**)&RELH, g_RELH);
    cudaGetSymbolAddress((void**)&WTh,  g_WTh);
    cudaGetSymbolAddress((void**)&Qh,   g_Qh);
    cudaGetSymbolAddress((void**)&Kh,   g_Kh);
    cudaGetSymbolAddress((void**)&Vp,   g_V);
    cudaGetSymbolAddress((void**)&CTH,  g_CTH);
    cudaGetSymbolAddress((void**)&PK,   g_PK);
    cudaGetSymbolAddress((void**)&PQ,   g_PQ);
    cudaGetSymbolAddress((void**)&PKH,  g_PKH);
    cudaGetSymbolAddress((void**)&PQH,  g_PQH);
    cudaGetSymbolAddress((void**)&XR,   g_XR);

    __half* WThq = WTh;
    __half* WThk = WTh + (size_t)H_ * H_;
    __half* WThv = WTh + (size_t)2 * H_ * H_;
    __half* WTho = WTh + (size_t)3 * H_ * H_;

    const int M = B_ * S_;                       // 32768

    // conversions
    f2h_kernel<<<TOT_ / 1024, 256>>>(hidden, HH);
    f2h_kernel<<<(512 * H_) / 1024, 256>>>(rel, RELH);
    dim3 tg(24, 24), tb(32, 8);
    transpose768h<<<tg, tb>>>(Wq, WThq);
    transpose768h<<<tg, tb>>>(Wk, WThk);
    transpose768h<<<tg, tb>>>(Wv, WThv);
    transpose768h<<<tg, tb>>>(Wo, WTho);

    cudaFuncSetAttribute(fp16_gemm,
                         cudaFuncAttributeMaxDynamicSharedMemorySize, GSMEM);

    dim3 gBig(H_ / 128, M / 128);                // (6, 256)
    dim3 gPos(H_ / 128, 512 / 128);              // (6, 4)

    // QKV projections: Q,K -> fp16, V -> fp32
    fp16_gemm<<<gBig, 256, GSMEM>>>(HH, WThq, bq, nullptr, nullptr, Qh, M);
    fp16_gemm<<<gBig, 256, GSMEM>>>(HH, WThk, bk, nullptr, nullptr, Kh, M);
    fp16_gemm<<<gBig, 256, GSMEM>>>(HH, WThv, bv, nullptr, Vp, nullptr, M);

    // positional projections (fp32 out) + fp16 diff tables
    fp16_gemm<<<gPos, 256, GSMEM>>>(RELH, WThk, bk, nullptr, PK, nullptr, 512);
    fp16_gemm<<<gPos, 256, GSMEM>>>(RELH, WThq, bq, nullptr, PQ, nullptr, 512);
    build_pos_h<<<511, 768>>>(PK, PQ, PKH, PQH);

    // attention
    const int smem_attn =
        (128 * QSTU * 2) * 4 + (128 * VST + 128 * SST + 3 * 128 + 256) * 4;
    cudaFuncSetAttribute(attn_mma,
                         cudaFuncAttributeMaxDynamicSharedMemorySize, smem_attn);
    attn_mma<<<dim3(NH_, NB_, B_), 256, smem_attn>>>(Qh, Kh, Vp, PKH, PQH, CTH);

    // output projection + residual, then layernorm
    fp16_gemm<<<gBig, 256, GSMEM>>>(CTH, WTho, bo, hidden, XR, nullptr, M);
    ln_kernel<<<M, 256>>>(XR, lns, lnb, out);
}

// round 9
// speedup vs baseline: 4.1552x; 1.0122x over previous
#include <cuda_runtime.h>
#include <cuda_fp16.h>
#include <math.h>
#include <stdint.h>

#define B_   4
#define S_   8192
#define H_   768
#define NH_  12
#define HD_  64
#define NB_  64
#define TOT_ (B_*S_*H_)

// attention smem strides
#define QSTU 36    // u32 stride for fp16 Q/K/V rows (32 u32 data + 4 pad)
#define PSTU 68    // u32 stride for fp16 P rows (64 u32 data + 4 pad)
#define SST  132   // fp32 score stride

// fp16 gemm config: BK=32 halves
#define GST   20                   // u32 stride per 32-half row (16 data + 4 pad)
#define GSTG  (128 * GST)          // u32 per stage per operand
#define GNSTG 3
#define GKT   24                   // 768 / 32
#define GSMEM (2 * GNSTG * GSTG * 4)   // 61440 B

// ---------------- scratch (device globals; no allocs allowed) ----------------
__device__ __half g_HH[TOT_];              // hidden fp16
__device__ __half g_RELH[512 * H_];        // rel fp16
__device__ __half g_WTh[4 * H_ * H_];      // transposed fp16 Wq,Wk,Wv,Wo
__device__ __half g_Qh[TOT_];
__device__ __half g_Kh[TOT_];
__device__ __half g_Vh[TOT_];
__device__ __half g_CTH[TOT_];
__device__ float  g_XR[TOT_];
__device__ float  g_PK[512 * H_];
__device__ float  g_PQ[512 * H_];
__device__ __half g_PKH[NH_ * 512 * HD_];  // [h][dd+1][d] fp16, row0 = pad
__device__ __half g_PQH[NH_ * 512 * HD_];

// ---------------- helpers -----------------------------------------------------
__device__ __forceinline__ void mma_f16(float* c, const uint32_t* a, const uint32_t* b) {
    asm volatile(
        "mma.sync.aligned.m16n8k16.row.col.f32.f16.f16.f32 "
        "{%0,%1,%2,%3},{%4,%5,%6,%7},{%8,%9},{%0,%1,%2,%3};\n"
        : "+f"(c[0]), "+f"(c[1]), "+f"(c[2]), "+f"(c[3])
        : "r"(a[0]), "r"(a[1]), "r"(a[2]), "r"(a[3]), "r"(b[0]), "r"(b[1]));
}

__device__ __forceinline__ void ldsm_x4_t(
    uint32_t& r0, uint32_t& r1, uint32_t& r2, uint32_t& r3, uint32_t addr)
{
    asm volatile(
        "ldmatrix.sync.aligned.m8n8.x4.trans.shared.b16 {%0,%1,%2,%3}, [%4];"
        : "=r"(r0), "=r"(r1), "=r"(r2), "=r"(r3) : "r"(addr));
}

__device__ __forceinline__ void cp16u(uint32_t* dst_smem, const void* src) {
    uint32_t d = (uint32_t)__cvta_generic_to_shared(dst_smem);
    asm volatile("cp.async.cg.shared.global [%0], [%1], 16;\n" :: "r"(d), "l"(src));
}
__device__ __forceinline__ void cp_commit() {
    asm volatile("cp.async.commit_group;\n");
}

// ---------------- conversion kernels -----------------------------------------
__global__ void __launch_bounds__(256) f2h_kernel(
    const float* __restrict__ x, __half* __restrict__ y)
{
    size_t i = ((size_t)blockIdx.x * 256 + threadIdx.x) * 4;
    float4 v = *(const float4*)(x + i);
    *(__half2*)(y + i)     = __floats2half2_rn(v.x, v.y);
    *(__half2*)(y + i + 2) = __floats2half2_rn(v.z, v.w);
}

// WT[n][k] = fp16(W[k][n])
__global__ void __launch_bounds__(256) transpose768h(
    const float* __restrict__ W, __half* __restrict__ WT)
{
    __shared__ float t[32][33];
    int x = blockIdx.x * 32 + threadIdx.x;
    int y = blockIdx.y * 32 + threadIdx.y;
    #pragma unroll
    for (int i = 0; i < 32; i += 8)
        t[threadIdx.y + i][threadIdx.x] = W[(size_t)(y + i) * H_ + x];
    __syncthreads();
    x = blockIdx.y * 32 + threadIdx.x;
    y = blockIdx.x * 32 + threadIdx.y;
    #pragma unroll
    for (int i = 0; i < 32; i += 8)
        WT[(size_t)(y + i) * H_ + x] = __float2half_rn(t[threadIdx.x][threadIdx.y + i]);
}

// ---------------- fp16 tensor-core GEMM, 3-stage cp.async, 2 CTAs/SM ---------
__global__ void __launch_bounds__(256, 2) fp16_gemm(
    const __half* __restrict__ A, const __half* __restrict__ Bw,
    const float* __restrict__ bias, const float* __restrict__ Rres,
    float* __restrict__ Cf, __half* __restrict__ Ch, int M)
{
    extern __shared__ uint32_t gsm[];
    uint32_t* As = gsm;
    uint32_t* Bs = gsm + GNSTG * GSTG;

    const int tid  = threadIdx.x;
    const int lane = tid & 31;
    const int warp = tid >> 5;
    const int wm   = (warp & 3) * 32;
    const int wn   = (warp >> 2) * 64;
    const int bm   = blockIdx.y * 128;
    const int bn   = blockIdx.x * 128;
    const int gid  = lane >> 2;
    const int tig  = lane & 3;

    const int fr = tid >> 1;                 // 0..127 row
    const int fc = (tid & 1) << 1;           // 0 or 2

    float acc[2][8][4];
    #pragma unroll
    for (int mt = 0; mt < 2; mt++)
        #pragma unroll
        for (int nt = 0; nt < 8; nt++)
            #pragma unroll
            for (int i = 0; i < 4; i++) acc[mt][nt][i] = 0.f;

    auto fill = [&](int s, int kt) {
        const int kb = kt * 32;
        const __half* Ab = A  + (size_t)(bm + fr) * H_ + kb;
        const __half* Bb = Bw + (size_t)(bn + fr) * H_ + kb;
        uint32_t* as = As + s * GSTG + fr * GST;
        uint32_t* bs = Bs + s * GSTG + fr * GST;
        cp16u(&as[fc * 4],       Ab + fc * 8);
        cp16u(&as[(fc + 1) * 4], Ab + (fc + 1) * 8);
        cp16u(&bs[fc * 4],       Bb + fc * 8);
        cp16u(&bs[(fc + 1) * 4], Bb + (fc + 1) * 8);
        cp_commit();
    };

    fill(0, 0);
    fill(1, 1);

    for (int kt = 0; kt < GKT; kt++) {
        if (kt + 1 < GKT) asm volatile("cp.async.wait_group 1;\n");
        else              asm volatile("cp.async.wait_group 0;\n");
        __syncthreads();

        const uint32_t* as = As + (kt % GNSTG) * GSTG;
        const uint32_t* bs = Bs + (kt % GNSTG) * GSTG;

        #pragma unroll
        for (int ks = 0; ks < 2; ks++) {
            const int wb = ks * 8;
            uint32_t a[2][4], b[8][2];
            #pragma unroll
            for (int mt = 0; mt < 2; mt++) {
                int r0 = wm + mt * 16 + gid;
                a[mt][0] = as[r0 * GST + wb + tig];
                a[mt][1] = as[(r0 + 8) * GST + wb + tig];
                a[mt][2] = as[r0 * GST + wb + 4 + tig];
                a[mt][3] = as[(r0 + 8) * GST + wb + 4 + tig];
            }
            #pragma unroll
            for (int nt = 0; nt < 8; nt++) {
                int cc = wn + nt * 8 + gid;
                b[nt][0] = bs[cc * GST + wb + tig];
                b[nt][1] = bs[cc * GST + wb + 4 + tig];
            }
            #pragma unroll
            for (int mt = 0; mt < 2; mt++)
                #pragma unroll
                for (int nt = 0; nt < 8; nt++)
                    mma_f16(acc[mt][nt], a[mt], b[nt]);
        }
        __syncthreads();

        if (kt + 2 < GKT) fill((kt + 2) % GNSTG, kt + 2);
    }

    #pragma unroll
    for (int mt = 0; mt < 2; mt++) {
        #pragma unroll
        for (int hi = 0; hi < 2; hi++) {
            size_t row = (size_t)bm + wm + mt * 16 + gid + hi * 8;
            #pragma unroll
            for (int nt = 0; nt < 8; nt++) {
                int col = bn + wn + nt * 8 + tig * 2;
                float v0 = acc[mt][nt][hi * 2 + 0] + bias[col];
                float v1 = acc[mt][nt][hi * 2 + 1] + bias[col + 1];
                if (Rres != nullptr) {
                    float2 rr = *(const float2*)(Rres + row * (size_t)H_ + col);
                    v0 += rr.x; v1 += rr.y;
                }
                if (Cf != nullptr)
                    *(float2*)(Cf + row * (size_t)H_ + col) = make_float2(v0, v1);
                else
                    *(__half2*)(Ch + row * (size_t)H_ + col) = __floats2half2_rn(v0, v1);
            }
        }
    }
}

// ---------------- bucketization + fp16 pos tables ----------------------------
__device__ __forceinline__ int bucket_idx_dev(int d)
{
    int ad = d < 0 ? -d : d;
    int v;
    if (ad <= 128) {
        v = d;
    } else {
        float t = logf((float)ad / 128.0f);
        t = t / 0.6892332713f;                   // fp32(ln(255/128))
        t = t * 127.0f;
        float lp = ceilf(t) + 128.0f;
        v = (int)(d < 0 ? -lp : lp);
    }
    v += 256;
    return v < 0 ? 0 : (v > 511 ? 511 : v);
}

__global__ void build_pos_h(const float* __restrict__ PK, const float* __restrict__ PQ,
                            __half* __restrict__ PKH, __half* __restrict__ PQH)
{
    int dd = blockIdx.x;                         // 0..510
    int t  = threadIdx.x;                        // 0..767
    int p  = bucket_idx_dev(dd - 383);
    int h  = t >> 6;
    int d  = t & 63;
    size_t dst = ((size_t)h * 512 + dd + 1) * HD_ + d;
    PKH[dst] = __float2half_rn(PK[(size_t)p * H_ + t]);
    PQH[dst] = __float2half_rn(PQ[(size_t)p * H_ + t]);
    if (dd == 0) {
        PKH[((size_t)h * 512) * HD_ + d] = __float2half_rn(0.f);
        PQH[((size_t)h * 512) * HD_ + d] = __float2half_rn(0.f);
    }
}

// ---------------- attention: full fp16 MMA (scores + PV) ---------------------
__global__ void __launch_bounds__(256, 1) attn_mma(
    const __half* __restrict__ Qh, const __half* __restrict__ Kh,
    const __half* __restrict__ Vh,
    const __half* __restrict__ PKH, const __half* __restrict__ PQH,
    __half* __restrict__ CTH)
{
    extern __shared__ char smc[];
    uint32_t* Qsu = (uint32_t*)smc;                       // 128*QSTU
    uint32_t* Ksu = Qsu + 128 * QSTU;                     // 128*QSTU
    uint32_t* Vsu = Ksu + 128 * QSTU;                     // 128*QSTU
    uint32_t* Phu = Vsu + 128 * QSTU;                     // 128*PSTU
    float* Ss   = (float*)(Phu + 128 * PSTU);             // 128*SST
    float* mrow = Ss + 128 * SST;                         // 128
    float* lrow = mrow + 128;
    float* crow = lrow + 128;
    float* pbuf = crow + 128;                             // 256

    const int h = blockIdx.x, n = blockIdx.y, b = blockIdx.z;
    const int tid  = threadIdx.x;
    const int lane = tid & 31;
    const int warp = tid >> 5;
    const int gid  = lane >> 2;
    const int tig  = lane & 3;
    const size_t qrow0 = (size_t)b * S_ + (size_t)n * 128;
    const size_t hoff  = (size_t)h * HD_;

    // stage Q tile: 64 halves/row = 8 uint4/row
    for (int i = tid; i < 128 * 8; i += 256) {
        int r = i >> 3, c = i & 7;
        uint4 v = *(const uint4*)(Qh + (qrow0 + r) * H_ + hoff + c * 8);
        uint32_t* d = &Qsu[r * QSTU + c * 4];
        d[0] = v.x; d[1] = v.y; d[2] = v.z; d[3] = v.w;
    }
    if (tid < 128) { mrow[tid] = -1e30f; lrow[tid] = 0.f; }
    __syncthreads();

    float ctx[8][4];
    #pragma unroll
    for (int nt = 0; nt < 8; nt++)
        #pragma unroll
        for (int i = 0; i < 4; i++) ctx[nt][i] = 0.f;

    const uint32_t* pk32 = (const uint32_t*)PKH + (size_t)h * 512 * 32;
    const uint32_t* pq32 = (const uint32_t*)PQH + (size_t)h * 512 * 32;
    const float scale = 0.07216878364870323f;    // 1/sqrt(192)

    // ldmatrix lane base for PV B-fragments (V row-major fp16, stride 144 B)
    const uint32_t vsmem = (uint32_t)__cvta_generic_to_shared(Vsu);
    const int lg  = lane >> 3;                   // 0..3
    const int lr  = lane & 7;
    const int vkb = (lg & 1) * 8 + lr;           // k offset within 16
    const int vnb = (lg >> 1) * 8;               // n offset within 16

    for (int c = 0; c < 3; c++) {
        const int  c0  = c * 128;
        const long sk0 = (long)n * 128 - 128 + c0;

        // stage K and V (fp16), zero-pad outside sequence
        for (int i = tid; i < 128 * 8; i += 256) {
            int r = i >> 3, cc = i & 7;
            long s = sk0 + r;
            uint4 kv = make_uint4(0u, 0u, 0u, 0u);
            uint4 vv = make_uint4(0u, 0u, 0u, 0u);
            if (s >= 0 && s < S_) {
                size_t g = ((size_t)b * S_ + s) * H_ + hoff + cc * 8;
                kv = *(const uint4*)(Kh + g);
                vv = *(const uint4*)(Vh + g);
            }
            uint32_t* dk = &Ksu[r * QSTU + cc * 4];
            dk[0] = kv.x; dk[1] = kv.y; dk[2] = kv.z; dk[3] = kv.w;
            uint32_t* dv = &Vsu[r * QSTU + cc * 4];
            dv[0] = vv.x; dv[1] = vv.y; dv[2] = vv.z; dv[3] = vv.w;
        }
        __syncthreads();

        // ---- c2c: S = Q @ K^T (fp16, 4 ksteps of k16) ----
        {
            const int wm = (warp & 3) * 32, wn = (warp >> 2) * 64;
            float acc[2][8][4];
            #pragma unroll
            for (int mt = 0; mt < 2; mt++)
                #pragma unroll
                for (int nt = 0; nt < 8; nt++)
                    #pragma unroll
                    for (int i = 0; i < 4; i++) acc[mt][nt][i] = 0.f;

            #pragma unroll
            for (int ks = 0; ks < 4; ks++) {
                const int wb = ks * 8;
                uint32_t a[2][4], bf[8][2];
                #pragma unroll
                for (int mt = 0; mt < 2; mt++) {
                    int r0 = wm + mt * 16 + gid;
                    a[mt][0] = Qsu[r0 * QSTU + wb + tig];
                    a[mt][1] = Qsu[(r0 + 8) * QSTU + wb + tig];
                    a[mt][2] = Qsu[r0 * QSTU + wb + 4 + tig];
                    a[mt][3] = Qsu[(r0 + 8) * QSTU + wb + 4 + tig];
                }
                #pragma unroll
                for (int nt = 0; nt < 8; nt++) {
                    int cc = wn + nt * 8 + gid;
                    bf[nt][0] = Ksu[cc * QSTU + wb + tig];
                    bf[nt][1] = Ksu[cc * QSTU + wb + 4 + tig];
                }
                #pragma unroll
                for (int mt = 0; mt < 2; mt++)
                    #pragma unroll
                    for (int nt = 0; nt < 8; nt++)
                        mma_f16(acc[mt][nt], a[mt], bf[nt]);
            }
            #pragma unroll
            for (int mt = 0; mt < 2; mt++) {
                int r1 = wm + mt * 16 + gid;
                #pragma unroll
                for (int nt = 0; nt < 8; nt++) {
                    int cc = wn + nt * 8 + 2 * tig;
                    *(float2*)&Ss[r1 * SST + cc] =
                        make_float2(acc[mt][nt][0], acc[mt][nt][1]);
                    *(float2*)&Ss[(r1 + 8) * SST + cc] =
                        make_float2(acc[mt][nt][2], acc[mt][nt][3]);
                }
            }
        }
        __syncthreads();

        // ---- C2P: Q @ PKH_slice^T, scatter-add S[q][q-col+128] ----
        // (no intra-section sync: every (row, jj) target has a unique writer)
        {
            const int wm = (warp & 3) * 32, wn2 = (warp >> 2) * 128;
            const int colbase = 256 - c0;
            #pragma unroll
            for (int half = 0; half < 2; half++) {
                const int cb = wn2 + half * 64;
                float acc[2][8][4];
                #pragma unroll
                for (int mt = 0; mt < 2; mt++)
                    #pragma unroll
                    for (int nt = 0; nt < 8; nt++)
                        #pragma unroll
                        for (int i = 0; i < 4; i++) acc[mt][nt][i] = 0.f;

                #pragma unroll
                for (int ks = 0; ks < 4; ks++) {
                    const int wb = ks * 8;
                    uint32_t a[2][4], bf[8][2];
                    #pragma unroll
                    for (int mt = 0; mt < 2; mt++) {
                        int r0 = wm + mt * 16 + gid;
                        a[mt][0] = Qsu[r0 * QSTU + wb + tig];
                        a[mt][1] = Qsu[(r0 + 8) * QSTU + wb + tig];
                        a[mt][2] = Qsu[r0 * QSTU + wb + 4 + tig];
                        a[mt][3] = Qsu[(r0 + 8) * QSTU + wb + 4 + tig];
                    }
                    #pragma unroll
                    for (int nt = 0; nt < 8; nt++) {
                        int cc = colbase + cb + nt * 8 + gid;
                        bf[nt][0] = __ldg(&pk32[(size_t)cc * 32 + wb + tig]);
                        bf[nt][1] = __ldg(&pk32[(size_t)cc * 32 + wb + 4 + tig]);
                    }
                    #pragma unroll
                    for (int mt = 0; mt < 2; mt++)
                        #pragma unroll
                        for (int nt = 0; nt < 8; nt++)
                            mma_f16(acc[mt][nt], a[mt], bf[nt]);
                }
                #pragma unroll
                for (int mt = 0; mt < 2; mt++) {
                    int r1 = wm + mt * 16 + gid;
                    #pragma unroll
                    for (int nt = 0; nt < 8; nt++) {
                        int ci = cb + nt * 8 + 2 * tig;
                        int jj;
                        jj = r1 - ci + 128;
                        if (jj >= 0 && jj < 128) Ss[r1 * SST + jj] += acc[mt][nt][0];
                        jj = r1 - ci + 127;
                        if (jj >= 0 && jj < 128) Ss[r1 * SST + jj] += acc[mt][nt][1];
                        int r2 = r1 + 8;
                        jj = r2 - ci + 128;
                        if (jj >= 0 && jj < 128) Ss[r2 * SST + jj] += acc[mt][nt][2];
                        jj = r2 - ci + 127;
                        if (jj >= 0 && jj < 128) Ss[r2 * SST + jj] += acc[mt][nt][3];
                    }
                }
            }
        }
        __syncthreads();

        // ---- P2C: K @ PQH_slice^T, scatter-add S[jj+col-128][jj] ----
        {
            const int wm = (warp & 3) * 32, wn2 = (warp >> 2) * 128;
            const int colbase = 256 - c0;
            #pragma unroll
            for (int half = 0; half < 2; half++) {
                const int cb = wn2 + half * 64;
                float acc[2][8][4];
                #pragma unroll
                for (int mt = 0; mt < 2; mt++)
                    #pragma unroll
                    for (int nt = 0; nt < 8; nt++)
                        #pragma unroll
                        for (int i = 0; i < 4; i++) acc[mt][nt][i] = 0.f;

                #pragma unroll
                for (int ks = 0; ks < 4; ks++) {
                    const int wb = ks * 8;
                    uint32_t a[2][4], bf[8][2];
                    #pragma unroll
                    for (int mt = 0; mt < 2; mt++) {
                        int r0 = wm + mt * 16 + gid;
                        a[mt][0] = Ksu[r0 * QSTU + wb + tig];
                        a[mt][1] = Ksu[(r0 + 8) * QSTU + wb + tig];
                        a[mt][2] = Ksu[r0 * QSTU + wb + 4 + tig];
                        a[mt][3] = Ksu[(r0 + 8) * QSTU + wb + 4 + tig];
                    }
                    #pragma unroll
                    for (int nt = 0; nt < 8; nt++) {
                        int cc = colbase + cb + nt * 8 + gid;
                        bf[nt][0] = __ldg(&pq32[(size_t)cc * 32 + wb + tig]);
                        bf[nt][1] = __ldg(&pq32[(size_t)cc * 32 + wb + 4 + tig]);
                    }
                    #pragma unroll
                    for (int mt = 0; mt < 2; mt++)
                        #pragma unroll
                        for (int nt = 0; nt < 8; nt++)
                            mma_f16(acc[mt][nt], a[mt], bf[nt]);
                }
                #pragma unroll
                for (int mt = 0; mt < 2; mt++) {
                    int r1 = wm + mt * 16 + gid;
                    #pragma unroll
                    for (int nt = 0; nt < 8; nt++) {
                        int ci = cb + nt * 8 + 2 * tig;
                        int q;
                        q = r1 + ci - 128;
                        if (q >= 0 && q < 128) Ss[q * SST + r1] += acc[mt][nt][0];
                        q = r1 + ci - 127;
                        if (q >= 0 && q < 128) Ss[q * SST + r1] += acc[mt][nt][1];
                        int r2 = r1 + 8;
                        q = r2 + ci - 128;
                        if (q >= 0 && q < 128) Ss[q * SST + r2] += acc[mt][nt][2];
                        q = r2 + ci - 127;
                        if (q >= 0 && q < 128) Ss[q * SST + r2] += acc[mt][nt][3];
                    }
                }
            }
        }
        __syncthreads();

        // ---- online softmax; P written as fp16 into Ph ----
        {
            const int r  = tid & 127;
            const int hh = tid >> 7;
            float* srow = Ss + r * SST + hh * 64;
            float mx = -1e30f;
            #pragma unroll 8
            for (int j = 0; j < 64; j++) mx = fmaxf(mx, srow[j]);
            pbuf[tid] = mx;
            __syncthreads();
            if (tid < 128) {
                float mb   = fmaxf(pbuf[tid], pbuf[tid + 128]) * scale;
                float mold = mrow[tid];
                float mnew = fmaxf(mold, mb);
                crow[tid]  = __expf(mold - mnew);
                mrow[tid]  = mnew;
            }
            __syncthreads();
            float mnew = mrow[r];
            float ssum = 0.f;
            uint32_t* prow = Phu + r * PSTU + hh * 32;
            #pragma unroll 8
            for (int j = 0; j < 64; j += 2) {
                float p0 = __expf(srow[j]     * scale - mnew);
                float p1 = __expf(srow[j + 1] * scale - mnew);
                ssum += p0 + p1;
                __half2 hp = __floats2half2_rn(p0, p1);
                prow[j >> 1] = *(uint32_t*)&hp;
            }
            pbuf[tid] = ssum;
            __syncthreads();
            if (tid < 128)
                lrow[tid] = lrow[tid] * crow[tid] + pbuf[tid] + pbuf[tid + 128];
            __syncthreads();
        }

        // ---- PV: ctx = ctx*corr + P(fp16) @ V(fp16), B via ldmatrix.trans ----
        {
            const int wm1 = warp * 16;
            float c1 = crow[wm1 + gid], c2 = crow[wm1 + gid + 8];
            #pragma unroll
            for (int nt = 0; nt < 8; nt++) {
                ctx[nt][0] *= c1; ctx[nt][1] *= c1;
                ctx[nt][2] *= c2; ctx[nt][3] *= c2;
            }
            const int r0 = wm1 + gid;
            #pragma unroll
            for (int ks = 0; ks < 8; ks++) {
                uint32_t a[4];
                a[0] = Phu[r0 * PSTU + ks * 8 + tig];
                a[1] = Phu[(r0 + 8) * PSTU + ks * 8 + tig];
                a[2] = Phu[r0 * PSTU + ks * 8 + 4 + tig];
                a[3] = Phu[(r0 + 8) * PSTU + ks * 8 + 4 + tig];
                // lane's V row for this kstep: k = 16*ks + vkb, col base vnb
                uint32_t vaddr = vsmem +
                    (uint32_t)((16 * ks + vkb) * (QSTU * 4)) + (uint32_t)(vnb * 2);
                #pragma unroll
                for (int ntp = 0; ntp < 4; ntp++) {
                    uint32_t b0, b1, b2, b3;
                    ldsm_x4_t(b0, b1, b2, b3, vaddr + ntp * 32);
                    uint32_t bA[2] = { b0, b1 };
                    uint32_t bB[2] = { b2, b3 };
                    mma_f16(ctx[2 * ntp],     a, bA);
                    mma_f16(ctx[2 * ntp + 1], a, bB);
                }
            }
        }
        __syncthreads();
    }

    // ---- write ctx (fp16 for out-proj input) ----
    {
        const int wm1 = warp * 16;
        float inv1 = 1.0f / lrow[wm1 + gid];
        float inv2 = 1.0f / lrow[wm1 + gid + 8];
        size_t row1 = qrow0 + wm1 + gid;
        size_t row2 = row1 + 8;
        #pragma unroll
        for (int nt = 0; nt < 8; nt++) {
            int col = nt * 8 + 2 * tig;
            *(__half2*)(CTH + row1 * H_ + hoff + col) =
                __floats2half2_rn(ctx[nt][0] * inv1, ctx[nt][1] * inv1);
            *(__half2*)(CTH + row2 * H_ + hoff + col) =
                __floats2half2_rn(ctx[nt][2] * inv2, ctx[nt][3] * inv2);
        }
    }
}

// ---------------- LayerNorm over H=768, one row per CTA ----------------------
__global__ void __launch_bounds__(256) ln_kernel(
    const float* __restrict__ X, const float* __restrict__ gam,
    const float* __restrict__ bet, float* __restrict__ out)
{
    const int row = blockIdx.x;
    const int t   = threadIdx.x;
    const float* x = X + (size_t)row * H_;
    float v0 = x[t], v1 = x[t + 256], v2 = x[t + 512];
    float s = v0 + v1 + v2;
    float q = v0 * v0 + v1 * v1 + v2 * v2;

    __shared__ float sh[64];
    #pragma unroll
    for (int o = 16; o > 0; o >>= 1) {
        s += __shfl_down_sync(0xffffffffu, s, o);
        q += __shfl_down_sync(0xffffffffu, q, o);
    }
    int w = t >> 5, lane = t & 31;
    if (lane == 0) { sh[w] = s; sh[32 + w] = q; }
    __syncthreads();
    if (t == 0) {
        float ts = 0.f, tq = 0.f;
        #pragma unroll
        for (int i = 0; i < 8; i++) { ts += sh[i]; tq += sh[32 + i]; }
        sh[0] = ts;
        sh[32] = tq;
    }
    __syncthreads();
    float mu  = sh[0] * (1.0f / 768.0f);
    float var = sh[32] * (1.0f / 768.0f) - mu * mu;
    float r   = rsqrtf(var + 1e-7f);

    float* o = out + (size_t)row * H_;
    o[t]       = (v0 - mu) * r * gam[t]       + bet[t];
    o[t + 256] = (v1 - mu) * r * gam[t + 256] + bet[t + 256];
    o[t + 512] = (v2 - mu) * r * gam[t + 512] + bet[t + 512];
}

// ---------------- launch ------------------------------------------------------
extern "C" void kernel_launch(void* const* d_in, const int* in_sizes, int n_in,
                              void* d_out, int out_size)
{
    const float* hidden = (const float*)d_in[0];
    const float* rel    = (const float*)d_in[1];
    const float* Wq = (const float*)d_in[2];  const float* bq = (const float*)d_in[3];
    const float* Wk = (const float*)d_in[4];  const float* bk = (const float*)d_in[5];
    const float* Wv = (const float*)d_in[6];  const float* bv = (const float*)d_in[7];
    const float* Wo = (const float*)d_in[8];  const float* bo = (const float*)d_in[9];
    const float* lns = (const float*)d_in[10];
    const float* lnb = (const float*)d_in[11];
    float* out = (float*)d_out;

    __half *HH, *RELH, *WTh, *Qh, *Kh, *Vh, *CTH, *PKH, *PQH;
    float *PK, *PQ, *XR;
    cudaGetSymbolAddress((void**)&HH,   g_HH);
    cudaGetSymbolAddress((void**)&RELH, g_RELH);
    cudaGetSymbolAddress((void**)&WTh,  g_WTh);
    cudaGetSymbolAddress((void**)&Qh,   g_Qh);
    cudaGetSymbolAddress((void**)&Kh,   g_Kh);
    cudaGetSymbolAddress((void**)&Vh,   g_Vh);
    cudaGetSymbolAddress((void**)&CTH,  g_CTH);
    cudaGetSymbolAddress((void**)&PK,   g_PK);
    cudaGetSymbolAddress((void**)&PQ,   g_PQ);
    cudaGetSymbolAddress((void**)&PKH,  g_PKH);
    cudaGetSymbolAddress((void**)&PQH,  g_PQH);
    cudaGetSymbolAddress((void**)&XR,   g_XR);

    __half* WThq = WTh;
    __half* WThk = WTh + (size_t)H_ * H_;
    __half* WThv = WTh + (size_t)2 * H_ * H_;
    __half* WTho = WTh + (size_t)3 * H_ * H_;

    const int M = B_ * S_;                       // 32768

    // conversions
    f2h_kernel<<<TOT_ / 1024, 256>>>(hidden, HH);
    f2h_kernel<<<(512 * H_) / 1024, 256>>>(rel, RELH);
    dim3 tg(24, 24), tb(32, 8);
    transpose768h<<<tg, tb>>>(Wq, WThq);
    transpose768h<<<tg, tb>>>(Wk, WThk);
    transpose768h<<<tg, tb>>>(Wv, WThv);
    transpose768h<<<tg, tb>>>(Wo, WTho);

    cudaFuncSetAttribute(fp16_gemm,
                         cudaFuncAttributeMaxDynamicSharedMemorySize, GSMEM);

    dim3 gBig(H_ / 128, M / 128);                // (6, 256)
    dim3 gPos(H_ / 128, 512 / 128);              // (6, 4)

    // QKV projections: all fp16 outputs
    fp16_gemm<<<gBig, 256, GSMEM>>>(HH, WThq, bq, nullptr, nullptr, Qh, M);
    fp16_gemm<<<gBig, 256, GSMEM>>>(HH, WThk, bk, nullptr, nullptr, Kh, M);
    fp16_gemm<<<gBig, 256, GSMEM>>>(HH, WThv, bv, nullptr, nullptr, Vh, M);

    // positional projections (fp32 out) + fp16 diff tables
    fp16_gemm<<<gPos, 256, GSMEM>>>(RELH, WThk, bk, nullptr, PK, nullptr, 512);
    fp16_gemm<<<gPos, 256, GSMEM>>>(RELH, WThq, bq, nullptr, PQ, nullptr, 512);
    build_pos_h<<<511, 768>>>(PK, PQ, PKH, PQH);

    // attention
    const int smem_attn =
        (128 * QSTU * 3 + 128 * PSTU) * 4 + (128 * SST + 3 * 128 + 256) * 4;
    cudaFuncSetAttribute(attn_mma,
                         cudaFuncAttributeMaxDynamicSharedMemorySize, smem_attn);
    attn_mma<<<dim3(NH_, NB_, B_), 256, smem_attn>>>(Qh, Kh, Vh, PKH, PQH, CTH);

    // output projection + residual, then layernorm
    fp16_gemm<<<gBig, 256, GSMEM>>>(CTH, WTho, bo, hidden, XR, nullptr, M);
    ln_kernel<<<M, 256>>>(XR, lns, lnb, out);
}

// round 10
// speedup vs baseline: 4.1995x; 1.0107x over previous
#include <cuda_runtime.h>
#include <cuda_fp16.h>
#include <math.h>
#include <stdint.h>

#define B_   4
#define S_   8192
#define H_   768
#define NH_  12
#define HD_  64
#define NB_  64
#define TOT_ (B_*S_*H_)

// attention smem strides
#define QSTU 36    // u32 stride for fp16 Q/K/V rows (32 u32 data + 4 pad)
#define PSTU 68    // u32 stride for fp16 P rows (64 u32 data + 4 pad)
#define SST  132   // fp32 score stride

// fp16 gemm config: BK=32 halves
#define GST   20                   // u32 stride per 32-half row (16 data + 4 pad)
#define GSTG  (128 * GST)          // u32 per stage per operand
#define GNSTG 3
#define GKT   24                   // 768 / 32
#define GSMEM (2 * GNSTG * GSTG * 4)   // 61440 B

// ---------------- scratch (device globals; no allocs allowed) ----------------
__device__ __half g_HH[TOT_];              // hidden fp16
__device__ __half g_RELH[512 * H_];        // rel fp16
__device__ __half g_WTh[4 * H_ * H_];      // transposed fp16 Wq,Wk,Wv,Wo
__device__ __half g_Qh[TOT_];
__device__ __half g_Kh[TOT_];
__device__ __half g_Vh[TOT_];
__device__ __half g_CTH[TOT_];
__device__ float  g_XR[TOT_];
__device__ float  g_PK[512 * H_];
__device__ float  g_PQ[512 * H_];
__device__ __half g_PKH[NH_ * 512 * HD_];  // [h][dd+1][d] fp16, row0 = pad
__device__ __half g_PQH[NH_ * 512 * HD_];

// ---------------- helpers -----------------------------------------------------
__device__ __forceinline__ void mma_f16(float* c, const uint32_t* a, const uint32_t* b) {
    asm volatile(
        "mma.sync.aligned.m16n8k16.row.col.f32.f16.f16.f32 "
        "{%0,%1,%2,%3},{%4,%5,%6,%7},{%8,%9},{%0,%1,%2,%3};\n"
        : "+f"(c[0]), "+f"(c[1]), "+f"(c[2]), "+f"(c[3])
        : "r"(a[0]), "r"(a[1]), "r"(a[2]), "r"(a[3]), "r"(b[0]), "r"(b[1]));
}

__device__ __forceinline__ void ldsm_x4(
    uint32_t& r0, uint32_t& r1, uint32_t& r2, uint32_t& r3, uint32_t addr)
{
    asm volatile(
        "ldmatrix.sync.aligned.m8n8.x4.shared.b16 {%0,%1,%2,%3}, [%4];"
        : "=r"(r0), "=r"(r1), "=r"(r2), "=r"(r3) : "r"(addr));
}

__device__ __forceinline__ void ldsm_x4_t(
    uint32_t& r0, uint32_t& r1, uint32_t& r2, uint32_t& r3, uint32_t addr)
{
    asm volatile(
        "ldmatrix.sync.aligned.m8n8.x4.trans.shared.b16 {%0,%1,%2,%3}, [%4];"
        : "=r"(r0), "=r"(r1), "=r"(r2), "=r"(r3) : "r"(addr));
}

__device__ __forceinline__ void cp16u(uint32_t* dst_smem, const void* src) {
    uint32_t d = (uint32_t)__cvta_generic_to_shared(dst_smem);
    asm volatile("cp.async.cg.shared.global [%0], [%1], 16;\n" :: "r"(d), "l"(src));
}
__device__ __forceinline__ void cp_commit() {
    asm volatile("cp.async.commit_group;\n");
}

// ---------------- conversion kernels -----------------------------------------
__global__ void __launch_bounds__(256) f2h_kernel(
    const float* __restrict__ x, __half* __restrict__ y)
{
    size_t i = ((size_t)blockIdx.x * 256 + threadIdx.x) * 4;
    float4 v = *(const float4*)(x + i);
    *(__half2*)(y + i)     = __floats2half2_rn(v.x, v.y);
    *(__half2*)(y + i + 2) = __floats2half2_rn(v.z, v.w);
}

// WT[n][k] = fp16(W[k][n])
__global__ void __launch_bounds__(256) transpose768h(
    const float* __restrict__ W, __half* __restrict__ WT)
{
    __shared__ float t[32][33];
    int x = blockIdx.x * 32 + threadIdx.x;
    int y = blockIdx.y * 32 + threadIdx.y;
    #pragma unroll
    for (int i = 0; i < 32; i += 8)
        t[threadIdx.y + i][threadIdx.x] = W[(size_t)(y + i) * H_ + x];
    __syncthreads();
    x = blockIdx.y * 32 + threadIdx.x;
    y = blockIdx.x * 32 + threadIdx.y;
    #pragma unroll
    for (int i = 0; i < 32; i += 8)
        WT[(size_t)(y + i) * H_ + x] = __float2half_rn(t[threadIdx.x][threadIdx.y + i]);
}

// ---------------- fp16 tensor-core GEMM, 3-stage cp.async, 2 CTAs/SM ---------
// fragment loads via ldmatrix (conflict-free: GST=20 u32 => 20r mod 32 distinct)
__global__ void __launch_bounds__(256, 2) fp16_gemm(
    const __half* __restrict__ A, const __half* __restrict__ Bw,
    const float* __restrict__ bias, const float* __restrict__ Rres,
    float* __restrict__ Cf, __half* __restrict__ Ch, int M)
{
    extern __shared__ uint32_t gsm[];
    uint32_t* As = gsm;
    uint32_t* Bs = gsm + GNSTG * GSTG;

    const int tid  = threadIdx.x;
    const int lane = tid & 31;
    const int warp = tid >> 5;
    const int wm   = (warp & 3) * 32;
    const int wn   = (warp >> 2) * 64;
    const int bm   = blockIdx.y * 128;
    const int bn   = blockIdx.x * 128;
    const int gid  = lane >> 2;
    const int tig  = lane & 3;
    const int lr16 = lane & 15;              // ldmatrix row-in-group
    const int lc4  = (lane >> 4) << 2;       // ldmatrix col offset (u32)

    const int fr = tid >> 1;                 // fill row
    const int fc = (tid & 1) << 1;

    const uint32_t as0 = (uint32_t)__cvta_generic_to_shared(As);
    const uint32_t bs0 = (uint32_t)__cvta_generic_to_shared(Bs);

    float acc[2][8][4];
    #pragma unroll
    for (int mt = 0; mt < 2; mt++)
        #pragma unroll
        for (int nt = 0; nt < 8; nt++)
            #pragma unroll
            for (int i = 0; i < 4; i++) acc[mt][nt][i] = 0.f;

    auto fill = [&](int s, int kt) {
        const int kb = kt * 32;
        const __half* Ab = A  + (size_t)(bm + fr) * H_ + kb;
        const __half* Bb = Bw + (size_t)(bn + fr) * H_ + kb;
        uint32_t* as = As + s * GSTG + fr * GST;
        uint32_t* bs = Bs + s * GSTG + fr * GST;
        cp16u(&as[fc * 4],       Ab + fc * 8);
        cp16u(&as[(fc + 1) * 4], Ab + (fc + 1) * 8);
        cp16u(&bs[fc * 4],       Bb + fc * 8);
        cp16u(&bs[(fc + 1) * 4], Bb + (fc + 1) * 8);
        cp_commit();
    };

    fill(0, 0);
    fill(1, 1);

    for (int kt = 0; kt < GKT; kt++) {
        if (kt + 1 < GKT) asm volatile("cp.async.wait_group 1;\n");
        else              asm volatile("cp.async.wait_group 0;\n");
        __syncthreads();

        const uint32_t asb = as0 + (uint32_t)((kt % GNSTG) * GSTG) * 4;
        const uint32_t bsb = bs0 + (uint32_t)((kt % GNSTG) * GSTG) * 4;

        #pragma unroll
        for (int ks = 0; ks < 2; ks++) {
            const int wb = ks * 8;
            uint32_t a[2][4], b[8][2];
            #pragma unroll
            for (int mt = 0; mt < 2; mt++)
                ldsm_x4(a[mt][0], a[mt][1], a[mt][2], a[mt][3],
                        asb + (uint32_t)(((wm + mt * 16 + lr16) * GST + wb + lc4) * 4));
            #pragma unroll
            for (int ntp = 0; ntp < 4; ntp++) {
                uint32_t r0, r1, r2, r3;
                ldsm_x4(r0, r1, r2, r3,
                        bsb + (uint32_t)(((wn + ntp * 16 + lr16) * GST + wb + lc4) * 4));
                b[2 * ntp][0]     = r0;
                b[2 * ntp + 1][0] = r1;
                b[2 * ntp][1]     = r2;
                b[2 * ntp + 1][1] = r3;
            }
            #pragma unroll
            for (int mt = 0; mt < 2; mt++)
                #pragma unroll
                for (int nt = 0; nt < 8; nt++)
                    mma_f16(acc[mt][nt], a[mt], b[nt]);
        }
        __syncthreads();

        if (kt + 2 < GKT) fill((kt + 2) % GNSTG, kt + 2);
    }

    #pragma unroll
    for (int mt = 0; mt < 2; mt++) {
        #pragma unroll
        for (int hi = 0; hi < 2; hi++) {
            size_t row = (size_t)bm + wm + mt * 16 + gid + hi * 8;
            #pragma unroll
            for (int nt = 0; nt < 8; nt++) {
                int col = bn + wn + nt * 8 + tig * 2;
                float v0 = acc[mt][nt][hi * 2 + 0] + bias[col];
                float v1 = acc[mt][nt][hi * 2 + 1] + bias[col + 1];
                if (Rres != nullptr) {
                    float2 rr = *(const float2*)(Rres + row * (size_t)H_ + col);
                    v0 += rr.x; v1 += rr.y;
                }
                if (Cf != nullptr)
                    *(float2*)(Cf + row * (size_t)H_ + col) = make_float2(v0, v1);
                else
                    *(__half2*)(Ch + row * (size_t)H_ + col) = __floats2half2_rn(v0, v1);
            }
        }
    }
}

// ---------------- bucketization + fp16 pos tables ----------------------------
__device__ __forceinline__ int bucket_idx_dev(int d)
{
    int ad = d < 0 ? -d : d;
    int v;
    if (ad <= 128) {
        v = d;
    } else {
        float t = logf((float)ad / 128.0f);
        t = t / 0.6892332713f;                   // fp32(ln(255/128))
        t = t * 127.0f;
        float lp = ceilf(t) + 128.0f;
        v = (int)(d < 0 ? -lp : lp);
    }
    v += 256;
    return v < 0 ? 0 : (v > 511 ? 511 : v);
}

__global__ void build_pos_h(const float* __restrict__ PK, const float* __restrict__ PQ,
                            __half* __restrict__ PKH, __half* __restrict__ PQH)
{
    int dd = blockIdx.x;                         // 0..510
    int t  = threadIdx.x;                        // 0..767
    int p  = bucket_idx_dev(dd - 383);
    int h  = t >> 6;
    int d  = t & 63;
    size_t dst = ((size_t)h * 512 + dd + 1) * HD_ + d;
    PKH[dst] = __float2half_rn(PK[(size_t)p * H_ + t]);
    PQH[dst] = __float2half_rn(PQ[(size_t)p * H_ + t]);
    if (dd == 0) {
        PKH[((size_t)h * 512) * HD_ + d] = __float2half_rn(0.f);
        PQH[((size_t)h * 512) * HD_ + d] = __float2half_rn(0.f);
    }
}

// ---------------- attention: full fp16 MMA, ldmatrix fragments ---------------
__global__ void __launch_bounds__(256, 1) attn_mma(
    const __half* __restrict__ Qh, const __half* __restrict__ Kh,
    const __half* __restrict__ Vh,
    const __half* __restrict__ PKH, const __half* __restrict__ PQH,
    __half* __restrict__ CTH)
{
    extern __shared__ char smc[];
    uint32_t* Qsu = (uint32_t*)smc;                       // 128*QSTU
    uint32_t* Ksu = Qsu + 128 * QSTU;                     // 128*QSTU
    uint32_t* Vsu = Ksu + 128 * QSTU;                     // 128*QSTU
    uint32_t* Phu = Vsu + 128 * QSTU;                     // 128*PSTU
    float* Ss   = (float*)(Phu + 128 * PSTU);             // 128*SST
    float* mrow = Ss + 128 * SST;                         // 128
    float* lrow = mrow + 128;
    float* crow = lrow + 128;
    float* pbuf = crow + 128;                             // 256

    const int h = blockIdx.x, n = blockIdx.y, b = blockIdx.z;
    const int tid  = threadIdx.x;
    const int lane = tid & 31;
    const int warp = tid >> 5;
    const int gid  = lane >> 2;
    const int tig  = lane & 3;
    const int lr16 = lane & 15;
    const int lc4  = (lane >> 4) << 2;
    const size_t qrow0 = (size_t)b * S_ + (size_t)n * 128;
    const size_t hoff  = (size_t)h * HD_;

    const uint32_t qbase = (uint32_t)__cvta_generic_to_shared(Qsu);
    const uint32_t kbase = (uint32_t)__cvta_generic_to_shared(Ksu);
    const uint32_t vbase = (uint32_t)__cvta_generic_to_shared(Vsu);
    const uint32_t pbase = (uint32_t)__cvta_generic_to_shared(Phu);

    // stage Q tile: 64 halves/row = 8 uint4/row
    for (int i = tid; i < 128 * 8; i += 256) {
        int r = i >> 3, c = i & 7;
        uint4 v = *(const uint4*)(Qh + (qrow0 + r) * H_ + hoff + c * 8);
        uint32_t* d = &Qsu[r * QSTU + c * 4];
        d[0] = v.x; d[1] = v.y; d[2] = v.z; d[3] = v.w;
    }
    if (tid < 128) { mrow[tid] = -1e30f; lrow[tid] = 0.f; }
    __syncthreads();

    float ctx[8][4];
    #pragma unroll
    for (int nt = 0; nt < 8; nt++)
        #pragma unroll
        for (int i = 0; i < 4; i++) ctx[nt][i] = 0.f;

    const uint32_t* pk32 = (const uint32_t*)PKH + (size_t)h * 512 * 32;
    const uint32_t* pq32 = (const uint32_t*)PQH + (size_t)h * 512 * 32;
    const float scale = 0.07216878364870323f;    // 1/sqrt(192)

    // ldmatrix.trans lane base for PV B-fragments
    const int lg  = lane >> 3;
    const int lr  = lane & 7;
    const int vkb = (lg & 1) * 8 + lr;
    const int vnb = (lg >> 1) * 8;

    for (int c = 0; c < 3; c++) {
        const int  c0  = c * 128;
        const long sk0 = (long)n * 128 - 128 + c0;

        // stage K and V (fp16), zero-pad outside sequence
        for (int i = tid; i < 128 * 8; i += 256) {
            int r = i >> 3, cc = i & 7;
            long s = sk0 + r;
            uint4 kv = make_uint4(0u, 0u, 0u, 0u);
            uint4 vv = make_uint4(0u, 0u, 0u, 0u);
            if (s >= 0 && s < S_) {
                size_t g = ((size_t)b * S_ + s) * H_ + hoff + cc * 8;
                kv = *(const uint4*)(Kh + g);
                vv = *(const uint4*)(Vh + g);
            }
            uint32_t* dk = &Ksu[r * QSTU + cc * 4];
            dk[0] = kv.x; dk[1] = kv.y; dk[2] = kv.z; dk[3] = kv.w;
            uint32_t* dv = &Vsu[r * QSTU + cc * 4];
            dv[0] = vv.x; dv[1] = vv.y; dv[2] = vv.z; dv[3] = vv.w;
        }
        __syncthreads();

        // ---- c2c: S = Q @ K^T (fp16, ldmatrix fragments) ----
        {
            const int wm = (warp & 3) * 32, wn = (warp >> 2) * 64;
            float acc[2][8][4];
            #pragma unroll
            for (int mt = 0; mt < 2; mt++)
                #pragma unroll
                for (int nt = 0; nt < 8; nt++)
                    #pragma unroll
                    for (int i = 0; i < 4; i++) acc[mt][nt][i] = 0.f;

            #pragma unroll
            for (int ks = 0; ks < 4; ks++) {
                const int wb = ks * 8;
                uint32_t a[2][4], bf[8][2];
                #pragma unroll
                for (int mt = 0; mt < 2; mt++)
                    ldsm_x4(a[mt][0], a[mt][1], a[mt][2], a[mt][3],
                            qbase + (uint32_t)(((wm + mt * 16 + lr16) * QSTU + wb + lc4) * 4));
                #pragma unroll
                for (int ntp = 0; ntp < 4; ntp++) {
                    uint32_t r0, r1, r2, r3;
                    ldsm_x4(r0, r1, r2, r3,
                            kbase + (uint32_t)(((wn + ntp * 16 + lr16) * QSTU + wb + lc4) * 4));
                    bf[2 * ntp][0]     = r0;
                    bf[2 * ntp + 1][0] = r1;
                    bf[2 * ntp][1]     = r2;
                    bf[2 * ntp + 1][1] = r3;
                }
                #pragma unroll
                for (int mt = 0; mt < 2; mt++)
                    #pragma unroll
                    for (int nt = 0; nt < 8; nt++)
                        mma_f16(acc[mt][nt], a[mt], bf[nt]);
            }
            #pragma unroll
            for (int mt = 0; mt < 2; mt++) {
                int r1 = wm + mt * 16 + gid;
                #pragma unroll
                for (int nt = 0; nt < 8; nt++) {
                    int cc = wn + nt * 8 + 2 * tig;
                    *(float2*)&Ss[r1 * SST + cc] =
                        make_float2(acc[mt][nt][0], acc[mt][nt][1]);
                    *(float2*)&Ss[(r1 + 8) * SST + cc] =
                        make_float2(acc[mt][nt][2], acc[mt][nt][3]);
                }
            }
        }
        __syncthreads();

        // ---- C2P: Q @ PKH_slice^T, scatter-add S[q][q-col+128] ----
        {
            const int wm = (warp & 3) * 32, wn2 = (warp >> 2) * 128;
            const int colbase = 256 - c0;
            #pragma unroll
            for (int half = 0; half < 2; half++) {
                const int cb = wn2 + half * 64;
                float acc[2][8][4];
                #pragma unroll
                for (int mt = 0; mt < 2; mt++)
                    #pragma unroll
                    for (int nt = 0; nt < 8; nt++)
                        #pragma unroll
                        for (int i = 0; i < 4; i++) acc[mt][nt][i] = 0.f;

                #pragma unroll
                for (int ks = 0; ks < 4; ks++) {
                    const int wb = ks * 8;
                    uint32_t a[2][4], bf[8][2];
                    #pragma unroll
                    for (int mt = 0; mt < 2; mt++)
                        ldsm_x4(a[mt][0], a[mt][1], a[mt][2], a[mt][3],
                                qbase + (uint32_t)(((wm + mt * 16 + lr16) * QSTU + wb + lc4) * 4));
                    #pragma unroll
                    for (int nt = 0; nt < 8; nt++) {
                        int cc = colbase + cb + nt * 8 + gid;
                        bf[nt][0] = __ldg(&pk32[(size_t)cc * 32 + wb + tig]);
                        bf[nt][1] = __ldg(&pk32[(size_t)cc * 32 + wb + 4 + tig]);
                    }
                    #pragma unroll
                    for (int mt = 0; mt < 2; mt++)
                        #pragma unroll
                        for (int nt = 0; nt < 8; nt++)
                            mma_f16(acc[mt][nt], a[mt], bf[nt]);
                }
                #pragma unroll
                for (int mt = 0; mt < 2; mt++) {
                    int r1 = wm + mt * 16 + gid;
                    #pragma unroll
                    for (int nt = 0; nt < 8; nt++) {
                        int ci = cb + nt * 8 + 2 * tig;
                        int jj;
                        jj = r1 - ci + 128;
                        if (jj >= 0 && jj < 128) Ss[r1 * SST + jj] += acc[mt][nt][0];
                        jj = r1 - ci + 127;
                        if (jj >= 0 && jj < 128) Ss[r1 * SST + jj] += acc[mt][nt][1];
                        int r2 = r1 + 8;
                        jj = r2 - ci + 128;
                        if (jj >= 0 && jj < 128) Ss[r2 * SST + jj] += acc[mt][nt][2];
                        jj = r2 - ci + 127;
                        if (jj >= 0 && jj < 128) Ss[r2 * SST + jj] += acc[mt][nt][3];
                    }
                }
            }
        }
        __syncthreads();

        // ---- P2C: K @ PQH_slice^T, scatter-add S[jj+col-128][jj] ----
        {
            const int wm = (warp & 3) * 32, wn2 = (warp >> 2) * 128;
            const int colbase = 256 - c0;
            #pragma unroll
            for (int half = 0; half < 2; half++) {
                const int cb = wn2 + half * 64;
                float acc[2][8][4];
                #pragma unroll
                for (int mt = 0; mt < 2; mt++)
                    #pragma unroll
                    for (int nt = 0; nt < 8; nt++)
                        #pragma unroll
                        for (int i = 0; i < 4; i++) acc[mt][nt][i] = 0.f;

                #pragma unroll
                for (int ks = 0; ks < 4; ks++) {
                    const int wb = ks * 8;
                    uint32_t a[2][4], bf[8][2];
                    #pragma unroll
                    for (int mt = 0; mt < 2; mt++)
                        ldsm_x4(a[mt][0], a[mt][1], a[mt][2], a[mt][3],
                                kbase + (uint32_t)(((wm + mt * 16 + lr16) * QSTU + wb + lc4) * 4));
                    #pragma unroll
                    for (int nt = 0; nt < 8; nt++) {
                        int cc = colbase + cb + nt * 8 + gid;
                        bf[nt][0] = __ldg(&pq32[(size_t)cc * 32 + wb + tig]);
                        bf[nt][1] = __ldg(&pq32[(size_t)cc * 32 + wb + 4 + tig]);
                    }
                    #pragma unroll
                    for (int mt = 0; mt < 2; mt++)
                        #pragma unroll
                        for (int nt = 0; nt < 8; nt++)
                            mma_f16(acc[mt][nt], a[mt], bf[nt]);
                }
                #pragma unroll
                for (int mt = 0; mt < 2; mt++) {
                    int r1 = wm + mt * 16 + gid;
                    #pragma unroll
                    for (int nt = 0; nt < 8; nt++) {
                        int ci = cb + nt * 8 + 2 * tig;
                        int q;
                        q = r1 + ci - 128;
                        if (q >= 0 && q < 128) Ss[q * SST + r1] += acc[mt][nt][0];
                        q = r1 + ci - 127;
                        if (q >= 0 && q < 128) Ss[q * SST + r1] += acc[mt][nt][1];
                        int r2 = r1 + 8;
                        q = r2 + ci - 128;
                        if (q >= 0 && q < 128) Ss[q * SST + r2] += acc[mt][nt][2];
                        q = r2 + ci - 127;
                        if (q >= 0 && q < 128) Ss[q * SST + r2] += acc[mt][nt][3];
                    }
                }
            }
        }
        __syncthreads();

        // ---- online softmax; P written as fp16 into Ph ----
        {
            const int r  = tid & 127;
            const int hh = tid >> 7;
            float* srow = Ss + r * SST + hh * 64;
            float mx = -1e30f;
            #pragma unroll 8
            for (int j = 0; j < 64; j++) mx = fmaxf(mx, srow[j]);
            pbuf[tid] = mx;
            __syncthreads();
            if (tid < 128) {
                float mb   = fmaxf(pbuf[tid], pbuf[tid + 128]) * scale;
                float mold = mrow[tid];
                float mnew = fmaxf(mold, mb);
                crow[tid]  = __expf(mold - mnew);
                mrow[tid]  = mnew;
            }
            __syncthreads();
            float mnew = mrow[r];
            float ssum = 0.f;
            uint32_t* prow = Phu + r * PSTU + hh * 32;
            #pragma unroll 8
            for (int j = 0; j < 64; j += 2) {
                float p0 = __expf(srow[j]     * scale - mnew);
                float p1 = __expf(srow[j + 1] * scale - mnew);
                ssum += p0 + p1;
                __half2 hp = __floats2half2_rn(p0, p1);
                prow[j >> 1] = *(uint32_t*)&hp;
            }
            pbuf[tid] = ssum;
            __syncthreads();
            if (tid < 128)
                lrow[tid] = lrow[tid] * crow[tid] + pbuf[tid] + pbuf[tid + 128];
            __syncthreads();
        }

        // ---- PV: ctx = ctx*corr + P(fp16) @ V(fp16) ----
        {
            const int wm1 = warp * 16;
            float c1 = crow[wm1 + gid], c2 = crow[wm1 + gid + 8];
            #pragma unroll
            for (int nt = 0; nt < 8; nt++) {
                ctx[nt][0] *= c1; ctx[nt][1] *= c1;
                ctx[nt][2] *= c2; ctx[nt][3] *= c2;
            }
            #pragma unroll
            for (int ks = 0; ks < 8; ks++) {
                uint32_t a[4];
                ldsm_x4(a[0], a[1], a[2], a[3],
                        pbase + (uint32_t)(((wm1 + lr16) * PSTU + ks * 8 + lc4) * 4));
                uint32_t vaddr = vbase +
                    (uint32_t)((16 * ks + vkb) * (QSTU * 4)) + (uint32_t)(vnb * 2);
                #pragma unroll
                for (int ntp = 0; ntp < 4; ntp++) {
                    uint32_t b0, b1, b2, b3;
                    ldsm_x4_t(b0, b1, b2, b3, vaddr + ntp * 32);
                    uint32_t bA[2] = { b0, b1 };
                    uint32_t bB[2] = { b2, b3 };
                    mma_f16(ctx[2 * ntp],     a, bA);
                    mma_f16(ctx[2 * ntp + 1], a, bB);
                }
            }
        }
        __syncthreads();
    }

    // ---- write ctx (fp16 for out-proj input) ----
    {
        const int wm1 = warp * 16;
        float inv1 = 1.0f / lrow[wm1 + gid];
        float inv2 = 1.0f / lrow[wm1 + gid + 8];
        size_t row1 = qrow0 + wm1 + gid;
        size_t row2 = row1 + 8;
        #pragma unroll
        for (int nt = 0; nt < 8; nt++) {
            int col = nt * 8 + 2 * tig;
            *(__half2*)(CTH + row1 * H_ + hoff + col) =
                __floats2half2_rn(ctx[nt][0] * inv1, ctx[nt][1] * inv1);
            *(__half2*)(CTH + row2 * H_ + hoff + col) =
                __floats2half2_rn(ctx[nt][2] * inv2, ctx[nt][3] * inv2);
        }
    }
}

// ---------------- LayerNorm over H=768, one row per CTA ----------------------
__global__ void __launch_bounds__(256) ln_kernel(
    const float* __restrict__ X, const float* __restrict__ gam,
    const float* __restrict__ bet, float* __restrict__ out)
{
    const int row = blockIdx.x;
    const int t   = threadIdx.x;
    const float* x = X + (size_t)row * H_;
    float v0 = x[t], v1 = x[t + 256], v2 = x[t + 512];
    float s = v0 + v1 + v2;
    float q = v0 * v0 + v1 * v1 + v2 * v2;

    __shared__ float sh[64];
    #pragma unroll
    for (int o = 16; o > 0; o >>= 1) {
        s += __shfl_down_sync(0xffffffffu, s, o);
        q += __shfl_down_sync(0xffffffffu, q, o);
    }
    int w = t >> 5, lane = t & 31;
    if (lane == 0) { sh[w] = s; sh[32 + w] = q; }
    __syncthreads();
    if (t == 0) {
        float ts = 0.f, tq = 0.f;
        #pragma unroll
        for (int i = 0; i < 8; i++) { ts += sh[i]; tq += sh[32 + i]; }
        sh[0] = ts;
        sh[32] = tq;
    }
    __syncthreads();
    float mu  = sh[0] * (1.0f / 768.0f);
    float var = sh[32] * (1.0f / 768.0f) - mu * mu;
    float r   = rsqrtf(var + 1e-7f);

    float* o = out + (size_t)row * H_;
    o[t]       = (v0 - mu) * r * gam[t]       + bet[t];
    o[t + 256] = (v1 - mu) * r * gam[t + 256] + bet[t + 256];
    o[t + 512] = (v2 - mu) * r * gam[t + 512] + bet[t + 512];
}

// ---------------- launch ------------------------------------------------------
extern "C" void kernel_launch(void* const* d_in, const int* in_sizes, int n_in,
                              void* d_out, int out_size)
{
    const float* hidden = (const float*)d_in[0];
    const float* rel    = (const float*)d_in[1];
    const float* Wq = (const float*)d_in[2];  const float* bq = (const float*)d_in[3];
    const float* Wk = (const float*)d_in[4];  const float* bk = (const float*)d_in[5];
    const float* Wv = (const float*)d_in[6];  const float* bv = (const float*)d_in[7];
    const float* Wo = (const float*)d_in[8];  const float* bo = (const float*)d_in[9];
    const float* lns = (const float*)d_in[10];
    const float* lnb = (const float*)d_in[11];
    float* out = (float*)d_out;

    __half *HH, *RELH, *WTh, *Qh, *Kh, *Vh, *CTH, *PKH, *PQH;
    float *PK, *PQ, *XR;
    cudaGetSymbolAddress((void**)&HH,   g_HH);
    cudaGetSymbolAddress((void**)&RELH, g_RELH);
    cudaGetSymbolAddress((void**)&WTh,  g_WTh);
    cudaGetSymbolAddress((void**)&Qh,   g_Qh);
    cudaGetSymbolAddress((void**)&Kh,   g_Kh);
    cudaGetSymbolAddress((void**)&Vh,   g_Vh);
    cudaGetSymbolAddress((void**)&CTH,  g_CTH);
    cudaGetSymbolAddress((void**)&PK,   g_PK);
    cudaGetSymbolAddress((void**)&PQ,   g_PQ);
    cudaGetSymbolAddress((void**)&PKH,  g_PKH);
    cudaGetSymbolAddress((void**)&PQH,  g_PQH);
    cudaGetSymbolAddress((void**)&XR,   g_XR);

    __half* WThq = WTh;
    __half* WThk = WTh + (size_t)H_ * H_;
    __half* WThv = WTh + (size_t)2 * H_ * H_;
    __half* WTho = WTh + (size_t)3 * H_ * H_;

    const int M = B_ * S_;                       // 32768

    // conversions
    f2h_kernel<<<TOT_ / 1024, 256>>>(hidden, HH);
    f2h_kernel<<<(512 * H_) / 1024, 256>>>(rel, RELH);
    dim3 tg(24, 24), tb(32, 8);
    transpose768h<<<tg, tb>>>(Wq, WThq);
    transpose768h<<<tg, tb>>>(Wk, WThk);
    transpose768h<<<tg, tb>>>(Wv, WThv);
    transpose768h<<<tg, tb>>>(Wo, WTho);

    cudaFuncSetAttribute(fp16_gemm,
                         cudaFuncAttributeMaxDynamicSharedMemorySize, GSMEM);

    dim3 gBig(H_ / 128, M / 128);                // (6, 256)
    dim3 gPos(H_ / 128, 512 / 128);              // (6, 4)

    // QKV projections: all fp16 outputs
    fp16_gemm<<<gBig, 256, GSMEM>>>(HH, WThq, bq, nullptr, nullptr, Qh, M);
    fp16_gemm<<<gBig, 256, GSMEM>>>(HH, WThk, bk, nullptr, nullptr, Kh, M);
    fp16_gemm<<<gBig, 256, GSMEM>>>(HH, WThv, bv, nullptr, nullptr, Vh, M);

    // positional projections (fp32 out) + fp16 diff tables
    fp16_gemm<<<gPos, 256, GSMEM>>>(RELH, WThk, bk, nullptr, PK, nullptr, 512);
    fp16_gemm<<<gPos, 256, GSMEM>>>(RELH, WThq, bq, nullptr, PQ, nullptr, 512);
    build_pos_h<<<511, 768>>>(PK, PQ, PKH, PQH);

    // attention
    const int smem_attn =
        (128 * QSTU * 3 + 128 * PSTU) * 4 + (128 * SST + 3 * 128 + 256) * 4;
    cudaFuncSetAttribute(attn_mma,
                         cudaFuncAttributeMaxDynamicSharedMemorySize, smem_attn);
    attn_mma<<<dim3(NH_, NB_, B_), 256, smem_attn>>>(Qh, Kh, Vh, PKH, PQH, CTH);

    // output projection + residual, then layernorm
    fp16_gemm<<<gBig, 256, GSMEM>>>(CTH, WTho, bo, hidden, XR, nullptr, M);
    ln_kernel<<<M, 256>>>(XR, lns, lnb, out);
}

// round 12
// speedup vs baseline: 4.4216x; 1.0529x over previous
#include <cuda_runtime.h>
#include <cuda_fp16.h>
#include <math.h>
#include <stdint.h>

#define B_   4
#define S_   8192
#define H_   768
#define NH_  12
#define HD_  64
#define NB_  64
#define TOT_ (B_*S_*H_)

// attention smem strides
#define QSTU 36    // u32 stride for fp16 Q/K/V rows (32 u32 data + 4 pad)
#define PSTU 68    // u32 stride for fp16 P rows (64 u32 data + 4 pad)
#define SST  132   // fp32 score stride (even: float2 stores stay 8B-aligned)

// fp16 gemm config: BK=32 halves
#define GST   20                   // u32 stride per 32-half row
#define GSTG  (128 * GST)
#define GNSTG 3
#define GKT   24                   // 768 / 32
#define GSMEM (2 * GNSTG * GSTG * 4)   // 61440 B

// ---------------- scratch (device globals; no allocs allowed) ----------------
__device__ __half g_HH[TOT_];
__device__ __half g_RELH[512 * H_];
__device__ __half g_WTh[4 * H_ * H_];
__device__ __half g_Qh[TOT_];
__device__ __half g_Kh[TOT_];
__device__ __half g_Vh[TOT_];
__device__ __half g_CTH[TOT_];
__device__ float  g_XR[TOT_];
__device__ float  g_PK[512 * H_];
__device__ float  g_PQ[512 * H_];
__device__ __half g_PKH[NH_ * 512 * HD_];
__device__ __half g_PQH[NH_ * 512 * HD_];

// ---------------- helpers -----------------------------------------------------
__device__ __forceinline__ void mma_f16(float* c, const uint32_t* a, const uint32_t* b) {
    asm volatile(
        "mma.sync.aligned.m16n8k16.row.col.f32.f16.f16.f32 "
        "{%0,%1,%2,%3},{%4,%5,%6,%7},{%8,%9},{%0,%1,%2,%3};\n"
        : "+f"(c[0]), "+f"(c[1]), "+f"(c[2]), "+f"(c[3])
        : "r"(a[0]), "r"(a[1]), "r"(a[2]), "r"(a[3]), "r"(b[0]), "r"(b[1]));
}

__device__ __forceinline__ void ldsm_x4(
    uint32_t& r0, uint32_t& r1, uint32_t& r2, uint32_t& r3, uint32_t addr)
{
    asm volatile(
        "ldmatrix.sync.aligned.m8n8.x4.shared.b16 {%0,%1,%2,%3}, [%4];"
        : "=r"(r0), "=r"(r1), "=r"(r2), "=r"(r3) : "r"(addr));
}

__device__ __forceinline__ void ldsm_x4_t(
    uint32_t& r0, uint32_t& r1, uint32_t& r2, uint32_t& r3, uint32_t addr)
{
    asm volatile(
        "ldmatrix.sync.aligned.m8n8.x4.trans.shared.b16 {%0,%1,%2,%3}, [%4];"
        : "=r"(r0), "=r"(r1), "=r"(r2), "=r"(r3) : "r"(addr));
}

__device__ __forceinline__ void cp16u(uint32_t* dst_smem, const void* src) {
    uint32_t d = (uint32_t)__cvta_generic_to_shared(dst_smem);
    asm volatile("cp.async.cg.shared.global [%0], [%1], 16;\n" :: "r"(d), "l"(src));
}
__device__ __forceinline__ void cp_commit() {
    asm volatile("cp.async.commit_group;\n");
}

__device__ __forceinline__ uint32_t ex2_f16x2(uint32_t x) {
    uint32_t r;
    asm volatile("ex2.approx.f16x2 %0, %1;" : "=r"(r) : "r"(x));
    return r;
}

// ---------------- conversion kernels -----------------------------------------
__global__ void __launch_bounds__(256) f2h_kernel(
    const float* __restrict__ x, __half* __restrict__ y)
{
    size_t i = ((size_t)blockIdx.x * 256 + threadIdx.x) * 4;
    float4 v = *(const float4*)(x + i);
    *(__half2*)(y + i)     = __floats2half2_rn(v.x, v.y);
    *(__half2*)(y + i + 2) = __floats2half2_rn(v.z, v.w);
}

// 4 weights transposed in one launch: WT[z][n][k] = fp16(W[z][k][n])
__global__ void __launch_bounds__(256) transpose768h4(
    const float* __restrict__ W0, const float* __restrict__ W1,
    const float* __restrict__ W2, const float* __restrict__ W3,
    __half* __restrict__ WT)
{
    __shared__ float t[32][33];
    const float* W = (blockIdx.z == 0) ? W0 : (blockIdx.z == 1) ? W1
                   : (blockIdx.z == 2) ? W2 : W3;
    __half* WTz = WT + (size_t)blockIdx.z * H_ * H_;
    int x = blockIdx.x * 32 + threadIdx.x;
    int y = blockIdx.y * 32 + threadIdx.y;
    #pragma unroll
    for (int i = 0; i < 32; i += 8)
        t[threadIdx.y + i][threadIdx.x] = W[(size_t)(y + i) * H_ + x];
    __syncthreads();
    x = blockIdx.y * 32 + threadIdx.x;
    y = blockIdx.x * 32 + threadIdx.y;
    #pragma unroll
    for (int i = 0; i < 32; i += 8)
        WTz[(size_t)(y + i) * H_ + x] = __float2half_rn(t[threadIdx.x][threadIdx.y + i]);
}

// ---------------- shared GEMM body: 3-stage cp.async, single sync/iter -------
__device__ __forceinline__ void gemm_body(
    const __half* __restrict__ A, const __half* __restrict__ Bw,
    const float* __restrict__ bias, const float* __restrict__ Rres,
    float* __restrict__ Cf, __half* __restrict__ Ch,
    int bm, int bn, uint32_t* gsm)
{
    uint32_t* As = gsm;
    uint32_t* Bs = gsm + GNSTG * GSTG;

    const int tid  = threadIdx.x;
    const int lane = tid & 31;
    const int warp = tid >> 5;
    const int wm   = (warp & 3) * 32;
    const int wn   = (warp >> 2) * 64;
    const int gid  = lane >> 2;
    const int tig  = lane & 3;
    const int lr16 = lane & 15;
    const int lc4  = (lane >> 4) << 2;

    const int fr = tid >> 1;
    const int fc = (tid & 1) << 1;

    const uint32_t as0 = (uint32_t)__cvta_generic_to_shared(As);
    const uint32_t bs0 = (uint32_t)__cvta_generic_to_shared(Bs);

    float acc[2][8][4];
    #pragma unroll
    for (int mt = 0; mt < 2; mt++)
        #pragma unroll
        for (int nt = 0; nt < 8; nt++)
            #pragma unroll
            for (int i = 0; i < 4; i++) acc[mt][nt][i] = 0.f;

    auto fill = [&](int s, int kt) {
        const int kb = kt * 32;
        const __half* Ab = A  + (size_t)(bm + fr) * H_ + kb;
        const __half* Bb = Bw + (size_t)(bn + fr) * H_ + kb;
        uint32_t* as = As + s * GSTG + fr * GST;
        uint32_t* bs = Bs + s * GSTG + fr * GST;
        cp16u(&as[fc * 4],       Ab + fc * 8);
        cp16u(&as[(fc + 1) * 4], Ab + (fc + 1) * 8);
        cp16u(&bs[fc * 4],       Bb + fc * 8);
        cp16u(&bs[(fc + 1) * 4], Bb + (fc + 1) * 8);
        cp_commit();
    };

    fill(0, 0);
    fill(1, 1);

    for (int kt = 0; kt < GKT; kt++) {
        if (kt < GKT - 1) asm volatile("cp.async.wait_group 1;\n");
        else              asm volatile("cp.async.wait_group 0;\n");
        __syncthreads();

        const uint32_t asb = as0 + (uint32_t)((kt % GNSTG) * GSTG) * 4;
        const uint32_t bsb = bs0 + (uint32_t)((kt % GNSTG) * GSTG) * 4;

        #pragma unroll
        for (int ks = 0; ks < 2; ks++) {
            const int wb = ks * 8;
            uint32_t a[2][4], b[8][2];
            #pragma unroll
            for (int mt = 0; mt < 2; mt++)
                ldsm_x4(a[mt][0], a[mt][1], a[mt][2], a[mt][3],
                        asb + (uint32_t)(((wm + mt * 16 + lr16) * GST + wb + lc4) * 4));
            #pragma unroll
            for (int ntp = 0; ntp < 4; ntp++) {
                uint32_t r0, r1, r2, r3;
                ldsm_x4(r0, r1, r2, r3,
                        bsb + (uint32_t)(((wn + ntp * 16 + lr16) * GST + wb + lc4) * 4));
                b[2 * ntp][0]     = r0;
                b[2 * ntp + 1][0] = r1;
                b[2 * ntp][1]     = r2;
                b[2 * ntp + 1][1] = r3;
            }
            #pragma unroll
            for (int mt = 0; mt < 2; mt++)
                #pragma unroll
                for (int nt = 0; nt < 8; nt++)
                    mma_f16(acc[mt][nt], a[mt], b[nt]);
        }
        // fill stage freed by compute(kt-1); safe after this iteration's sync
        if (kt + 2 < GKT) fill((kt + 2) % GNSTG, kt + 2);
    }

    #pragma unroll
    for (int mt = 0; mt < 2; mt++) {
        #pragma unroll
        for (int hi = 0; hi < 2; hi++) {
            size_t row = (size_t)bm + wm + mt * 16 + gid + hi * 8;
            #pragma unroll
            for (int nt = 0; nt < 8; nt++) {
                int col = bn + wn + nt * 8 + tig * 2;
                float v0 = acc[mt][nt][hi * 2 + 0] + bias[col];
                float v1 = acc[mt][nt][hi * 2 + 1] + bias[col + 1];
                if (Rres != nullptr) {
                    float2 rr = *(const float2*)(Rres + row * (size_t)H_ + col);
                    v0 += rr.x; v1 += rr.y;
                }
                if (Cf != nullptr)
                    *(float2*)(Cf + row * (size_t)H_ + col) = make_float2(v0, v1);
                else
                    *(__half2*)(Ch + row * (size_t)H_ + col) = __floats2half2_rn(v0, v1);
            }
        }
    }
}

// QKV in one launch: blockIdx.x/6 selects {Q,K,V}
__global__ void __launch_bounds__(256, 2) qkv_gemm(
    const __half* __restrict__ A, const __half* __restrict__ WT,
    const float* __restrict__ bq, const float* __restrict__ bk,
    const float* __restrict__ bv,
    __half* __restrict__ Oq, __half* __restrict__ Ok, __half* __restrict__ Ov)
{
    extern __shared__ uint32_t gsm[];
    const int which = blockIdx.x / 6;
    const int bn = (blockIdx.x % 6) * 128;
    const int bm = blockIdx.y * 128;
    const __half* Bw = WT + (size_t)which * H_ * H_;
    const float* bias = (which == 0) ? bq : (which == 1) ? bk : bv;
    __half* Ch = (which == 0) ? Oq : (which == 1) ? Ok : Ov;
    gemm_body(A, Bw, bias, nullptr, nullptr, Ch, bm, bn, gsm);
}

// both pos projections in one launch: blockIdx.x/6 selects {PK(Wk), PQ(Wq)}
__global__ void __launch_bounds__(256, 2) pos_gemm(
    const __half* __restrict__ A, const __half* __restrict__ WT,
    const float* __restrict__ bq, const float* __restrict__ bk,
    float* __restrict__ Opk, float* __restrict__ Opq)
{
    extern __shared__ uint32_t gsm[];
    const int which = blockIdx.x / 6;
    const int bn = (blockIdx.x % 6) * 128;
    const int bm = blockIdx.y * 128;
    const __half* Bw = WT + (size_t)(which == 0 ? 1 : 0) * H_ * H_; // Wk else Wq
    const float* bias = (which == 0) ? bk : bq;
    float* Cf = (which == 0) ? Opk : Opq;
    gemm_body(A, Bw, bias, nullptr, Cf, nullptr, bm, bn, gsm);
}

// out-proj with residual, fp32 out
__global__ void __launch_bounds__(256, 2) out_gemm(
    const __half* __restrict__ A, const __half* __restrict__ WT,
    const float* __restrict__ bias, const float* __restrict__ Rres,
    float* __restrict__ Cf)
{
    extern __shared__ uint32_t gsm[];
    const int bn = blockIdx.x * 128;
    const int bm = blockIdx.y * 128;
    gemm_body(A, WT, bias, Rres, Cf, nullptr, bm, bn, gsm);
}

// ---------------- bucketization + fp16 pos tables ----------------------------
__device__ __forceinline__ int bucket_idx_dev(int d)
{
    int ad = d < 0 ? -d : d;
    int v;
    if (ad <= 128) {
        v = d;
    } else {
        float t = logf((float)ad / 128.0f);
        t = t / 0.6892332713f;                   // fp32(ln(255/128))
        t = t * 127.0f;
        float lp = ceilf(t) + 128.0f;
        v = (int)(d < 0 ? -lp : lp);
    }
    v += 256;
    return v < 0 ? 0 : (v > 511 ? 511 : v);
}

__global__ void build_pos_h(const float* __restrict__ PK, const float* __restrict__ PQ,
                            __half* __restrict__ PKH, __half* __restrict__ PQH)
{
    int dd = blockIdx.x;                         // 0..510
    int t  = threadIdx.x;                        // 0..767
    int p  = bucket_idx_dev(dd - 383);
    int h  = t >> 6;
    int d  = t & 63;
    size_t dst = ((size_t)h * 512 + dd + 1) * HD_ + d;
    PKH[dst] = __float2half_rn(PK[(size_t)p * H_ + t]);
    PQH[dst] = __float2half_rn(PQ[(size_t)p * H_ + t]);
    if (dd == 0) {
        PKH[((size_t)h * 512) * HD_ + d] = __float2half_rn(0.f);
        PQH[((size_t)h * 512) * HD_ + d] = __float2half_rn(0.f);
    }
}

// ---------------- attention: fp16 MMA, shuffle softmax, ex2.f16x2 ------------
__global__ void __launch_bounds__(256, 1) attn_mma(
    const __half* __restrict__ Qh, const __half* __restrict__ Kh,
    const __half* __restrict__ Vh,
    const __half* __restrict__ PKH, const __half* __restrict__ PQH,
    __half* __restrict__ CTH)
{
    extern __shared__ char smc[];
    uint32_t* Qsu = (uint32_t*)smc;                       // 128*QSTU
    uint32_t* Ksu = Qsu + 128 * QSTU;
    uint32_t* Vsu = Ksu + 128 * QSTU;
    uint32_t* Phu = Vsu + 128 * QSTU;                     // 128*PSTU
    float* Ss   = (float*)(Phu + 128 * PSTU);             // 128*SST
    float* mrow = Ss + 128 * SST;                         // 128
    float* lrow = mrow + 128;
    float* crow = lrow + 128;

    const int h = blockIdx.x, n = blockIdx.y, b = blockIdx.z;
    const int tid  = threadIdx.x;
    const int lane = tid & 31;
    const int warp = tid >> 5;
    const int gid  = lane >> 2;
    const int tig  = lane & 3;
    const int lr16 = lane & 15;
    const int lc4  = (lane >> 4) << 2;
    const size_t qrow0 = (size_t)b * S_ + (size_t)n * 128;
    const size_t hoff  = (size_t)h * HD_;

    const uint32_t qbase = (uint32_t)__cvta_generic_to_shared(Qsu);
    const uint32_t kbase = (uint32_t)__cvta_generic_to_shared(Ksu);
    const uint32_t vbase = (uint32_t)__cvta_generic_to_shared(Vsu);
    const uint32_t pbase = (uint32_t)__cvta_generic_to_shared(Phu);

    for (int i = tid; i < 128 * 8; i += 256) {
        int r = i >> 3, c = i & 7;
        uint4 v = *(const uint4*)(Qh + (qrow0 + r) * H_ + hoff + c * 8);
        uint32_t* d = &Qsu[r * QSTU + c * 4];
        d[0] = v.x; d[1] = v.y; d[2] = v.z; d[3] = v.w;
    }
    if (tid < 128) { mrow[tid] = -1e30f; lrow[tid] = 0.f; }
    __syncthreads();

    float ctx[8][4];
    #pragma unroll
    for (int nt = 0; nt < 8; nt++)
        #pragma unroll
        for (int i = 0; i < 4; i++) ctx[nt][i] = 0.f;

    const uint32_t* pk32 = (const uint32_t*)PKH + (size_t)h * 512 * 32;
    const uint32_t* pq32 = (const uint32_t*)PQH + (size_t)h * 512 * 32;
    const float scale = 0.07216878364870323f;    // 1/sqrt(192)
    const float L2E   = 1.4426950408889634f;

    const int lg  = lane >> 3;
    const int lr  = lane & 7;
    const int vkb = (lg & 1) * 8 + lr;
    const int vnb = (lg >> 1) * 8;

    for (int c = 0; c < 3; c++) {
        const int  c0  = c * 128;
        const long sk0 = (long)n * 128 - 128 + c0;

        for (int i = tid; i < 128 * 8; i += 256) {
            int r = i >> 3, cc = i & 7;
            long s = sk0 + r;
            uint4 kv = make_uint4(0u, 0u, 0u, 0u);
            uint4 vv = make_uint4(0u, 0u, 0u, 0u);
            if (s >= 0 && s < S_) {
                size_t g = ((size_t)b * S_ + s) * H_ + hoff + cc * 8;
                kv = *(const uint4*)(Kh + g);
                vv = *(const uint4*)(Vh + g);
            }
            uint32_t* dk = &Ksu[r * QSTU + cc * 4];
            dk[0] = kv.x; dk[1] = kv.y; dk[2] = kv.z; dk[3] = kv.w;
            uint32_t* dv = &Vsu[r * QSTU + cc * 4];
            dv[0] = vv.x; dv[1] = vv.y; dv[2] = vv.z; dv[3] = vv.w;
        }
        __syncthreads();

        // ---- c2c ----
        {
            const int wm = (warp & 3) * 32, wn = (warp >> 2) * 64;
            float acc[2][8][4];
            #pragma unroll
            for (int mt = 0; mt < 2; mt++)
                #pragma unroll
                for (int nt = 0; nt < 8; nt++)
                    #pragma unroll
                    for (int i = 0; i < 4; i++) acc[mt][nt][i] = 0.f;

            #pragma unroll
            for (int ks = 0; ks < 4; ks++) {
                const int wb = ks * 8;
                uint32_t a[2][4], bf[8][2];
                #pragma unroll
                for (int mt = 0; mt < 2; mt++)
                    ldsm_x4(a[mt][0], a[mt][1], a[mt][2], a[mt][3],
                            qbase + (uint32_t)(((wm + mt * 16 + lr16) * QSTU + wb + lc4) * 4));
                #pragma unroll
                for (int ntp = 0; ntp < 4; ntp++) {
                    uint32_t r0, r1, r2, r3;
                    ldsm_x4(r0, r1, r2, r3,
                            kbase + (uint32_t)(((wn + ntp * 16 + lr16) * QSTU + wb + lc4) * 4));
                    bf[2 * ntp][0]     = r0;
                    bf[2 * ntp + 1][0] = r1;
                    bf[2 * ntp][1]     = r2;
                    bf[2 * ntp + 1][1] = r3;
                }
                #pragma unroll
                for (int mt = 0; mt < 2; mt++)
                    #pragma unroll
                    for (int nt = 0; nt < 8; nt++)
                        mma_f16(acc[mt][nt], a[mt], bf[nt]);
            }
            #pragma unroll
            for (int mt = 0; mt < 2; mt++) {
                int r1 = wm + mt * 16 + gid;
                #pragma unroll
                for (int nt = 0; nt < 8; nt++) {
                    int cc = wn + nt * 8 + 2 * tig;
                    *(float2*)&Ss[r1 * SST + cc] =
                        make_float2(acc[mt][nt][0], acc[mt][nt][1]);
                    *(float2*)&Ss[(r1 + 8) * SST + cc] =
                        make_float2(acc[mt][nt][2], acc[mt][nt][3]);
                }
            }
        }
        __syncthreads();

        // ---- C2P ----
        {
            const int wm = (warp & 3) * 32, wn2 = (warp >> 2) * 128;
            const int colbase = 256 - c0;
            #pragma unroll
            for (int half = 0; half < 2; half++) {
                const int cb = wn2 + half * 64;
                float acc[2][8][4];
                #pragma unroll
                for (int mt = 0; mt < 2; mt++)
                    #pragma unroll
                    for (int nt = 0; nt < 8; nt++)
                        #pragma unroll
                        for (int i = 0; i < 4; i++) acc[mt][nt][i] = 0.f;

                #pragma unroll
                for (int ks = 0; ks < 4; ks++) {
                    const int wb = ks * 8;
                    uint32_t a[2][4], bf[8][2];
                    #pragma unroll
                    for (int mt = 0; mt < 2; mt++)
                        ldsm_x4(a[mt][0], a[mt][1], a[mt][2], a[mt][3],
                                qbase + (uint32_t)(((wm + mt * 16 + lr16) * QSTU + wb + lc4) * 4));
                    #pragma unroll
                    for (int nt = 0; nt < 8; nt++) {
                        int cc = colbase + cb + nt * 8 + gid;
                        bf[nt][0] = __ldg(&pk32[(size_t)cc * 32 + wb + tig]);
                        bf[nt][1] = __ldg(&pk32[(size_t)cc * 32 + wb + 4 + tig]);
                    }
                    #pragma unroll
                    for (int mt = 0; mt < 2; mt++)
                        #pragma unroll
                        for (int nt = 0; nt < 8; nt++)
                            mma_f16(acc[mt][nt], a[mt], bf[nt]);
                }
                #pragma unroll
                for (int mt = 0; mt < 2; mt++) {
                    int r1 = wm + mt * 16 + gid;
                    #pragma unroll
                    for (int nt = 0; nt < 8; nt++) {
                        int ci = cb + nt * 8 + 2 * tig;
                        int jj;
                        jj = r1 - ci + 128;
                        if (jj >= 0 && jj < 128) Ss[r1 * SST + jj] += acc[mt][nt][0];
                        jj = r1 - ci + 127;
                        if (jj >= 0 && jj < 128) Ss[r1 * SST + jj] += acc[mt][nt][1];
                        int r2 = r1 + 8;
                        jj = r2 - ci + 128;
                        if (jj >= 0 && jj < 128) Ss[r2 * SST + jj] += acc[mt][nt][2];
                        jj = r2 - ci + 127;
                        if (jj >= 0 && jj < 128) Ss[r2 * SST + jj] += acc[mt][nt][3];
                    }
                }
            }
        }
        __syncthreads();

        // ---- P2C ----
        {
            const int wm = (warp & 3) * 32, wn2 = (warp >> 2) * 128;
            const int colbase = 256 - c0;
            #pragma unroll
            for (int half = 0; half < 2; half++) {
                const int cb = wn2 + half * 64;
                float acc[2][8][4];
                #pragma unroll
                for (int mt = 0; mt < 2; mt++)
                    #pragma unroll
                    for (int nt = 0; nt < 8; nt++)
                        #pragma unroll
                        for (int i = 0; i < 4; i++) acc[mt][nt][i] = 0.f;

                #pragma unroll
                for (int ks = 0; ks < 4; ks++) {
                    const int wb = ks * 8;
                    uint32_t a[2][4], bf[8][2];
                    #pragma unroll
                    for (int mt = 0; mt < 2; mt++)
                        ldsm_x4(a[mt][0], a[mt][1], a[mt][2], a[mt][3],
                                kbase + (uint32_t)(((wm + mt * 16 + lr16) * QSTU + wb + lc4) * 4));
                    #pragma unroll
                    for (int nt = 0; nt < 8; nt++) {
                        int cc = colbase + cb + nt * 8 + gid;
                        bf[nt][0] = __ldg(&pq32[(size_t)cc * 32 + wb + tig]);
                        bf[nt][1] = __ldg(&pq32[(size_t)cc * 32 + wb + 4 + tig]);
                    }
                    #pragma unroll
                    for (int mt = 0; mt < 2; mt++)
                        #pragma unroll
                        for (int nt = 0; nt < 8; nt++)
                            mma_f16(acc[mt][nt], a[mt], bf[nt]);
                }
                #pragma unroll
                for (int mt = 0; mt < 2; mt++) {
                    int r1 = wm + mt * 16 + gid;
                    #pragma unroll
                    for (int nt = 0; nt < 8; nt++) {
                        int ci = cb + nt * 8 + 2 * tig;
                        int q;
                        q = r1 + ci - 128;
                        if (q >= 0 && q < 128) Ss[q * SST + r1] += acc[mt][nt][0];
                        q = r1 + ci - 127;
                        if (q >= 0 && q < 128) Ss[q * SST + r1] += acc[mt][nt][1];
                        int r2 = r1 + 8;
                        q = r2 + ci - 128;
                        if (q >= 0 && q < 128) Ss[q * SST + r2] += acc[mt][nt][2];
                        q = r2 + ci - 127;
                        if (q >= 0 && q < 128) Ss[q * SST + r2] += acc[mt][nt][3];
                    }
                }
            }
        }
        __syncthreads();

        // ---- online softmax: lane-pair per row, shuffle reductions, ex2 -----
        {
            const int r  = tid >> 1;                 // row 0..127
            const int hh = tid & 1;                  // half 0/1 (same warp pair)
            float* srow = Ss + r * SST + hh * 64;
            float mx = -1e30f;
            #pragma unroll 8
            for (int j = 0; j < 64; j++) mx = fmaxf(mx, srow[j]);
            mx = fmaxf(mx, __shfl_xor_sync(0xffffffffu, mx, 1));

            float mold = mrow[r];
            float mnew = fmaxf(mold, mx * scale);
            float corr = exp2f((mold - mnew) * L2E);

            const float sl = scale * L2E;
            const float ml = mnew * L2E;
            float ssum = 0.f;
            uint32_t* prow = Phu + r * PSTU + hh * 32;
            #pragma unroll 8
            for (int j = 0; j < 64; j += 2) {
                float t0 = fmaf(srow[j],     sl, -ml);
                float t1 = fmaf(srow[j + 1], sl, -ml);
                __half2 th = __floats2half2_rn(t0, t1);
                uint32_t ph = ex2_f16x2(*(uint32_t*)&th);
                prow[j >> 1] = ph;
                float2 pf = __half22float2(*(__half2*)&ph);
                ssum += pf.x + pf.y;
            }
            ssum += __shfl_xor_sync(0xffffffffu, ssum, 1);
            if (hh == 0) {
                crow[r] = corr;
                mrow[r] = mnew;
                lrow[r] = lrow[r] * corr + ssum;
            }
        }
        __syncthreads();

        // ---- PV ----
        {
            const int wm1 = warp * 16;
            float c1 = crow[wm1 + gid], c2 = crow[wm1 + gid + 8];
            #pragma unroll
            for (int nt = 0; nt < 8; nt++) {
                ctx[nt][0] *= c1; ctx[nt][1] *= c1;
                ctx[nt][2] *= c2; ctx[nt][3] *= c2;
            }
            #pragma unroll
            for (int ks = 0; ks < 8; ks++) {
                uint32_t a[4];
                ldsm_x4(a[0], a[1], a[2], a[3],
                        pbase + (uint32_t)(((wm1 + lr16) * PSTU + ks * 8 + lc4) * 4));
                uint32_t vaddr = vbase +
                    (uint32_t)((16 * ks + vkb) * (QSTU * 4)) + (uint32_t)(vnb * 2);
                #pragma unroll
                for (int ntp = 0; ntp < 4; ntp++) {
                    uint32_t b0, b1, b2, b3;
                    ldsm_x4_t(b0, b1, b2, b3, vaddr + ntp * 32);
                    uint32_t bA[2] = { b0, b1 };
                    uint32_t bB[2] = { b2, b3 };
                    mma_f16(ctx[2 * ntp],     a, bA);
                    mma_f16(ctx[2 * ntp + 1], a, bB);
                }
            }
        }
        __syncthreads();
    }

    // ---- write ctx ----
    {
        const int wm1 = warp * 16;
        float inv1 = 1.0f / lrow[wm1 + gid];
        float inv2 = 1.0f / lrow[wm1 + gid + 8];
        size_t row1 = qrow0 + wm1 + gid;
        size_t row2 = row1 + 8;
        #pragma unroll
        for (int nt = 0; nt < 8; nt++) {
            int col = nt * 8 + 2 * tig;
            *(__half2*)(CTH + row1 * H_ + hoff + col) =
                __floats2half2_rn(ctx[nt][0] * inv1, ctx[nt][1] * inv1);
            *(__half2*)(CTH + row2 * H_ + hoff + col) =
                __floats2half2_rn(ctx[nt][2] * inv2, ctx[nt][3] * inv2);
        }
    }
}

// ---------------- LayerNorm over H=768, one row per CTA ----------------------
__global__ void __launch_bounds__(256) ln_kernel(
    const float* __restrict__ X, const float* __restrict__ gam,
    const float* __restrict__ bet, float* __restrict__ out)
{
    const int row = blockIdx.x;
    const int t   = threadIdx.x;
    const float* x = X + (size_t)row * H_;
    float v0 = x[t], v1 = x[t + 256], v2 = x[t + 512];
    float s = v0 + v1 + v2;
    float q = v0 * v0 + v1 * v1 + v2 * v2;

    __shared__ float sh[64];
    #pragma unroll
    for (int o = 16; o > 0; o >>= 1) {
        s += __shfl_down_sync(0xffffffffu, s, o);
        q += __shfl_down_sync(0xffffffffu, q, o);
    }
    int w = t >> 5, lane = t & 31;
    if (lane == 0) { sh[w] = s; sh[32 + w] = q; }
    __syncthreads();
    if (t == 0) {
        float ts = 0.f, tq = 0.f;
        #pragma unroll
        for (int i = 0; i < 8; i++) { ts += sh[i]; tq += sh[32 + i]; }
        sh[0] = ts;
        sh[32] = tq;
    }
    __syncthreads();
    float mu  = sh[0] * (1.0f / 768.0f);
    float var = sh[32] * (1.0f / 768.0f) - mu * mu;
    float r   = rsqrtf(var + 1e-7f);

    float* o = out + (size_t)row * H_;
    o[t]       = (v0 - mu) * r * gam[t]       + bet[t];
    o[t + 256] = (v1 - mu) * r * gam[t + 256] + bet[t + 256];
    o[t + 512] = (v2 - mu) * r * gam[t + 512] + bet[t + 512];
}

// ---------------- launch ------------------------------------------------------
extern "C" void kernel_launch(void* const* d_in, const int* in_sizes, int n_in,
                              void* d_out, int out_size)
{
    const float* hidden = (const float*)d_in[0];
    const float* rel    = (const float*)d_in[1];
    const float* Wq = (const float*)d_in[2];  const float* bq = (const float*)d_in[3];
    const float* Wk = (const float*)d_in[4];  const float* bk = (const float*)d_in[5];
    const float* Wv = (const float*)d_in[6];  const float* bv = (const float*)d_in[7];
    const float* Wo = (const float*)d_in[8];  const float* bo = (const float*)d_in[9];
    const float* lns = (const float*)d_in[10];
    const float* lnb = (const float*)d_in[11];
    float* out = (float*)d_out;

    __half *HH, *RELH, *WTh, *Qh, *Kh, *Vh, *CTH, *PKH, *PQH;
    float *PK, *PQ, *XR;
    cudaGetSymbolAddress((void**)&HH,   g_HH);
    cudaGetSymbolAddress((void**)&RELH, g_RELH);
    cudaGetSymbolAddress((void**)&WTh,  g_WTh);
    cudaGetSymbolAddress((void**)&Qh,   g_Qh);
    cudaGetSymbolAddress((void**)&Kh,   g_Kh);
    cudaGetSymbolAddress((void**)&Vh,   g_Vh);
    cudaGetSymbolAddress((void**)&CTH,  g_CTH);
    cudaGetSymbolAddress((void**)&PK,   g_PK);
    cudaGetSymbolAddress((void**)&PQ,   g_PQ);
    cudaGetSymbolAddress((void**)&PKH,  g_PKH);
    cudaGetSymbolAddress((void**)&PQH,  g_PQH);
    cudaGetSymbolAddress((void**)&XR,   g_XR);

    const int M = B_ * S_;                       // 32768

    // conversions (one transpose launch for all 4 weights)
    f2h_kernel<<<TOT_ / 1024, 256>>>(hidden, HH);
    f2h_kernel<<<(512 * H_) / 1024, 256>>>(rel, RELH);
    transpose768h4<<<dim3(24, 24, 4), dim3(32, 8)>>>(Wq, Wk, Wv, Wo, WTh);

    cudaFuncSetAttribute(qkv_gemm,
                         cudaFuncAttributeMaxDynamicSharedMemorySize, GSMEM);
    cudaFuncSetAttribute(pos_gemm,
                         cudaFuncAttributeMaxDynamicSharedMemorySize, GSMEM);
    cudaFuncSetAttribute(out_gemm,
                         cudaFuncAttributeMaxDynamicSharedMemorySize, GSMEM);

    // QKV in one launch; pos projections in one launch
    qkv_gemm<<<dim3(18, M / 128), 256, GSMEM>>>(HH, WTh, bq, bk, bv, Qh, Kh, Vh);
    pos_gemm<<<dim3(12, 512 / 128), 256, GSMEM>>>(RELH, WTh, bq, bk, PK, PQ);
    build_pos_h<<<511, 768>>>(PK, PQ, PKH, PQH);

    // attention
    const int smem_attn =
        (128 * QSTU * 3 + 128 * PSTU) * 4 + (128 * SST + 3 * 128) * 4;
    cudaFuncSetAttribute(attn_mma,
                         cudaFuncAttributeMaxDynamicSharedMemorySize, smem_attn);
    attn_mma<<<dim3(NH_, NB_, B_), 256, smem_attn>>>(Qh, Kh, Vh, PKH, PQH, CTH);

    // output projection + residual, then layernorm
    out_gemm<<<dim3(6, M / 128), 256, GSMEM>>>(CTH, WTh + (size_t)3 * H_ * H_,
                                               bo, hidden, XR);
    ln_kernel<<<M, 256>>>(XR, lns, lnb, out);
}

// round 13
// speedup vs baseline: 5.0249x; 1.1364x over previous
#include <cuda_runtime.h>
#include <cuda_fp16.h>
#include <math.h>
#include <stdint.h>

#define B_   4
#define S_   8192
#define H_   768
#define NH_  12
#define HD_  64
#define NB_  64
#define TOT_ (B_*S_*H_)

// attention smem strides
#define QSTU 36    // u32 stride for fp16 Q/K/V rows (32 u32 data + 4 pad)
#define PSTU 68    // u32 stride for fp16 P rows (64 u32 data + 4 pad)
#define SST  132   // fp32 score stride (even: float2 stores stay 8B-aligned)

// fp16 gemm config: BK=32 halves
#define GST   20                   // u32 stride per 32-half row
#define GSTG  (128 * GST)
#define GNSTG 3
#define GKT   24                   // 768 / 32
#define GSMEM (2 * GNSTG * GSTG * 4)   // 61440 B

// ---------------- scratch (device globals; no allocs allowed) ----------------
__device__ __half g_HH[TOT_];
__device__ __half g_RELH[512 * H_];
__device__ __half g_WTh[4 * H_ * H_];
__device__ __half g_Qh[TOT_];
__device__ __half g_Kh[TOT_];
__device__ __half g_Vh[TOT_];
__device__ __half g_CTH[TOT_];
__device__ float  g_XR[TOT_];
__device__ float  g_PK[512 * H_];
__device__ float  g_PQ[512 * H_];
__device__ __half g_PKH[NH_ * 512 * HD_];
__device__ __half g_PQH[NH_ * 512 * HD_];

// ---------------- helpers -----------------------------------------------------
__device__ __forceinline__ void mma_f16(float* c, const uint32_t* a, const uint32_t* b) {
    asm volatile(
        "mma.sync.aligned.m16n8k16.row.col.f32.f16.f16.f32 "
        "{%0,%1,%2,%3},{%4,%5,%6,%7},{%8,%9},{%0,%1,%2,%3};\n"
        : "+f"(c[0]), "+f"(c[1]), "+f"(c[2]), "+f"(c[3])
        : "r"(a[0]), "r"(a[1]), "r"(a[2]), "r"(a[3]), "r"(b[0]), "r"(b[1]));
}

__device__ __forceinline__ void ldsm_x4(
    uint32_t& r0, uint32_t& r1, uint32_t& r2, uint32_t& r3, uint32_t addr)
{
    asm volatile(
        "ldmatrix.sync.aligned.m8n8.x4.shared.b16 {%0,%1,%2,%3}, [%4];"
        : "=r"(r0), "=r"(r1), "=r"(r2), "=r"(r3) : "r"(addr));
}

__device__ __forceinline__ void ldsm_x4_t(
    uint32_t& r0, uint32_t& r1, uint32_t& r2, uint32_t& r3, uint32_t addr)
{
    asm volatile(
        "ldmatrix.sync.aligned.m8n8.x4.trans.shared.b16 {%0,%1,%2,%3}, [%4];"
        : "=r"(r0), "=r"(r1), "=r"(r2), "=r"(r3) : "r"(addr));
}

__device__ __forceinline__ void cp16u(uint32_t* dst_smem, const void* src) {
    uint32_t d = (uint32_t)__cvta_generic_to_shared(dst_smem);
    asm volatile("cp.async.cg.shared.global [%0], [%1], 16;\n" :: "r"(d), "l"(src));
}
__device__ __forceinline__ void cp_commit() {
    asm volatile("cp.async.commit_group;\n");
}

__device__ __forceinline__ uint32_t ex2_f16x2(uint32_t x) {
    uint32_t r;
    asm volatile("ex2.approx.f16x2 %0, %1;" : "=r"(r) : "r"(x));
    return r;
}

// ---------------- conversion kernels -----------------------------------------
__global__ void __launch_bounds__(256) f2h_kernel(
    const float* __restrict__ x, __half* __restrict__ y)
{
    size_t i = ((size_t)blockIdx.x * 256 + threadIdx.x) * 4;
    float4 v = *(const float4*)(x + i);
    *(__half2*)(y + i)     = __floats2half2_rn(v.x, v.y);
    *(__half2*)(y + i + 2) = __floats2half2_rn(v.z, v.w);
}

// 4 weights transposed in one launch: WT[z][n][k] = fp16(W[z][k][n])
__global__ void __launch_bounds__(256) transpose768h4(
    const float* __restrict__ W0, const float* __restrict__ W1,
    const float* __restrict__ W2, const float* __restrict__ W3,
    __half* __restrict__ WT)
{
    __shared__ float t[32][33];
    const float* W = (blockIdx.z == 0) ? W0 : (blockIdx.z == 1) ? W1
                   : (blockIdx.z == 2) ? W2 : W3;
    __half* WTz = WT + (size_t)blockIdx.z * H_ * H_;
    int x = blockIdx.x * 32 + threadIdx.x;
    int y = blockIdx.y * 32 + threadIdx.y;
    #pragma unroll
    for (int i = 0; i < 32; i += 8)
        t[threadIdx.y + i][threadIdx.x] = W[(size_t)(y + i) * H_ + x];
    __syncthreads();
    x = blockIdx.y * 32 + threadIdx.x;
    y = blockIdx.x * 32 + threadIdx.y;
    #pragma unroll
    for (int i = 0; i < 32; i += 8)
        WTz[(size_t)(y + i) * H_ + x] = __float2half_rn(t[threadIdx.x][threadIdx.y + i]);
}

// ---------------- shared GEMM body: 3-stage cp.async, single sync/iter -------
__device__ __forceinline__ void gemm_body(
    const __half* __restrict__ A, const __half* __restrict__ Bw,
    const float* __restrict__ bias, const float* __restrict__ Rres,
    float* __restrict__ Cf, __half* __restrict__ Ch,
    int bm, int bn, uint32_t* gsm)
{
    uint32_t* As = gsm;
    uint32_t* Bs = gsm + GNSTG * GSTG;

    const int tid  = threadIdx.x;
    const int lane = tid & 31;
    const int warp = tid >> 5;
    const int wm   = (warp & 3) * 32;
    const int wn   = (warp >> 2) * 64;
    const int gid  = lane >> 2;
    const int tig  = lane & 3;
    const int lr16 = lane & 15;
    const int lc4  = (lane >> 4) << 2;

    const int fr = tid >> 1;
    const int fc = (tid & 1) << 1;

    const uint32_t as0 = (uint32_t)__cvta_generic_to_shared(As);
    const uint32_t bs0 = (uint32_t)__cvta_generic_to_shared(Bs);

    float acc[2][8][4];
    #pragma unroll
    for (int mt = 0; mt < 2; mt++)
        #pragma unroll
        for (int nt = 0; nt < 8; nt++)
            #pragma unroll
            for (int i = 0; i < 4; i++) acc[mt][nt][i] = 0.f;

    auto fill = [&](int s, int kt) {
        const int kb = kt * 32;
        const __half* Ab = A  + (size_t)(bm + fr) * H_ + kb;
        const __half* Bb = Bw + (size_t)(bn + fr) * H_ + kb;
        uint32_t* as = As + s * GSTG + fr * GST;
        uint32_t* bs = Bs + s * GSTG + fr * GST;
        cp16u(&as[fc * 4],       Ab + fc * 8);
        cp16u(&as[(fc + 1) * 4], Ab + (fc + 1) * 8);
        cp16u(&bs[fc * 4],       Bb + fc * 8);
        cp16u(&bs[(fc + 1) * 4], Bb + (fc + 1) * 8);
        cp_commit();
    };

    fill(0, 0);
    fill(1, 1);

    for (int kt = 0; kt < GKT; kt++) {
        if (kt < GKT - 1) asm volatile("cp.async.wait_group 1;\n");
        else              asm volatile("cp.async.wait_group 0;\n");
        __syncthreads();

        const uint32_t asb = as0 + (uint32_t)((kt % GNSTG) * GSTG) * 4;
        const uint32_t bsb = bs0 + (uint32_t)((kt % GNSTG) * GSTG) * 4;

        #pragma unroll
        for (int ks = 0; ks < 2; ks++) {
            const int wb = ks * 8;
            uint32_t a[2][4], b[8][2];
            #pragma unroll
            for (int mt = 0; mt < 2; mt++)
                ldsm_x4(a[mt][0], a[mt][1], a[mt][2], a[mt][3],
                        asb + (uint32_t)(((wm + mt * 16 + lr16) * GST + wb + lc4) * 4));
            #pragma unroll
            for (int ntp = 0; ntp < 4; ntp++) {
                uint32_t r0, r1, r2, r3;
                ldsm_x4(r0, r1, r2, r3,
                        bsb + (uint32_t)(((wn + ntp * 16 + lr16) * GST + wb + lc4) * 4));
                b[2 * ntp][0]     = r0;
                b[2 * ntp + 1][0] = r1;
                b[2 * ntp][1]     = r2;
                b[2 * ntp + 1][1] = r3;
            }
            #pragma unroll
            for (int mt = 0; mt < 2; mt++)
                #pragma unroll
                for (int nt = 0; nt < 8; nt++)
                    mma_f16(acc[mt][nt], a[mt], b[nt]);
        }
        // fill stage freed by compute(kt-1); safe after this iteration's sync
        if (kt + 2 < GKT) fill((kt + 2) % GNSTG, kt + 2);
    }

    #pragma unroll
    for (int mt = 0; mt < 2; mt++) {
        #pragma unroll
        for (int hi = 0; hi < 2; hi++) {
            size_t row = (size_t)bm + wm + mt * 16 + gid + hi * 8;
            #pragma unroll
            for (int nt = 0; nt < 8; nt++) {
                int col = bn + wn + nt * 8 + tig * 2;
                float v0 = acc[mt][nt][hi * 2 + 0] + bias[col];
                float v1 = acc[mt][nt][hi * 2 + 1] + bias[col + 1];
                if (Rres != nullptr) {
                    float2 rr = *(const float2*)(Rres + row * (size_t)H_ + col);
                    v0 += rr.x; v1 += rr.y;
                }
                if (Cf != nullptr)
                    *(float2*)(Cf + row * (size_t)H_ + col) = make_float2(v0, v1);
                else
                    *(__half2*)(Ch + row * (size_t)H_ + col) = __floats2half2_rn(v0, v1);
            }
        }
    }
}

// QKV in one launch: blockIdx.x/6 selects {Q,K,V}
__global__ void __launch_bounds__(256, 2) qkv_gemm(
    const __half* __restrict__ A, const __half* __restrict__ WT,
    const float* __restrict__ bq, const float* __restrict__ bk,
    const float* __restrict__ bv,
    __half* __restrict__ Oq, __half* __restrict__ Ok, __half* __restrict__ Ov)
{
    extern __shared__ uint32_t gsm[];
    const int which = blockIdx.x / 6;
    const int bn = (blockIdx.x % 6) * 128;
    const int bm = blockIdx.y * 128;
    const __half* Bw = WT + (size_t)which * H_ * H_;
    const float* bias = (which == 0) ? bq : (which == 1) ? bk : bv;
    __half* Ch = (which == 0) ? Oq : (which == 1) ? Ok : Ov;
    gemm_body(A, Bw, bias, nullptr, nullptr, Ch, bm, bn, gsm);
}

// both pos projections in one launch: blockIdx.x/6 selects {PK(Wk), PQ(Wq)}
__global__ void __launch_bounds__(256, 2) pos_gemm(
    const __half* __restrict__ A, const __half* __restrict__ WT,
    const float* __restrict__ bq, const float* __restrict__ bk,
    float* __restrict__ Opk, float* __restrict__ Opq)
{
    extern __shared__ uint32_t gsm[];
    const int which = blockIdx.x / 6;
    const int bn = (blockIdx.x % 6) * 128;
    const int bm = blockIdx.y * 128;
    const __half* Bw = WT + (size_t)(which == 0 ? 1 : 0) * H_ * H_; // Wk else Wq
    const float* bias = (which == 0) ? bk : bq;
    float* Cf = (which == 0) ? Opk : Opq;
    gemm_body(A, Bw, bias, nullptr, Cf, nullptr, bm, bn, gsm);
}

// out-proj with residual, fp32 out
__global__ void __launch_bounds__(256, 2) out_gemm(
    const __half* __restrict__ A, const __half* __restrict__ WT,
    const float* __restrict__ bias, const float* __restrict__ Rres,
    float* __restrict__ Cf)
{
    extern __shared__ uint32_t gsm[];
    const int bn = blockIdx.x * 128;
    const int bm = blockIdx.y * 128;
    gemm_body(A, WT, bias, Rres, Cf, nullptr, bm, bn, gsm);
}

// ---------------- bucketization + fp16 pos tables ----------------------------
__device__ __forceinline__ int bucket_idx_dev(int d)
{
    int ad = d < 0 ? -d : d;
    int v;
    if (ad <= 128) {
        v = d;
    } else {
        float t = logf((float)ad / 128.0f);
        t = t / 0.6892332713f;                   // fp32(ln(255/128))
        t = t * 127.0f;
        float lp = ceilf(t) + 128.0f;
        v = (int)(d < 0 ? -lp : lp);
    }
    v += 256;
    return v < 0 ? 0 : (v > 511 ? 511 : v);
}

__global__ void build_pos_h(const float* __restrict__ PK, const float* __restrict__ PQ,
                            __half* __restrict__ PKH, __half* __restrict__ PQH)
{
    int dd = blockIdx.x;                         // 0..510
    int t  = threadIdx.x;                        // 0..767
    int p  = bucket_idx_dev(dd - 383);
    int h  = t >> 6;
    int d  = t & 63;
    size_t dst = ((size_t)h * 512 + dd + 1) * HD_ + d;
    PKH[dst] = __float2half_rn(PK[(size_t)p * H_ + t]);
    PQH[dst] = __float2half_rn(PQ[(size_t)p * H_ + t]);
    if (dd == 0) {
        PKH[((size_t)h * 512) * HD_ + d] = __float2half_rn(0.f);
        PQH[((size_t)h * 512) * HD_ + d] = __float2half_rn(0.f);
    }
}

// ---------------- attention: fp16 MMA, exact-window C2P/P2C ------------------
__global__ void __launch_bounds__(256, 1) attn_mma(
    const __half* __restrict__ Qh, const __half* __restrict__ Kh,
    const __half* __restrict__ Vh,
    const __half* __restrict__ PKH, const __half* __restrict__ PQH,
    __half* __restrict__ CTH)
{
    extern __shared__ char smc[];
    uint32_t* Qsu = (uint32_t*)smc;                       // 128*QSTU
    uint32_t* Ksu = Qsu + 128 * QSTU;
    uint32_t* Vsu = Ksu + 128 * QSTU;
    uint32_t* Phu = Vsu + 128 * QSTU;                     // 128*PSTU
    float* Ss   = (float*)(Phu + 128 * PSTU);             // 128*SST
    float* mrow = Ss + 128 * SST;                         // 128
    float* lrow = mrow + 128;
    float* crow = lrow + 128;

    const int h = blockIdx.x, n = blockIdx.y, b = blockIdx.z;
    const int tid  = threadIdx.x;
    const int lane = tid & 31;
    const int warp = tid >> 5;
    const int gid  = lane >> 2;
    const int tig  = lane & 3;
    const int lr16 = lane & 15;
    const int lc4  = (lane >> 4) << 2;
    const size_t qrow0 = (size_t)b * S_ + (size_t)n * 128;
    const size_t hoff  = (size_t)h * HD_;

    const uint32_t qbase = (uint32_t)__cvta_generic_to_shared(Qsu);
    const uint32_t kbase = (uint32_t)__cvta_generic_to_shared(Ksu);
    const uint32_t vbase = (uint32_t)__cvta_generic_to_shared(Vsu);
    const uint32_t pbase = (uint32_t)__cvta_generic_to_shared(Phu);

    for (int i = tid; i < 128 * 8; i += 256) {
        int r = i >> 3, c = i & 7;
        uint4 v = *(const uint4*)(Qh + (qrow0 + r) * H_ + hoff + c * 8);
        uint32_t* d = &Qsu[r * QSTU + c * 4];
        d[0] = v.x; d[1] = v.y; d[2] = v.z; d[3] = v.w;
    }
    if (tid < 128) { mrow[tid] = -1e30f; lrow[tid] = 0.f; }
    __syncthreads();

    float ctx[8][4];
    #pragma unroll
    for (int nt = 0; nt < 8; nt++)
        #pragma unroll
        for (int i = 0; i < 4; i++) ctx[nt][i] = 0.f;

    const uint32_t* pk32 = (const uint32_t*)PKH + (size_t)h * 512 * 32;
    const uint32_t* pq32 = (const uint32_t*)PQH + (size_t)h * 512 * 32;
    const float scale = 0.07216878364870323f;    // 1/sqrt(192)
    const float L2E   = 1.4426950408889634f;

    const int lg  = lane >> 3;
    const int lr  = lane & 7;
    const int vkb = (lg & 1) * 8 + lr;
    const int vnb = (lg >> 1) * 8;

    for (int c = 0; c < 3; c++) {
        const int  c0  = c * 128;
        const long sk0 = (long)n * 128 - 128 + c0;

        for (int i = tid; i < 128 * 8; i += 256) {
            int r = i >> 3, cc = i & 7;
            long s = sk0 + r;
            uint4 kv = make_uint4(0u, 0u, 0u, 0u);
            uint4 vv = make_uint4(0u, 0u, 0u, 0u);
            if (s >= 0 && s < S_) {
                size_t g = ((size_t)b * S_ + s) * H_ + hoff + cc * 8;
                kv = *(const uint4*)(Kh + g);
                vv = *(const uint4*)(Vh + g);
            }
            uint32_t* dk = &Ksu[r * QSTU + cc * 4];
            dk[0] = kv.x; dk[1] = kv.y; dk[2] = kv.z; dk[3] = kv.w;
            uint32_t* dv = &Vsu[r * QSTU + cc * 4];
            dv[0] = vv.x; dv[1] = vv.y; dv[2] = vv.z; dv[3] = vv.w;
        }
        __syncthreads();

        // ---- c2c ----
        {
            const int wm = (warp & 3) * 32, wn = (warp >> 2) * 64;
            float acc[2][8][4];
            #pragma unroll
            for (int mt = 0; mt < 2; mt++)
                #pragma unroll
                for (int nt = 0; nt < 8; nt++)
                    #pragma unroll
                    for (int i = 0; i < 4; i++) acc[mt][nt][i] = 0.f;

            #pragma unroll
            for (int ks = 0; ks < 4; ks++) {
                const int wb = ks * 8;
                uint32_t a[2][4], bf[8][2];
                #pragma unroll
                for (int mt = 0; mt < 2; mt++)
                    ldsm_x4(a[mt][0], a[mt][1], a[mt][2], a[mt][3],
                            qbase + (uint32_t)(((wm + mt * 16 + lr16) * QSTU + wb + lc4) * 4));
                #pragma unroll
                for (int ntp = 0; ntp < 4; ntp++) {
                    uint32_t r0, r1, r2, r3;
                    ldsm_x4(r0, r1, r2, r3,
                            kbase + (uint32_t)(((wn + ntp * 16 + lr16) * QSTU + wb + lc4) * 4));
                    bf[2 * ntp][0]     = r0;
                    bf[2 * ntp + 1][0] = r1;
                    bf[2 * ntp][1]     = r2;
                    bf[2 * ntp + 1][1] = r3;
                }
                #pragma unroll
                for (int mt = 0; mt < 2; mt++)
                    #pragma unroll
                    for (int nt = 0; nt < 8; nt++)
                        mma_f16(acc[mt][nt], a[mt], bf[nt]);
            }
            #pragma unroll
            for (int mt = 0; mt < 2; mt++) {
                int r1 = wm + mt * 16 + gid;
                #pragma unroll
                for (int nt = 0; nt < 8; nt++) {
                    int cc = wn + nt * 8 + 2 * tig;
                    *(float2*)&Ss[r1 * SST + cc] =
                        make_float2(acc[mt][nt][0], acc[mt][nt][1]);
                    *(float2*)&Ss[(r1 + 8) * SST + cc] =
                        make_float2(acc[mt][nt][2], acc[mt][nt][3]);
                }
            }
        }
        __syncthreads();

        // ---- C2P: exact window [wm, wm+160), warp pair splits 80+80 ---------
        // output: S[r][jj] += acc, jj = r - ci + 128; valid ci in (r, r+128]
        {
            const int wm = (warp & 3) * 32;
            const int wg = warp >> 2;
            const int colbase = 256 - c0;
            const int ws = wm + wg * 80;
            float acc[2][10][4];
            #pragma unroll
            for (int mt = 0; mt < 2; mt++)
                #pragma unroll
                for (int nt = 0; nt < 10; nt++)
                    #pragma unroll
                    for (int i = 0; i < 4; i++) acc[mt][nt][i] = 0.f;

            #pragma unroll
            for (int ks = 0; ks < 4; ks++) {
                const int wb = ks * 8;
                uint32_t a[2][4];
                #pragma unroll
                for (int mt = 0; mt < 2; mt++)
                    ldsm_x4(a[mt][0], a[mt][1], a[mt][2], a[mt][3],
                            qbase + (uint32_t)(((wm + mt * 16 + lr16) * QSTU + wb + lc4) * 4));
                #pragma unroll
                for (int nt = 0; nt < 10; nt++) {
                    int cc = colbase + ws + nt * 8 + gid;
                    uint32_t bf[2];
                    bf[0] = __ldg(&pk32[(size_t)cc * 32 + wb + tig]);
                    bf[1] = __ldg(&pk32[(size_t)cc * 32 + wb + 4 + tig]);
                    mma_f16(acc[0][nt], a[0], bf);
                    mma_f16(acc[1][nt], a[1], bf);
                }
            }
            #pragma unroll
            for (int mt = 0; mt < 2; mt++) {
                int r1 = wm + mt * 16 + gid;
                #pragma unroll
                for (int nt = 0; nt < 10; nt++) {
                    int ci = ws + nt * 8 + 2 * tig;
                    int jj;
                    jj = r1 - ci + 128;
                    if (jj >= 0 && jj < 128) Ss[r1 * SST + jj] += acc[mt][nt][0];
                    jj = r1 - ci + 127;
                    if (jj >= 0 && jj < 128) Ss[r1 * SST + jj] += acc[mt][nt][1];
                    int r2 = r1 + 8;
                    jj = r2 - ci + 128;
                    if (jj >= 0 && jj < 128) Ss[r2 * SST + jj] += acc[mt][nt][2];
                    jj = r2 - ci + 127;
                    if (jj >= 0 && jj < 128) Ss[r2 * SST + jj] += acc[mt][nt][3];
                }
            }
        }
        __syncthreads();

        // ---- P2C: exact window [96-wm, 256-wm), warp pair splits 80+80 ------
        // output: S[q][r] += acc, q = r + ci - 128; valid ci in [128-r, 256-r)
        {
            const int wm = (warp & 3) * 32;
            const int wg = warp >> 2;
            const int colbase = 256 - c0;
            const int ws = (96 - wm) + wg * 80;
            float acc[2][10][4];
            #pragma unroll
            for (int mt = 0; mt < 2; mt++)
                #pragma unroll
                for (int nt = 0; nt < 10; nt++)
                    #pragma unroll
                    for (int i = 0; i < 4; i++) acc[mt][nt][i] = 0.f;

            #pragma unroll
            for (int ks = 0; ks < 4; ks++) {
                const int wb = ks * 8;
                uint32_t a[2][4];
                #pragma unroll
                for (int mt = 0; mt < 2; mt++)
                    ldsm_x4(a[mt][0], a[mt][1], a[mt][2], a[mt][3],
                            kbase + (uint32_t)(((wm + mt * 16 + lr16) * QSTU + wb + lc4) * 4));
                #pragma unroll
                for (int nt = 0; nt < 10; nt++) {
                    int cc = colbase + ws + nt * 8 + gid;
                    uint32_t bf[2];
                    bf[0] = __ldg(&pq32[(size_t)cc * 32 + wb + tig]);
                    bf[1] = __ldg(&pq32[(size_t)cc * 32 + wb + 4 + tig]);
                    mma_f16(acc[0][nt], a[0], bf);
                    mma_f16(acc[1][nt], a[1], bf);
                }
            }
            #pragma unroll
            for (int mt = 0; mt < 2; mt++) {
                int r1 = wm + mt * 16 + gid;
                #pragma unroll
                for (int nt = 0; nt < 10; nt++) {
                    int ci = ws + nt * 8 + 2 * tig;
                    int q;
                    q = r1 + ci - 128;
                    if (q >= 0 && q < 128) Ss[q * SST + r1] += acc[mt][nt][0];
                    q = r1 + ci - 127;
                    if (q >= 0 && q < 128) Ss[q * SST + r1] += acc[mt][nt][1];
                    int r2 = r1 + 8;
                    q = r2 + ci - 128;
                    if (q >= 0 && q < 128) Ss[q * SST + r2] += acc[mt][nt][2];
                    q = r2 + ci - 127;
                    if (q >= 0 && q < 128) Ss[q * SST + r2] += acc[mt][nt][3];
                }
            }
        }
        __syncthreads();

        // ---- online softmax: lane-pair per row, shuffle reductions, ex2 -----
        {
            const int r  = tid >> 1;
            const int hh = tid & 1;
            float* srow = Ss + r * SST + hh * 64;
            float mx = -1e30f;
            #pragma unroll 8
            for (int j = 0; j < 64; j++) mx = fmaxf(mx, srow[j]);
            mx = fmaxf(mx, __shfl_xor_sync(0xffffffffu, mx, 1));

            float mold = mrow[r];
            float mnew = fmaxf(mold, mx * scale);
            float corr = exp2f((mold - mnew) * L2E);

            const float sl = scale * L2E;
            const float ml = mnew * L2E;
            float ssum = 0.f;
            uint32_t* prow = Phu + r * PSTU + hh * 32;
            #pragma unroll 8
            for (int j = 0; j < 64; j += 2) {
                float t0 = fmaf(srow[j],     sl, -ml);
                float t1 = fmaf(srow[j + 1], sl, -ml);
                __half2 th = __floats2half2_rn(t0, t1);
                uint32_t ph = ex2_f16x2(*(uint32_t*)&th);
                prow[j >> 1] = ph;
                float2 pf = __half22float2(*(__half2*)&ph);
                ssum += pf.x + pf.y;
            }
            ssum += __shfl_xor_sync(0xffffffffu, ssum, 1);
            if (hh == 0) {
                crow[r] = corr;
                mrow[r] = mnew;
                lrow[r] = lrow[r] * corr + ssum;
            }
        }
        __syncthreads();

        // ---- PV ----
        {
            const int wm1 = warp * 16;
            float c1 = crow[wm1 + gid], c2 = crow[wm1 + gid + 8];
            #pragma unroll
            for (int nt = 0; nt < 8; nt++) {
                ctx[nt][0] *= c1; ctx[nt][1] *= c1;
                ctx[nt][2] *= c2; ctx[nt][3] *= c2;
            }
            #pragma unroll
            for (int ks = 0; ks < 8; ks++) {
                uint32_t a[4];
                ldsm_x4(a[0], a[1], a[2], a[3],
                        pbase + (uint32_t)(((wm1 + lr16) * PSTU + ks * 8 + lc4) * 4));
                uint32_t vaddr = vbase +
                    (uint32_t)((16 * ks + vkb) * (QSTU * 4)) + (uint32_t)(vnb * 2);
                #pragma unroll
                for (int ntp = 0; ntp < 4; ntp++) {
                    uint32_t b0, b1, b2, b3;
                    ldsm_x4_t(b0, b1, b2, b3, vaddr + ntp * 32);
                    uint32_t bA[2] = { b0, b1 };
                    uint32_t bB[2] = { b2, b3 };
                    mma_f16(ctx[2 * ntp],     a, bA);
                    mma_f16(ctx[2 * ntp + 1], a, bB);
                }
            }
        }
        __syncthreads();
    }

    // ---- write ctx ----
    {
        const int wm1 = warp * 16;
        float inv1 = 1.0f / lrow[wm1 + gid];
        float inv2 = 1.0f / lrow[wm1 + gid + 8];
        size_t row1 = qrow0 + wm1 + gid;
        size_t row2 = row1 + 8;
        #pragma unroll
        for (int nt = 0; nt < 8; nt++) {
            int col = nt * 8 + 2 * tig;
            *(__half2*)(CTH + row1 * H_ + hoff + col) =
                __floats2half2_rn(ctx[nt][0] * inv1, ctx[nt][1] * inv1);
            *(__half2*)(CTH + row2 * H_ + hoff + col) =
                __floats2half2_rn(ctx[nt][2] * inv2, ctx[nt][3] * inv2);
        }
    }
}

// ---------------- LayerNorm over H=768, one row per CTA ----------------------
__global__ void __launch_bounds__(256) ln_kernel(
    const float* __restrict__ X, const float* __restrict__ gam,
    const float* __restrict__ bet, float* __restrict__ out)
{
    const int row = blockIdx.x;
    const int t   = threadIdx.x;
    const float* x = X + (size_t)row * H_;
    float v0 = x[t], v1 = x[t + 256], v2 = x[t + 512];
    float s = v0 + v1 + v2;
    float q = v0 * v0 + v1 * v1 + v2 * v2;

    __shared__ float sh[64];
    #pragma unroll
    for (int o = 16; o > 0; o >>= 1) {
        s += __shfl_down_sync(0xffffffffu, s, o);
        q += __shfl_down_sync(0xffffffffu, q, o);
    }
    int w = t >> 5, lane = t & 31;
    if (lane == 0) { sh[w] = s; sh[32 + w] = q; }
    __syncthreads();
    if (t == 0) {
        float ts = 0.f, tq = 0.f;
        #pragma unroll
        for (int i = 0; i < 8; i++) { ts += sh[i]; tq += sh[32 + i]; }
        sh[0] = ts;
        sh[32] = tq;
    }
    __syncthreads();
    float mu  = sh[0] * (1.0f / 768.0f);
    float var = sh[32] * (1.0f / 768.0f) - mu * mu;
    float r   = rsqrtf(var + 1e-7f);

    float* o = out + (size_t)row * H_;
    o[t]       = (v0 - mu) * r * gam[t]       + bet[t];
    o[t + 256] = (v1 - mu) * r * gam[t + 256] + bet[t + 256];
    o[t + 512] = (v2 - mu) * r * gam[t + 512] + bet[t + 512];
}

// ---------------- launch ------------------------------------------------------
extern "C" void kernel_launch(void* const* d_in, const int* in_sizes, int n_in,
                              void* d_out, int out_size)
{
    const float* hidden = (const float*)d_in[0];
    const float* rel    = (const float*)d_in[1];
    const float* Wq = (const float*)d_in[2];  const float* bq = (const float*)d_in[3];
    const float* Wk = (const float*)d_in[4];  const float* bk = (const float*)d_in[5];
    const float* Wv = (const float*)d_in[6];  const float* bv = (const float*)d_in[7];
    const float* Wo = (const float*)d_in[8];  const float* bo = (const float*)d_in[9];
    const float* lns = (const float*)d_in[10];
    const float* lnb = (const float*)d_in[11];
    float* out = (float*)d_out;

    __half *HH, *RELH, *WTh, *Qh, *Kh, *Vh, *CTH, *PKH, *PQH;
    float *PK, *PQ, *XR;
    cudaGetSymbolAddress((void**)&HH,   g_HH);
    cudaGetSymbolAddress((void**)&RELH, g_RELH);
    cudaGetSymbolAddress((void**)&WTh,  g_WTh);
    cudaGetSymbolAddress((void**)&Qh,   g_Qh);
    cudaGetSymbolAddress((void**)&Kh,   g_Kh);
    cudaGetSymbolAddress((void**)&Vh,   g_Vh);
    cudaGetSymbolAddress((void**)&CTH,  g_CTH);
    cudaGetSymbolAddress((void**)&PK,   g_PK);
    cudaGetSymbolAddress((void**)&PQ,   g_PQ);
    cudaGetSymbolAddress((void**)&PKH,  g_PKH);
    cudaGetSymbolAddress((void**)&PQH,  g_PQH);
    cudaGetSymbolAddress((void**)&XR,   g_XR);

    const int M = B_ * S_;                       // 32768

    // conversions (one transpose launch for all 4 weights)
    f2h_kernel<<<TOT_ / 1024, 256>>>(hidden, HH);
    f2h_kernel<<<(512 * H_) / 1024, 256>>>(rel, RELH);
    transpose768h4<<<dim3(24, 24, 4), dim3(32, 8)>>>(Wq, Wk, Wv, Wo, WTh);

    cudaFuncSetAttribute(qkv_gemm,
                         cudaFuncAttributeMaxDynamicSharedMemorySize, GSMEM);
    cudaFuncSetAttribute(pos_gemm,
                         cudaFuncAttributeMaxDynamicSharedMemorySize, GSMEM);
    cudaFuncSetAttribute(out_gemm,
                         cudaFuncAttributeMaxDynamicSharedMemorySize, GSMEM);

    // QKV in one launch; pos projections in one launch
    qkv_gemm<<<dim3(18, M / 128), 256, GSMEM>>>(HH, WTh, bq, bk, bv, Qh, Kh, Vh);
    pos_gemm<<<dim3(12, 512 / 128), 256, GSMEM>>>(RELH, WTh, bq, bk, PK, PQ);
    build_pos_h<<<511, 768>>>(PK, PQ, PKH, PQH);

    // attention
    const int smem_attn =
        (128 * QSTU * 3 + 128 * PSTU) * 4 + (128 * SST + 3 * 128) * 4;
    cudaFuncSetAttribute(attn_mma,
                         cudaFuncAttributeMaxDynamicSharedMemorySize, smem_attn);
    attn_mma<<<dim3(NH_, NB_, B_), 256, smem_attn>>>(Qh, Kh, Vh, PKH, PQH, CTH);

    // output projection + residual, then layernorm
    out_gemm<<<dim3(6, M / 128), 256, GSMEM>>>(CTH, WTh + (size_t)3 * H_ * H_,
                                               bo, hidden, XR);
    ln_kernel<<<M, 256>>>(XR, lns, lnb, out);
}